// round 5
// baseline (speedup 1.0000x reference)
#include <cuda_runtime.h>
#include <cuda_bf16.h>
#include <math.h>
#include <stdint.h>

#define BB 2
#define NNq 2048
#define CCd 1024
#define HHn 16
#define HIDd 4096
#define ROWS (BB * NNq)   // 4096

// ================= scratch (device globals) =================
__device__ float g_x1[ROWS * CCd];
__device__ float g_h1[ROWS * HIDd];
__device__ __nv_bfloat16 g_ah[ROWS * HIDd];
__device__ __nv_bfloat16 g_al[ROWS * HIDd];
__device__ __nv_bfloat16 g_atth[ROWS * CCd];
__device__ __nv_bfloat16 g_attl[ROWS * CCd];
__device__ __nv_bfloat16 g_qh2[ROWS * CCd], g_ql2[ROWS * CCd];
__device__ __nv_bfloat16 g_kh2[ROWS * CCd], g_kl2[ROWS * CCd];
__device__ __nv_bfloat16 g_vh2[ROWS * CCd], g_vl2[ROWS * CCd];
__device__ __nv_bfloat16 g_wqh[3072 * 1024], g_wql[3072 * 1024];
__device__ __nv_bfloat16 g_wph[1024 * 1024], g_wpl[1024 * 1024];
__device__ __nv_bfloat16 g_w1h[4096 * 1024], g_w1l[4096 * 1024];
__device__ __nv_bfloat16 g_w2h[1024 * 4096], g_w2l[1024 * 4096];

// ================= helpers =================
__device__ __forceinline__ uint32_t smem_u32(const void* p) {
  uint32_t a;
  asm("{ .reg .u64 t; cvta.to.shared.u64 t, %1; cvt.u32.u64 %0, t; }"
      : "=r"(a) : "l"(p));
  return a;
}

#define CP_ASYNC16(sm, gp) \
  asm volatile("cp.async.cg.shared.global [%0], [%1], 16;" \
               :: "r"(sm), "l"(gp) : "memory")
#define CP_COMMIT() asm volatile("cp.async.commit_group;" ::: "memory")
#define CP_WAIT0() asm volatile("cp.async.wait_group 0;" ::: "memory")
#define CP_WAIT1() asm volatile("cp.async.wait_group 1;" ::: "memory")

#define LDSM_X4(r0, r1, r2, r3, a) \
  asm volatile("ldmatrix.sync.aligned.m8n8.x4.shared.b16 {%0,%1,%2,%3}, [%4];" \
               : "=r"(r0), "=r"(r1), "=r"(r2), "=r"(r3) : "r"(a))
#define LDSM_X4_T(r0, r1, r2, r3, a) \
  asm volatile("ldmatrix.sync.aligned.m8n8.x4.trans.shared.b16 {%0,%1,%2,%3}, [%4];" \
               : "=r"(r0), "=r"(r1), "=r"(r2), "=r"(r3) : "r"(a))

#define MMA16816(d, a0, a1, a2, a3, b0, b1) \
  asm volatile("mma.sync.aligned.m16n8k16.row.col.f32.bf16.bf16.f32 " \
               "{%0,%1,%2,%3}, {%4,%5,%6,%7}, {%8,%9}, {%0,%1,%2,%3};" \
               : "+f"((d)[0]), "+f"((d)[1]), "+f"((d)[2]), "+f"((d)[3]) \
               : "r"(a0), "r"(a1), "r"(a2), "r"(a3), "r"(b0), "r"(b1))

__device__ __forceinline__ float gelu_f(float v) {
  return 0.5f * v * (1.f + erff(v * 0.70710678118654752f));
}

// ================= weight convert + transpose =================
__global__ __launch_bounds__(256) void wconv_kernel(
    const float* __restrict__ W, __nv_bfloat16* __restrict__ th,
    __nv_bfloat16* __restrict__ tl, int K, int N) {
  __shared__ float t[32][33];
  int n0 = blockIdx.x * 32, k0 = blockIdx.y * 32;
  int tx = threadIdx.x & 31, ty = threadIdx.x >> 5;
#pragma unroll
  for (int i = 0; i < 4; i++)
    t[ty + i * 8][tx] = W[(size_t)(k0 + ty + i * 8) * N + n0 + tx];
  __syncthreads();
#pragma unroll
  for (int i = 0; i < 4; i++) {
    float v = t[tx][ty + i * 8];
    __nv_bfloat16 h = __float2bfloat16(v);
    __nv_bfloat16 l = __float2bfloat16(v - __bfloat162float(h));
    size_t o = (size_t)(n0 + ty + i * 8) * K + k0 + tx;
    th[o] = h;
    tl[o] = l;
  }
}

// ================= LayerNorm -> bf16 hi/lo =================
template <int NIT>
__global__ __launch_bounds__(256) void ln_bf_kernel(
    const float* __restrict__ in, const float* __restrict__ gw,
    const float* __restrict__ bw, __nv_bfloat16* __restrict__ oh,
    __nv_bfloat16* __restrict__ ol) {
  const int cols = NIT * 1024;
  int row = blockIdx.x;
  const float* rp = in + (size_t)row * cols;
  float4 buf[NIT];
  float s = 0.f, sq = 0.f;
#pragma unroll
  for (int it = 0; it < NIT; it++) {
    int c = (it * 256 + threadIdx.x) * 4;
    float4 v = *(const float4*)(rp + c);
    buf[it] = v;
    s += v.x + v.y + v.z + v.w;
    sq += v.x * v.x + v.y * v.y + v.z * v.z + v.w * v.w;
  }
  __shared__ float red0[8], red1[8];
#pragma unroll
  for (int o = 16; o; o >>= 1) {
    s += __shfl_xor_sync(0xffffffff, s, o);
    sq += __shfl_xor_sync(0xffffffff, sq, o);
  }
  int warp = threadIdx.x >> 5, lane = threadIdx.x & 31;
  if (lane == 0) { red0[warp] = s; red1[warp] = sq; }
  __syncthreads();
  __shared__ float s_mu, s_ri;
  if (threadIdx.x == 0) {
    float ts = 0.f, tq = 0.f;
#pragma unroll
    for (int i = 0; i < 8; i++) { ts += red0[i]; tq += red1[i]; }
    float mu = ts / (float)cols;
    float var = tq / (float)cols - mu * mu;
    s_mu = mu;
    s_ri = rsqrtf(var + 1e-5f);
  }
  __syncthreads();
  float mu = s_mu, ri = s_ri;
#pragma unroll
  for (int it = 0; it < NIT; it++) {
    int c = (it * 256 + threadIdx.x) * 4;
    float4 v = buf[it];
    float4 g4 = *(const float4*)(gw + c);
    float4 b4 = *(const float4*)(bw + c);
    float o0 = (v.x - mu) * ri * g4.x + b4.x;
    float o1 = (v.y - mu) * ri * g4.y + b4.y;
    float o2 = (v.z - mu) * ri * g4.z + b4.z;
    float o3 = (v.w - mu) * ri * g4.w + b4.w;
    __nv_bfloat162 h01, h23, l01, l23;
    h01.x = __float2bfloat16(o0); h01.y = __float2bfloat16(o1);
    h23.x = __float2bfloat16(o2); h23.y = __float2bfloat16(o3);
    l01.x = __float2bfloat16(o0 - __bfloat162float(h01.x));
    l01.y = __float2bfloat16(o1 - __bfloat162float(h01.y));
    l23.x = __float2bfloat16(o2 - __bfloat162float(h23.x));
    l23.y = __float2bfloat16(o3 - __bfloat162float(h23.y));
    size_t o = (size_t)row * cols + c;
    *(__nv_bfloat162*)(oh + o) = h01;
    *(__nv_bfloat162*)(oh + o + 2) = h23;
    *(__nv_bfloat162*)(ol + o) = l01;
    *(__nv_bfloat162*)(ol + o + 2) = l23;
  }
}

// ================= mma.sync split-bf16 GEMM =================
// CTA tile 128x256x32, 8 warps (2m x 4n), warp tile 64x64, 2-stage cp.async.
// EPI 0: bias; 1: +GELU; 2: +residual; 3: QKV (bias + RoPE + split write).
#define TILE_A 10240                 // 128 rows * 40 pitch * 2B
#define TILE_Bb 20480                // 256 rows * 40 pitch * 2B
#define STAGE_B (2 * TILE_A + 2 * TILE_Bb)  // 61440

template <int EPI>
__global__ __launch_bounds__(256) void gemm_mma(
    const __nv_bfloat16* __restrict__ Ah, const __nv_bfloat16* __restrict__ Al,
    const __nv_bfloat16* __restrict__ Bh, const __nv_bfloat16* __restrict__ Bl,
    const float* __restrict__ bias, const float* __restrict__ res,
    float* __restrict__ C, int K, int N,
    __nv_bfloat16* qh_, __nv_bfloat16* ql_, __nv_bfloat16* kh_,
    __nv_bfloat16* kl_, __nv_bfloat16* vh_, __nv_bfloat16* vl_) {
  extern __shared__ char smem[];
  uint32_t sb = smem_u32(smem);
  int tid = threadIdx.x, wid = tid >> 5, lane = tid & 31;
  int m0 = blockIdx.y * 128, n0 = blockIdx.x * 256;
  int wm = wid & 1, wn = wid >> 1;         // 2 x 4 warp grid, 64x64 each
  int lrow = lane & 15, lc8 = (lane >> 4) * 8;

  float acc[4][8][4];
#pragma unroll
  for (int i = 0; i < 4; i++)
#pragma unroll
    for (int j = 0; j < 8; j++)
#pragma unroll
      for (int t = 0; t < 4; t++) acc[i][j][t] = 0.f;

  int NCH = K >> 5;

  // loader lambdas via macro-ish inline
#define GEMM_LOADS(stgbase, ktv)                                              \
  {                                                                           \
    uint32_t stg = (stgbase);                                                 \
    int kt = (ktv);                                                           \
    _Pragma("unroll") for (int i = 0; i < 2; i++) {                           \
      int c = tid + i * 256;                                                  \
      int r = c >> 2, q = c & 3;                                              \
      uint32_t so = (uint32_t)(r * 80 + q * 16);                              \
      CP_ASYNC16(stg + so, Ah + (size_t)(m0 + r) * K + kt + q * 8);           \
      CP_ASYNC16(stg + TILE_A + so, Al + (size_t)(m0 + r) * K + kt + q * 8);  \
    }                                                                         \
    _Pragma("unroll") for (int i = 0; i < 4; i++) {                           \
      int c = tid + i * 256;                                                  \
      int r = c >> 2, q = c & 3;                                              \
      uint32_t so = (uint32_t)(r * 80 + q * 16);                              \
      CP_ASYNC16(stg + 2 * TILE_A + so,                                       \
                 Bh + (size_t)(n0 + r) * K + kt + q * 8);                     \
      CP_ASYNC16(stg + 2 * TILE_A + TILE_Bb + so,                             \
                 Bl + (size_t)(n0 + r) * K + kt + q * 8);                     \
    }                                                                         \
    CP_COMMIT();                                                              \
  }

  GEMM_LOADS(sb, 0);

  for (int kc = 0; kc < NCH; kc++) {
    int cur = kc & 1;
    if (kc + 1 < NCH) {
      GEMM_LOADS(sb + ((kc + 1) & 1) * STAGE_B, (kc + 1) * 32);
      CP_WAIT1();
    } else {
      CP_WAIT0();
    }
    __syncthreads();

    uint32_t stA = sb + cur * STAGE_B;
    uint32_t stAl = stA + TILE_A;
    uint32_t stB = stA + 2 * TILE_A;
    uint32_t stBl = stB + TILE_Bb;

#pragma unroll
    for (int ks = 0; ks < 32; ks += 16) {
      uint32_t bhf[16], blf[16];
#pragma unroll
      for (int j = 0; j < 4; j++) {
        uint32_t boff = (uint32_t)((wn * 64 + j * 16 + lrow) * 80 + (ks + lc8) * 2);
        LDSM_X4(bhf[j * 4], bhf[j * 4 + 1], bhf[j * 4 + 2], bhf[j * 4 + 3], stB + boff);
        LDSM_X4(blf[j * 4], blf[j * 4 + 1], blf[j * 4 + 2], blf[j * 4 + 3], stBl + boff);
      }
#pragma unroll
      for (int mb = 0; mb < 4; mb++) {
        uint32_t ah[4], al[4];
        uint32_t aoff = (uint32_t)((wm * 64 + mb * 16 + lrow) * 80 + (ks + lc8) * 2);
        LDSM_X4(ah[0], ah[1], ah[2], ah[3], stA + aoff);
        LDSM_X4(al[0], al[1], al[2], al[3], stAl + aoff);
#pragma unroll
        for (int nb = 0; nb < 8; nb++) {
          int j = nb >> 1, od = nb & 1;
          uint32_t b0h = bhf[j * 4 + od], b1h = bhf[j * 4 + od + 2];
          uint32_t b0l = blf[j * 4 + od], b1l = blf[j * 4 + od + 2];
          MMA16816(acc[mb][nb], ah[0], ah[1], ah[2], ah[3], b0h, b1h);
          MMA16816(acc[mb][nb], al[0], al[1], al[2], al[3], b0h, b1h);
          MMA16816(acc[mb][nb], ah[0], ah[1], ah[2], ah[3], b0l, b1l);
        }
      }
    }
    __syncthreads();
  }

  int erow = lane >> 2, ecol = (lane & 3) * 2;
#pragma unroll
  for (int mb = 0; mb < 4; mb++) {
#pragma unroll
    for (int nb = 0; nb < 8; nb++) {
      float* d = acc[mb][nb];
      int gr = m0 + wm * 64 + mb * 16 + erow;
      int gc = n0 + wn * 64 + nb * 8 + ecol;
      float2 b2 = *(const float2*)(bias + gc);
      float v0 = d[0] + b2.x, v1 = d[1] + b2.y;
      float v2 = d[2] + b2.x, v3 = d[3] + b2.y;
      if (EPI == 1) {
        v0 = gelu_f(v0); v1 = gelu_f(v1);
        v2 = gelu_f(v2); v3 = gelu_f(v3);
      } else if (EPI == 2) {
        float2 r0 = *(const float2*)(res + (size_t)gr * N + gc);
        float2 r1 = *(const float2*)(res + (size_t)(gr + 8) * N + gc);
        v0 += r0.x; v1 += r0.y; v2 += r1.x; v3 += r1.y;
      }
      if (EPI == 3) {
        int region = gc >> 10;           // 0 q, 1 k, 2 v
        int hh = (gc & 1023) >> 6;
        int dd = gc & 63;
        int b = gr >> 11;
        int n = gr & 2047;
        if (region < 2) {
          float inv = 1.0f / powf(10000.0f, (float)(dd & ~1) / 64.0f);
          float c0, s0, c1, s1;
          sincosf((float)n * inv, &s0, &c0);
          sincosf((float)(n + 8) * inv, &s1, &c1);
          float r0 = v0 * c0 - v1 * s0, r1 = v1 * c0 + v0 * s0;
          float r2 = v2 * c1 - v3 * s1, r3 = v3 * c1 + v2 * s1;
          v0 = r0; v1 = r1; v2 = r2; v3 = r3;
        }
        __nv_bfloat16* dh = (region == 0) ? qh_ : (region == 1) ? kh_ : vh_;
        __nv_bfloat16* dl = (region == 0) ? ql_ : (region == 1) ? kl_ : vl_;
        size_t o0 = ((size_t)((b * 16 + hh) * 2048 + n)) * 64 + dd;
        size_t o1 = o0 + 8 * 64;
        __nv_bfloat162 h01, h23, l01, l23;
        h01.x = __float2bfloat16(v0); h01.y = __float2bfloat16(v1);
        h23.x = __float2bfloat16(v2); h23.y = __float2bfloat16(v3);
        l01.x = __float2bfloat16(v0 - __bfloat162float(h01.x));
        l01.y = __float2bfloat16(v1 - __bfloat162float(h01.y));
        l23.x = __float2bfloat16(v2 - __bfloat162float(h23.x));
        l23.y = __float2bfloat16(v3 - __bfloat162float(h23.y));
        *(__nv_bfloat162*)(dh + o0) = h01;
        *(__nv_bfloat162*)(dl + o0) = l01;
        *(__nv_bfloat162*)(dh + o1) = h23;
        *(__nv_bfloat162*)(dl + o1) = l23;
      } else {
        float2 o0 = {v0, v1}, o1 = {v2, v3};
        *(float2*)(C + (size_t)gr * N + gc) = o0;
        *(float2*)(C + (size_t)(gr + 8) * N + gc) = o1;
      }
    }
  }
}

// ================= mma.sync flash attention =================
// 128-query tiles, 512 threads (4m x 4n warps, 32x16 micro-tiles),
// double-buffered K/V cp.async prefetch. 1 CTA/SM.
#define APB 144   // bytes per smem row (72 bf16)
#define A_oQh 0
#define A_oQl 18432
#define A_oKV0 36864          // Kh,Kl,Vh,Vl each 9216
#define A_oKV1 73728
#define A_oPh 110592
#define A_oPl 129024
#define A_oSf 147456          // 128 x 68 fp32
#define A_oSt 182272
#define ATTN_SMEM 184320

__global__ __launch_bounds__(512, 1) void attn_mma(
    const __nv_bfloat16* __restrict__ qh, const __nv_bfloat16* __restrict__ ql,
    const __nv_bfloat16* __restrict__ kh, const __nv_bfloat16* __restrict__ kl,
    const __nv_bfloat16* __restrict__ vh, const __nv_bfloat16* __restrict__ vl,
    __nv_bfloat16* __restrict__ oh, __nv_bfloat16* __restrict__ ol) {
  extern __shared__ char sm[];
  uint32_t sb = smem_u32(sm);
  float* Sf = (float*)(sm + A_oSf);
  float* m_s = (float*)(sm + A_oSt);
  float* l_s = m_s + 128;
  float* c_s = l_s + 128;

  int tid = threadIdx.x, wid = tid >> 5, lane = tid & 31;
  int wm = wid & 3, wn = wid >> 2;
  int lrow = lane & 15, lc8 = (lane >> 4) * 8;
  int erow = lane >> 2, ecol = (lane & 3) * 2;
  int bh = blockIdx.y, qt = blockIdx.x;
  size_t base = (size_t)bh * (2048 * 64);

  // Q tiles (128 rows)
  {
    const __nv_bfloat16* gqh = qh + base + (size_t)(qt * 128) * 64;
    const __nv_bfloat16* gql = ql + base + (size_t)(qt * 128) * 64;
#pragma unroll
    for (int i = 0; i < 2; i++) {
      int c = tid + i * 512;
      int r = c >> 3, c8 = c & 7;
      uint32_t so = (uint32_t)(r * APB + c8 * 16);
      CP_ASYNC16(sb + A_oQh + so, gqh + r * 64 + c8 * 8);
      CP_ASYNC16(sb + A_oQl + so, gql + r * 64 + c8 * 8);
    }
    CP_COMMIT();
  }

#define ATTN_KV_LOADS(stgoff, ktv)                                           \
  {                                                                          \
    int kt_ = (ktv);                                                         \
    int r = tid >> 3, c8 = tid & 7;                                          \
    uint32_t so = (uint32_t)(r * APB + c8 * 16);                             \
    size_t go = base + (size_t)(kt_ * 64 + r) * 64 + c8 * 8;                 \
    uint32_t d0 = sb + (stgoff);                                             \
    CP_ASYNC16(d0 + so, kh + go);                                            \
    CP_ASYNC16(d0 + 9216 + so, kl + go);                                     \
    CP_ASYNC16(d0 + 18432 + so, vh + go);                                    \
    CP_ASYNC16(d0 + 27648 + so, vl + go);                                    \
    CP_COMMIT();                                                             \
  }

  ATTN_KV_LOADS(A_oKV0, 0);

  if (tid < 128) { m_s[tid] = -INFINITY; l_s[tid] = 0.f; }

  float oacc[2][2][4];
#pragma unroll
  for (int a = 0; a < 2; a++)
#pragma unroll
    for (int b = 0; b < 2; b++)
#pragma unroll
      for (int t = 0; t < 4; t++) oacc[a][b][t] = 0.f;

  const float scale = 0.125f;
  int q_s = tid >> 2, kg = tid & 3;

  for (int kt = 0; kt < 32; kt++) {
    if (kt) __syncthreads();  // prior PV reads of the stage we're about to fill
    uint32_t kvcur = (kt & 1) ? A_oKV1 : A_oKV0;
    if (kt + 1 < 32) {
      ATTN_KV_LOADS((kt & 1) ? A_oKV0 : A_oKV1, kt + 1);
      CP_WAIT1();
    } else {
      CP_WAIT0();
    }
    __syncthreads();

    uint32_t sKh = sb + kvcur, sKl = sKh + 9216;
    uint32_t sVh = sKl + 9216, sVl = sVh + 9216;

    // ---- S = scale * Q K^T (3-term split) ----
    float sacc[2][2][4];
#pragma unroll
    for (int a = 0; a < 2; a++)
#pragma unroll
      for (int b = 0; b < 2; b++)
#pragma unroll
        for (int t = 0; t < 4; t++) sacc[a][b][t] = 0.f;
#pragma unroll
    for (int ks = 0; ks < 64; ks += 16) {
      uint32_t bhf[4], blf[4];
      uint32_t boff = (uint32_t)((wn * 16 + lrow) * APB + (ks + lc8) * 2);
      LDSM_X4(bhf[0], bhf[1], bhf[2], bhf[3], sKh + boff);
      LDSM_X4(blf[0], blf[1], blf[2], blf[3], sKl + boff);
#pragma unroll
      for (int mb = 0; mb < 2; mb++) {
        uint32_t ahf[4], alf[4];
        uint32_t aoff = (uint32_t)((wm * 32 + mb * 16 + lrow) * APB + (ks + lc8) * 2);
        LDSM_X4(ahf[0], ahf[1], ahf[2], ahf[3], sb + A_oQh + aoff);
        LDSM_X4(alf[0], alf[1], alf[2], alf[3], sb + A_oQl + aoff);
#pragma unroll
        for (int nb = 0; nb < 2; nb++) {
          uint32_t b0h = bhf[nb], b1h = bhf[nb + 2];
          uint32_t b0l = blf[nb], b1l = blf[nb + 2];
          MMA16816(sacc[mb][nb], ahf[0], ahf[1], ahf[2], ahf[3], b0h, b1h);
          MMA16816(sacc[mb][nb], alf[0], alf[1], alf[2], alf[3], b0h, b1h);
          MMA16816(sacc[mb][nb], ahf[0], ahf[1], ahf[2], ahf[3], b0l, b1l);
        }
      }
    }
#pragma unroll
    for (int mb = 0; mb < 2; mb++)
#pragma unroll
      for (int nb = 0; nb < 2; nb++) {
        int q = wm * 32 + mb * 16 + erow;
        int k = wn * 16 + nb * 8 + ecol;
        float2 s01 = {sacc[mb][nb][0] * scale, sacc[mb][nb][1] * scale};
        float2 s23 = {sacc[mb][nb][2] * scale, sacc[mb][nb][3] * scale};
        *(float2*)(&Sf[q * 68 + k]) = s01;
        *(float2*)(&Sf[(q + 8) * 68 + k]) = s23;
      }
    __syncthreads();

    // ---- online softmax (4 threads per query row) ----
    {
      float rowmax = -INFINITY;
#pragma unroll
      for (int j = 0; j < 16; j++)
        rowmax = fmaxf(rowmax, Sf[q_s * 68 + kg * 16 + j]);
      rowmax = fmaxf(rowmax, __shfl_xor_sync(0xffffffff, rowmax, 1));
      rowmax = fmaxf(rowmax, __shfl_xor_sync(0xffffffff, rowmax, 2));
      float mold = m_s[q_s];
      float newm = fmaxf(mold, rowmax);
      float c = __expf(mold - newm);
      float part = 0.f;
#pragma unroll
      for (int j = 0; j < 16; j += 2) {
        int k = kg * 16 + j;
        float p0 = __expf(Sf[q_s * 68 + k] - newm);
        float p1 = __expf(Sf[q_s * 68 + k + 1] - newm);
        part += p0 + p1;
        __nv_bfloat162 ph2, pl2;
        ph2.x = __float2bfloat16(p0); ph2.y = __float2bfloat16(p1);
        pl2.x = __float2bfloat16(p0 - __bfloat162float(ph2.x));
        pl2.y = __float2bfloat16(p1 - __bfloat162float(ph2.y));
        *(__nv_bfloat162*)(sm + A_oPh + q_s * APB + k * 2) = ph2;
        *(__nv_bfloat162*)(sm + A_oPl + q_s * APB + k * 2) = pl2;
      }
      part += __shfl_xor_sync(0xffffffff, part, 1);
      part += __shfl_xor_sync(0xffffffff, part, 2);
      if (kg == 0) {
        m_s[q_s] = newm;
        c_s[q_s] = c;
        l_s[q_s] = l_s[q_s] * c + part;
      }
    }
    __syncthreads();

    // ---- O = O*c + P V (3-term split) ----
#pragma unroll
    for (int mb = 0; mb < 2; mb++) {
      float cc0 = c_s[wm * 32 + mb * 16 + erow];
      float cc1 = c_s[wm * 32 + mb * 16 + erow + 8];
#pragma unroll
      for (int nb = 0; nb < 2; nb++) {
        oacc[mb][nb][0] *= cc0; oacc[mb][nb][1] *= cc0;
        oacc[mb][nb][2] *= cc1; oacc[mb][nb][3] *= cc1;
      }
    }
#pragma unroll
    for (int ks = 0; ks < 64; ks += 16) {
      uint32_t vbh[4], vbl[4];
      uint32_t voff = (uint32_t)((ks + lrow) * APB + (wn * 16 + lc8) * 2);
      LDSM_X4_T(vbh[0], vbh[1], vbh[2], vbh[3], sVh + voff);
      LDSM_X4_T(vbl[0], vbl[1], vbl[2], vbl[3], sVl + voff);
#pragma unroll
      for (int mb = 0; mb < 2; mb++) {
        uint32_t pa[4], pla[4];
        uint32_t poff = (uint32_t)((wm * 32 + mb * 16 + lrow) * APB + (ks + lc8) * 2);
        LDSM_X4(pa[0], pa[1], pa[2], pa[3], sb + A_oPh + poff);
        LDSM_X4(pla[0], pla[1], pla[2], pla[3], sb + A_oPl + poff);
#pragma unroll
        for (int nb = 0; nb < 2; nb++) {
          uint32_t b0h = vbh[nb * 2], b1h = vbh[nb * 2 + 1];
          uint32_t b0l = vbl[nb * 2], b1l = vbl[nb * 2 + 1];
          MMA16816(oacc[mb][nb], pa[0], pa[1], pa[2], pa[3], b0h, b1h);
          MMA16816(oacc[mb][nb], pla[0], pla[1], pla[2], pla[3], b0h, b1h);
          MMA16816(oacc[mb][nb], pa[0], pa[1], pa[2], pa[3], b0l, b1l);
        }
      }
    }
  }
  __syncthreads();

  // ---- output: O / l -> bf16 hi/lo at [B,N,C] ----
  int b = bh >> 4, h = bh & 15;
#pragma unroll
  for (int mb = 0; mb < 2; mb++) {
    int q = wm * 32 + mb * 16 + erow;
    float il0 = 1.f / l_s[q];
    float il1 = 1.f / l_s[q + 8];
#pragma unroll
    for (int nb = 0; nb < 2; nb++) {
      int d = wn * 16 + nb * 8 + ecol;
      float v0 = oacc[mb][nb][0] * il0, v1 = oacc[mb][nb][1] * il0;
      float v2 = oacc[mb][nb][2] * il1, v3 = oacc[mb][nb][3] * il1;
      size_t off0 = ((size_t)(b * 2048 + qt * 128 + q)) * 1024 + h * 64 + d;
      size_t off8 = off0 + 8 * 1024;
      __nv_bfloat162 h01, h23, l01, l23;
      h01.x = __float2bfloat16(v0); h01.y = __float2bfloat16(v1);
      h23.x = __float2bfloat16(v2); h23.y = __float2bfloat16(v3);
      l01.x = __float2bfloat16(v0 - __bfloat162float(h01.x));
      l01.y = __float2bfloat16(v1 - __bfloat162float(h01.y));
      l23.x = __float2bfloat16(v2 - __bfloat162float(h23.x));
      l23.y = __float2bfloat16(v3 - __bfloat162float(h23.y));
      *(__nv_bfloat162*)(oh + off0) = h01;
      *(__nv_bfloat162*)(ol + off0) = l01;
      *(__nv_bfloat162*)(oh + off8) = h23;
      *(__nv_bfloat162*)(ol + off8) = l23;
    }
  }
}

// ================= launch =================
#define GEMM_SMEM (2 * STAGE_B)   // 122880 bytes

extern "C" void kernel_launch(void* const* d_in, const int* in_sizes, int n_in,
                              void* d_out, int out_size) {
  const float* x = (const float*)d_in[0];
  const float* ln1_g = (const float*)d_in[1];
  const float* ln1_b = (const float*)d_in[2];
  const float* qkv_w = (const float*)d_in[3];
  const float* qkv_b = (const float*)d_in[4];
  const float* proj_w = (const float*)d_in[5];
  const float* proj_b = (const float*)d_in[6];
  const float* ln2_g = (const float*)d_in[7];
  const float* ln2_b = (const float*)d_in[8];
  const float* fc1_w = (const float*)d_in[9];
  const float* fc1_b = (const float*)d_in[10];
  const float* ffln_g = (const float*)d_in[11];
  const float* ffln_b = (const float*)d_in[12];
  const float* fc2_w = (const float*)d_in[13];
  const float* fc2_b = (const float*)d_in[14];
  float* out = (float*)d_out;

  float *x1, *h1;
  __nv_bfloat16 *ah, *al, *atth, *attl;
  __nv_bfloat16 *qh, *ql, *kh, *kl, *vh, *vl;
  __nv_bfloat16 *wqh, *wql, *wph, *wpl, *w1h, *w1l, *w2h, *w2l;
  cudaGetSymbolAddress((void**)&x1, g_x1);
  cudaGetSymbolAddress((void**)&h1, g_h1);
  cudaGetSymbolAddress((void**)&ah, g_ah);
  cudaGetSymbolAddress((void**)&al, g_al);
  cudaGetSymbolAddress((void**)&atth, g_atth);
  cudaGetSymbolAddress((void**)&attl, g_attl);
  cudaGetSymbolAddress((void**)&qh, g_qh2);
  cudaGetSymbolAddress((void**)&ql, g_ql2);
  cudaGetSymbolAddress((void**)&kh, g_kh2);
  cudaGetSymbolAddress((void**)&kl, g_kl2);
  cudaGetSymbolAddress((void**)&vh, g_vh2);
  cudaGetSymbolAddress((void**)&vl, g_vl2);
  cudaGetSymbolAddress((void**)&wqh, g_wqh);
  cudaGetSymbolAddress((void**)&wql, g_wql);
  cudaGetSymbolAddress((void**)&wph, g_wph);
  cudaGetSymbolAddress((void**)&wpl, g_wpl);
  cudaGetSymbolAddress((void**)&w1h, g_w1h);
  cudaGetSymbolAddress((void**)&w1l, g_w1l);
  cudaGetSymbolAddress((void**)&w2h, g_w2h);
  cudaGetSymbolAddress((void**)&w2l, g_w2l);

  cudaFuncSetAttribute(gemm_mma<0>, cudaFuncAttributeMaxDynamicSharedMemorySize, GEMM_SMEM);
  cudaFuncSetAttribute(gemm_mma<1>, cudaFuncAttributeMaxDynamicSharedMemorySize, GEMM_SMEM);
  cudaFuncSetAttribute(gemm_mma<2>, cudaFuncAttributeMaxDynamicSharedMemorySize, GEMM_SMEM);
  cudaFuncSetAttribute(gemm_mma<3>, cudaFuncAttributeMaxDynamicSharedMemorySize, GEMM_SMEM);
  cudaFuncSetAttribute(attn_mma, cudaFuncAttributeMaxDynamicSharedMemorySize, ATTN_SMEM);

  wconv_kernel<<<dim3(3072 / 32, 1024 / 32), 256>>>(qkv_w, wqh, wql, 1024, 3072);
  wconv_kernel<<<dim3(1024 / 32, 1024 / 32), 256>>>(proj_w, wph, wpl, 1024, 1024);
  wconv_kernel<<<dim3(4096 / 32, 1024 / 32), 256>>>(fc1_w, w1h, w1l, 1024, 4096);
  wconv_kernel<<<dim3(1024 / 32, 4096 / 32), 256>>>(fc2_w, w2h, w2l, 4096, 1024);

  // 1) LN1 -> bf16 hi/lo
  ln_bf_kernel<1><<<ROWS, 256>>>(x, ln1_g, ln1_b, ah, al);
  // 2) QKV GEMM + RoPE + split write (EPI 3)
  gemm_mma<3><<<dim3(3072 / 256, ROWS / 128), 256, GEMM_SMEM>>>(
      ah, al, wqh, wql, qkv_b, nullptr, nullptr, 1024, 3072,
      qh, ql, kh, kl, vh, vl);
  // 3) attention (tensor-core flash, 128q tiles)
  attn_mma<<<dim3(NNq / 128, BB * HHn), 512, ATTN_SMEM>>>(
      qh, ql, kh, kl, vh, vl, atth, attl);
  // 4) proj + residual(x) -> x1
  gemm_mma<2><<<dim3(1024 / 256, ROWS / 128), 256, GEMM_SMEM>>>(
      atth, attl, wph, wpl, proj_b, x, x1, 1024, 1024,
      nullptr, nullptr, nullptr, nullptr, nullptr, nullptr);
  // 5) LN2 -> bf16 hi/lo
  ln_bf_kernel<1><<<ROWS, 256>>>(x1, ln2_g, ln2_b, ah, al);
  // 6) fc1 + GELU -> fp32 h1
  gemm_mma<1><<<dim3(4096 / 256, ROWS / 128), 256, GEMM_SMEM>>>(
      ah, al, w1h, w1l, fc1_b, nullptr, h1, 1024, 4096,
      nullptr, nullptr, nullptr, nullptr, nullptr, nullptr);
  // 7) ffn LN (4096 wide) -> bf16 hi/lo
  ln_bf_kernel<4><<<ROWS, 256>>>(h1, ffln_g, ffln_b, ah, al);
  // 8) fc2 + residual(x1) -> out
  gemm_mma<2><<<dim3(1024 / 256, ROWS / 128), 256, GEMM_SMEM>>>(
      ah, al, w2h, w2l, fc2_b, x1, out, 4096, 1024,
      nullptr, nullptr, nullptr, nullptr, nullptr, nullptr);
}

// round 6
// speedup vs baseline: 1.4672x; 1.4672x over previous
#include <cuda_runtime.h>
#include <cuda_fp16.h>
#include <math.h>
#include <stdint.h>

#define BB 2
#define NNq 2048
#define CCd 1024
#define HHn 16
#define HIDd 4096
#define ROWS (BB * NNq)   // 4096

// ================= scratch (device globals) =================
__device__ float g_x1[ROWS * CCd];
__device__ float g_h1[ROWS * HIDd];
__device__ __half g_ah[ROWS * HIDd];           // activation hi
__device__ __half g_al[ROWS * HIDd];           // activation lo
__device__ __half g_atth[ROWS * CCd];
__device__ __half g_attl[ROWS * CCd];
__device__ __half g_qh2[ROWS * CCd], g_ql2[ROWS * CCd];   // q hi/lo [B,H,N,D]
__device__ __half g_kh2[ROWS * CCd];                      // k hi only
__device__ __half g_vh2[ROWS * CCd];                      // v hi only
__device__ __half g_wq[3072 * 1024];
__device__ __half g_wp[1024 * 1024];
__device__ __half g_w1[4096 * 1024];
__device__ __half g_w2[1024 * 4096];

// ================= helpers =================
__device__ __forceinline__ uint32_t smem_u32(const void* p) {
  uint32_t a;
  asm("{ .reg .u64 t; cvta.to.shared.u64 t, %1; cvt.u32.u64 %0, t; }"
      : "=r"(a) : "l"(p));
  return a;
}

#define CP_ASYNC16(sm, gp) \
  asm volatile("cp.async.cg.shared.global [%0], [%1], 16;" \
               :: "r"(sm), "l"(gp) : "memory")
#define CP_COMMIT() asm volatile("cp.async.commit_group;" ::: "memory")
#define CP_WAIT0() asm volatile("cp.async.wait_group 0;" ::: "memory")
#define CP_WAIT1() asm volatile("cp.async.wait_group 1;" ::: "memory")

#define LDSM_X4(r0, r1, r2, r3, a) \
  asm volatile("ldmatrix.sync.aligned.m8n8.x4.shared.b16 {%0,%1,%2,%3}, [%4];" \
               : "=r"(r0), "=r"(r1), "=r"(r2), "=r"(r3) : "r"(a))
#define LDSM_X4_T(r0, r1, r2, r3, a) \
  asm volatile("ldmatrix.sync.aligned.m8n8.x4.trans.shared.b16 {%0,%1,%2,%3}, [%4];" \
               : "=r"(r0), "=r"(r1), "=r"(r2), "=r"(r3) : "r"(a))

#define MMA16816(d, a0, a1, a2, a3, b0, b1) \
  asm volatile("mma.sync.aligned.m16n8k16.row.col.f32.f16.f16.f32 " \
               "{%0,%1,%2,%3}, {%4,%5,%6,%7}, {%8,%9}, {%0,%1,%2,%3};" \
               : "+f"((d)[0]), "+f"((d)[1]), "+f"((d)[2]), "+f"((d)[3]) \
               : "r"(a0), "r"(a1), "r"(a2), "r"(a3), "r"(b0), "r"(b1))

__device__ __forceinline__ float gelu_f(float v) {
  return 0.5f * v * (1.f + erff(v * 0.70710678118654752f));
}

// ================= weight convert + transpose (fp32 [K,N] -> fp16 [N,K]) ===
__global__ __launch_bounds__(256) void wconv_kernel(
    const float* __restrict__ W, __half* __restrict__ th, int K, int N) {
  __shared__ float t[32][33];
  int n0 = blockIdx.x * 32, k0 = blockIdx.y * 32;
  int tx = threadIdx.x & 31, ty = threadIdx.x >> 5;
#pragma unroll
  for (int i = 0; i < 4; i++)
    t[ty + i * 8][tx] = W[(size_t)(k0 + ty + i * 8) * N + n0 + tx];
  __syncthreads();
#pragma unroll
  for (int i = 0; i < 4; i++) {
    float v = t[tx][ty + i * 8];
    th[(size_t)(n0 + ty + i * 8) * K + k0 + tx] = __float2half_rn(v);
  }
}

// ================= LayerNorm -> fp16 hi/lo =================
template <int NIT>
__global__ __launch_bounds__(256) void ln_h_kernel(
    const float* __restrict__ in, const float* __restrict__ gw,
    const float* __restrict__ bw, __half* __restrict__ oh,
    __half* __restrict__ ol) {
  const int cols = NIT * 1024;
  int row = blockIdx.x;
  const float* rp = in + (size_t)row * cols;
  float4 buf[NIT];
  float s = 0.f, sq = 0.f;
#pragma unroll
  for (int it = 0; it < NIT; it++) {
    int c = (it * 256 + threadIdx.x) * 4;
    float4 v = *(const float4*)(rp + c);
    buf[it] = v;
    s += v.x + v.y + v.z + v.w;
    sq += v.x * v.x + v.y * v.y + v.z * v.z + v.w * v.w;
  }
  __shared__ float red0[8], red1[8];
#pragma unroll
  for (int o = 16; o; o >>= 1) {
    s += __shfl_xor_sync(0xffffffff, s, o);
    sq += __shfl_xor_sync(0xffffffff, sq, o);
  }
  int warp = threadIdx.x >> 5, lane = threadIdx.x & 31;
  if (lane == 0) { red0[warp] = s; red1[warp] = sq; }
  __syncthreads();
  __shared__ float s_mu, s_ri;
  if (threadIdx.x == 0) {
    float ts = 0.f, tq = 0.f;
#pragma unroll
    for (int i = 0; i < 8; i++) { ts += red0[i]; tq += red1[i]; }
    float mu = ts / (float)cols;
    float var = tq / (float)cols - mu * mu;
    s_mu = mu;
    s_ri = rsqrtf(var + 1e-5f);
  }
  __syncthreads();
  float mu = s_mu, ri = s_ri;
#pragma unroll
  for (int it = 0; it < NIT; it++) {
    int c = (it * 256 + threadIdx.x) * 4;
    float4 v = buf[it];
    float4 g4 = *(const float4*)(gw + c);
    float4 b4 = *(const float4*)(bw + c);
    float o0 = (v.x - mu) * ri * g4.x + b4.x;
    float o1 = (v.y - mu) * ri * g4.y + b4.y;
    float o2 = (v.z - mu) * ri * g4.z + b4.z;
    float o3 = (v.w - mu) * ri * g4.w + b4.w;
    __half2 h01, h23, l01, l23;
    h01.x = __float2half_rn(o0); h01.y = __float2half_rn(o1);
    h23.x = __float2half_rn(o2); h23.y = __float2half_rn(o3);
    l01.x = __float2half_rn(o0 - __half2float(h01.x));
    l01.y = __float2half_rn(o1 - __half2float(h01.y));
    l23.x = __float2half_rn(o2 - __half2float(h23.x));
    l23.y = __float2half_rn(o3 - __half2float(h23.y));
    size_t o = (size_t)row * cols + c;
    *(__half2*)(oh + o) = h01;
    *(__half2*)(oh + o + 2) = h23;
    *(__half2*)(ol + o) = l01;
    *(__half2*)(ol + o + 2) = l23;
  }
}

// ================= mma.sync fp16 2-term GEMM =================
// C = (Ah+Al)[M,K] @ Bh^T + bias, Bh stored [N,K] (weights truncated fp16).
// Tile 128x128x32, 8 warps (2m x 4n), warp 64x32, 2-stage cp.async, 2 CTA/SM.
// EPI 0: bias; 1: +GELU; 2: +residual; 3: QKV (bias + RoPE + split write).
#define TILE_H 10240                // 128 rows * 40 pitch * 2B
#define STAGE_H (3 * TILE_H)        // Ah, Al, Bh

template <int EPI>
__global__ __launch_bounds__(256, 2) void gemm_mma(
    const __half* __restrict__ Ah, const __half* __restrict__ Al,
    const __half* __restrict__ Bh,
    const float* __restrict__ bias, const float* __restrict__ res,
    float* __restrict__ C, int K, int N,
    __half* qh_, __half* ql_, __half* kh_, __half* vh_) {
  extern __shared__ char smem[];
  uint32_t sb = smem_u32(smem);
  int tid = threadIdx.x, wid = tid >> 5, lane = tid & 31;
  int m0 = blockIdx.y * 128, n0 = blockIdx.x * 128;
  int wm = wid & 1, wn = wid >> 1;
  int lrow = lane & 15, lc8 = (lane >> 4) * 8;

  float acc[4][4][4];
#pragma unroll
  for (int i = 0; i < 4; i++)
#pragma unroll
    for (int j = 0; j < 4; j++)
#pragma unroll
      for (int t = 0; t < 4; t++) acc[i][j][t] = 0.f;

  int NCH = K >> 5;

#define GEMM_LOADS(stgbase, ktv)                                             \
  {                                                                          \
    uint32_t stg = (stgbase);                                                \
    int kt = (ktv);                                                          \
    _Pragma("unroll") for (int i = 0; i < 2; i++) {                          \
      int c = tid + i * 256;                                                 \
      int r = c >> 2, q = c & 3;                                             \
      uint32_t so = (uint32_t)(r * 80 + q * 16);                             \
      CP_ASYNC16(stg + so, Ah + (size_t)(m0 + r) * K + kt + q * 8);          \
      CP_ASYNC16(stg + TILE_H + so, Al + (size_t)(m0 + r) * K + kt + q * 8); \
      CP_ASYNC16(stg + 2 * TILE_H + so,                                      \
                 Bh + (size_t)(n0 + r) * K + kt + q * 8);                    \
    }                                                                        \
    CP_COMMIT();                                                             \
  }

  GEMM_LOADS(sb, 0);

  for (int kc = 0; kc < NCH; kc++) {
    int cur = kc & 1;
    if (kc + 1 < NCH) {
      GEMM_LOADS(sb + ((kc + 1) & 1) * STAGE_H, (kc + 1) * 32);
      CP_WAIT1();
    } else {
      CP_WAIT0();
    }
    __syncthreads();

    uint32_t stA = sb + cur * STAGE_H;
    uint32_t stAl = stA + TILE_H;
    uint32_t stB = stA + 2 * TILE_H;

#pragma unroll
    for (int ks = 0; ks < 32; ks += 16) {
      uint32_t bhf[8];
      uint32_t boff0 = (uint32_t)((wn * 32 + lrow) * 80 + (ks + lc8) * 2);
      uint32_t boff1 = (uint32_t)((wn * 32 + 16 + lrow) * 80 + (ks + lc8) * 2);
      LDSM_X4(bhf[0], bhf[1], bhf[2], bhf[3], stB + boff0);
      LDSM_X4(bhf[4], bhf[5], bhf[6], bhf[7], stB + boff1);
#pragma unroll
      for (int mb = 0; mb < 4; mb++) {
        uint32_t ah[4], al[4];
        uint32_t aoff = (uint32_t)((wm * 64 + mb * 16 + lrow) * 80 + (ks + lc8) * 2);
        LDSM_X4(ah[0], ah[1], ah[2], ah[3], stA + aoff);
        LDSM_X4(al[0], al[1], al[2], al[3], stAl + aoff);
#pragma unroll
        for (int nb = 0; nb < 4; nb++) {
          int pi = (nb >> 1) * 4, od = nb & 1;
          uint32_t b0 = bhf[pi + od], b1 = bhf[pi + 2 + od];
          MMA16816(acc[mb][nb], ah[0], ah[1], ah[2], ah[3], b0, b1);
          MMA16816(acc[mb][nb], al[0], al[1], al[2], al[3], b0, b1);
        }
      }
    }
    __syncthreads();
  }

  int erow = lane >> 2, ecol = (lane & 3) * 2;
#pragma unroll
  for (int mb = 0; mb < 4; mb++) {
#pragma unroll
    for (int nb = 0; nb < 4; nb++) {
      float* d = acc[mb][nb];
      int gr = m0 + wm * 64 + mb * 16 + erow;
      int gc = n0 + wn * 32 + nb * 8 + ecol;
      float2 b2 = *(const float2*)(bias + gc);
      float v0 = d[0] + b2.x, v1 = d[1] + b2.y;
      float v2 = d[2] + b2.x, v3 = d[3] + b2.y;
      if (EPI == 1) {
        v0 = gelu_f(v0); v1 = gelu_f(v1);
        v2 = gelu_f(v2); v3 = gelu_f(v3);
      } else if (EPI == 2) {
        float2 r0 = *(const float2*)(res + (size_t)gr * N + gc);
        float2 r1 = *(const float2*)(res + (size_t)(gr + 8) * N + gc);
        v0 += r0.x; v1 += r0.y; v2 += r1.x; v3 += r1.y;
      }
      if (EPI == 3) {
        int region = gc >> 10;           // 0 q, 1 k, 2 v
        int hh = (gc & 1023) >> 6;
        int dd = gc & 63;
        int b = gr >> 11;
        int n = gr & 2047;
        if (region < 2) {
          float inv = 1.0f / powf(10000.0f, (float)(dd & ~1) / 64.0f);
          float c0, s0, c1, s1;
          sincosf((float)n * inv, &s0, &c0);
          sincosf((float)(n + 8) * inv, &s1, &c1);
          float r0 = v0 * c0 - v1 * s0, r1 = v1 * c0 + v0 * s0;
          float r2 = v2 * c1 - v3 * s1, r3 = v3 * c1 + v2 * s1;
          v0 = r0; v1 = r1; v2 = r2; v3 = r3;
        }
        size_t o0 = ((size_t)((b * 16 + hh) * 2048 + n)) * 64 + dd;
        size_t o1 = o0 + 8 * 64;
        if (region == 0) {
          __half2 h01, h23, l01, l23;
          h01.x = __float2half_rn(v0); h01.y = __float2half_rn(v1);
          h23.x = __float2half_rn(v2); h23.y = __float2half_rn(v3);
          l01.x = __float2half_rn(v0 - __half2float(h01.x));
          l01.y = __float2half_rn(v1 - __half2float(h01.y));
          l23.x = __float2half_rn(v2 - __half2float(h23.x));
          l23.y = __float2half_rn(v3 - __half2float(h23.y));
          *(__half2*)(qh_ + o0) = h01;
          *(__half2*)(ql_ + o0) = l01;
          *(__half2*)(qh_ + o1) = h23;
          *(__half2*)(ql_ + o1) = l23;
        } else {
          __half* dst = (region == 1) ? kh_ : vh_;
          __half2 h01, h23;
          h01.x = __float2half_rn(v0); h01.y = __float2half_rn(v1);
          h23.x = __float2half_rn(v2); h23.y = __float2half_rn(v3);
          *(__half2*)(dst + o0) = h01;
          *(__half2*)(dst + o1) = h23;
        }
      } else {
        float2 o0 = {v0, v1}, o1 = {v2, v3};
        *(float2*)(C + (size_t)gr * N + gc) = o0;
        *(float2*)(C + (size_t)(gr + 8) * N + gc) = o1;
      }
    }
  }
}

// ================= mma.sync flash attention (fp16 2-term) =================
// 64-query tiles, 256 threads (2m x 4n warps), Q full (hi/lo), K/V truncated,
// P full (hi/lo). Double-buffered K/V cp.async. 2 CTAs/SM.
#define APB 144   // bytes per smem row (72 fp16)
#define A_oQh 0
#define A_oQl 9216
#define A_oK0 18432
#define A_oV0 27648
#define A_oK1 36864
#define A_oV1 46080
#define A_oPh 55296
#define A_oPl 64512
#define A_oSf 73728          // 64 x 68 fp32 = 17408
#define A_oSt 91136
#define ATTN_SMEM 92160

__global__ __launch_bounds__(256, 2) void attn_mma(
    const __half* __restrict__ qh, const __half* __restrict__ ql,
    const __half* __restrict__ kh, const __half* __restrict__ vh,
    __half* __restrict__ oh, __half* __restrict__ ol) {
  extern __shared__ char sm[];
  uint32_t sb = smem_u32(sm);
  float* Sf = (float*)(sm + A_oSf);
  float* m_s = (float*)(sm + A_oSt);
  float* l_s = m_s + 64;
  float* c_s = l_s + 64;

  int tid = threadIdx.x, wid = tid >> 5, lane = tid & 31;
  int wm = wid & 1, wn = wid >> 1;
  int lrow = lane & 15, lc8 = (lane >> 4) * 8;
  int erow = lane >> 2, ecol = (lane & 3) * 2;
  int bh = blockIdx.y, qt = blockIdx.x;
  size_t base = (size_t)bh * (2048 * 64);

  // Q tiles (hi/lo)
  {
    const __half* gqh = qh + base + (size_t)(qt * 64) * 64;
    const __half* gql = ql + base + (size_t)(qt * 64) * 64;
#pragma unroll
    for (int i = 0; i < 2; i++) {
      int f = tid + i * 256;
      int r = f >> 3, c8 = f & 7;
      uint32_t so = (uint32_t)(r * APB + c8 * 16);
      CP_ASYNC16(sb + A_oQh + so, gqh + r * 64 + c8 * 8);
      CP_ASYNC16(sb + A_oQl + so, gql + r * 64 + c8 * 8);
    }
    CP_COMMIT();
  }

#define ATTN_KV_LOADS(koff, voff_, ktv)                                      \
  {                                                                          \
    int kt_ = (ktv);                                                         \
    _Pragma("unroll") for (int i = 0; i < 2; i++) {                          \
      int f = tid + i * 256;                                                 \
      int r = f >> 3, c8 = f & 7;                                            \
      uint32_t so = (uint32_t)(r * APB + c8 * 16);                           \
      size_t go = base + (size_t)(kt_ * 64 + r) * 64 + c8 * 8;               \
      CP_ASYNC16(sb + (koff) + so, kh + go);                                 \
      CP_ASYNC16(sb + (voff_) + so, vh + go);                                \
    }                                                                        \
    CP_COMMIT();                                                             \
  }

  ATTN_KV_LOADS(A_oK0, A_oV0, 0);

  if (tid < 64) { m_s[tid] = -INFINITY; l_s[tid] = 0.f; }

  float oacc[2][2][4];
#pragma unroll
  for (int a = 0; a < 2; a++)
#pragma unroll
    for (int b = 0; b < 2; b++)
#pragma unroll
      for (int t = 0; t < 4; t++) oacc[a][b][t] = 0.f;

  const float scale = 0.125f;
  int q_s = tid >> 2, kg = tid & 3;

  for (int kt = 0; kt < 32; kt++) {
    if (kt) __syncthreads();  // prior PV reads of the stage about to be refilled
    uint32_t sK = (kt & 1) ? (sb + A_oK1) : (sb + A_oK0);
    uint32_t sV = sK + 9216;
    if (kt + 1 < 32) {
      if (kt & 1) { ATTN_KV_LOADS(A_oK0, A_oV0, kt + 1); }
      else        { ATTN_KV_LOADS(A_oK1, A_oV1, kt + 1); }
      CP_WAIT1();
    } else {
      CP_WAIT0();
    }
    __syncthreads();

    // ---- S = scale * (Qh+Ql) Kh^T ----
    float sacc[2][2][4];
#pragma unroll
    for (int a = 0; a < 2; a++)
#pragma unroll
      for (int b = 0; b < 2; b++)
#pragma unroll
        for (int t = 0; t < 4; t++) sacc[a][b][t] = 0.f;
#pragma unroll
    for (int ks = 0; ks < 64; ks += 16) {
      uint32_t bhf[4];
      uint32_t boff = (uint32_t)((wn * 16 + lrow) * APB + (ks + lc8) * 2);
      LDSM_X4(bhf[0], bhf[1], bhf[2], bhf[3], sK + boff);
#pragma unroll
      for (int mb = 0; mb < 2; mb++) {
        uint32_t ahf[4], alf[4];
        uint32_t aoff = (uint32_t)((wm * 32 + mb * 16 + lrow) * APB + (ks + lc8) * 2);
        LDSM_X4(ahf[0], ahf[1], ahf[2], ahf[3], sb + A_oQh + aoff);
        LDSM_X4(alf[0], alf[1], alf[2], alf[3], sb + A_oQl + aoff);
#pragma unroll
        for (int nb = 0; nb < 2; nb++) {
          uint32_t b0 = bhf[nb], b1 = bhf[nb + 2];
          MMA16816(sacc[mb][nb], ahf[0], ahf[1], ahf[2], ahf[3], b0, b1);
          MMA16816(sacc[mb][nb], alf[0], alf[1], alf[2], alf[3], b0, b1);
        }
      }
    }
#pragma unroll
    for (int mb = 0; mb < 2; mb++)
#pragma unroll
      for (int nb = 0; nb < 2; nb++) {
        int q = wm * 32 + mb * 16 + erow;
        int k = wn * 16 + nb * 8 + ecol;
        float2 s01 = {sacc[mb][nb][0] * scale, sacc[mb][nb][1] * scale};
        float2 s23 = {sacc[mb][nb][2] * scale, sacc[mb][nb][3] * scale};
        *(float2*)(&Sf[q * 68 + k]) = s01;
        *(float2*)(&Sf[(q + 8) * 68 + k]) = s23;
      }
    __syncthreads();

    // ---- online softmax (4 threads per query row) ----
    {
      float rowmax = -INFINITY;
#pragma unroll
      for (int j = 0; j < 16; j++)
        rowmax = fmaxf(rowmax, Sf[q_s * 68 + kg * 16 + j]);
      rowmax = fmaxf(rowmax, __shfl_xor_sync(0xffffffff, rowmax, 1));
      rowmax = fmaxf(rowmax, __shfl_xor_sync(0xffffffff, rowmax, 2));
      float mold = m_s[q_s];
      float newm = fmaxf(mold, rowmax);
      float c = __expf(mold - newm);
      float part = 0.f;
#pragma unroll
      for (int j = 0; j < 16; j += 2) {
        int k = kg * 16 + j;
        float p0 = __expf(Sf[q_s * 68 + k] - newm);
        float p1 = __expf(Sf[q_s * 68 + k + 1] - newm);
        part += p0 + p1;
        __half2 ph2, pl2;
        ph2.x = __float2half_rn(p0); ph2.y = __float2half_rn(p1);
        pl2.x = __float2half_rn(p0 - __half2float(ph2.x));
        pl2.y = __float2half_rn(p1 - __half2float(ph2.y));
        *(__half2*)(sm + A_oPh + q_s * APB + k * 2) = ph2;
        *(__half2*)(sm + A_oPl + q_s * APB + k * 2) = pl2;
      }
      part += __shfl_xor_sync(0xffffffff, part, 1);
      part += __shfl_xor_sync(0xffffffff, part, 2);
      if (kg == 0) {
        m_s[q_s] = newm;
        c_s[q_s] = c;
        l_s[q_s] = l_s[q_s] * c + part;
      }
    }
    __syncthreads();

    // ---- O = O*c + (Ph+Pl) Vh ----
#pragma unroll
    for (int mb = 0; mb < 2; mb++) {
      float cc0 = c_s[wm * 32 + mb * 16 + erow];
      float cc1 = c_s[wm * 32 + mb * 16 + erow + 8];
#pragma unroll
      for (int nb = 0; nb < 2; nb++) {
        oacc[mb][nb][0] *= cc0; oacc[mb][nb][1] *= cc0;
        oacc[mb][nb][2] *= cc1; oacc[mb][nb][3] *= cc1;
      }
    }
#pragma unroll
    for (int ks = 0; ks < 64; ks += 16) {
      uint32_t vbh[4];
      uint32_t voff = (uint32_t)((ks + lrow) * APB + (wn * 16 + lc8) * 2);
      LDSM_X4_T(vbh[0], vbh[1], vbh[2], vbh[3], sV + voff);
#pragma unroll
      for (int mb = 0; mb < 2; mb++) {
        uint32_t pa[4], pla[4];
        uint32_t poff = (uint32_t)((wm * 32 + mb * 16 + lrow) * APB + (ks + lc8) * 2);
        LDSM_X4(pa[0], pa[1], pa[2], pa[3], sb + A_oPh + poff);
        LDSM_X4(pla[0], pla[1], pla[2], pla[3], sb + A_oPl + poff);
#pragma unroll
        for (int nb = 0; nb < 2; nb++) {
          uint32_t b0 = vbh[nb * 2], b1 = vbh[nb * 2 + 1];
          MMA16816(oacc[mb][nb], pa[0], pa[1], pa[2], pa[3], b0, b1);
          MMA16816(oacc[mb][nb], pla[0], pla[1], pla[2], pla[3], b0, b1);
        }
      }
    }
  }
  __syncthreads();

  // ---- output: O / l -> fp16 hi/lo at [B,N,C] ----
  int b = bh >> 4, h = bh & 15;
#pragma unroll
  for (int mb = 0; mb < 2; mb++) {
    int q = wm * 32 + mb * 16 + erow;
    float il0 = 1.f / l_s[q];
    float il1 = 1.f / l_s[q + 8];
#pragma unroll
    for (int nb = 0; nb < 2; nb++) {
      int d = wn * 16 + nb * 8 + ecol;
      float v0 = oacc[mb][nb][0] * il0, v1 = oacc[mb][nb][1] * il0;
      float v2 = oacc[mb][nb][2] * il1, v3 = oacc[mb][nb][3] * il1;
      size_t off0 = ((size_t)(b * 2048 + qt * 64 + q)) * 1024 + h * 64 + d;
      size_t off8 = off0 + 8 * 1024;
      __half2 h01, h23, l01, l23;
      h01.x = __float2half_rn(v0); h01.y = __float2half_rn(v1);
      h23.x = __float2half_rn(v2); h23.y = __float2half_rn(v3);
      l01.x = __float2half_rn(v0 - __half2float(h01.x));
      l01.y = __float2half_rn(v1 - __half2float(h01.y));
      l23.x = __float2half_rn(v2 - __half2float(h23.x));
      l23.y = __float2half_rn(v3 - __half2float(h23.y));
      *(__half2*)(oh + off0) = h01;
      *(__half2*)(ol + off0) = l01;
      *(__half2*)(oh + off8) = h23;
      *(__half2*)(ol + off8) = l23;
    }
  }
}

// ================= launch =================
#define GEMM_SMEM (2 * STAGE_H)   // 61440 bytes

extern "C" void kernel_launch(void* const* d_in, const int* in_sizes, int n_in,
                              void* d_out, int out_size) {
  const float* x = (const float*)d_in[0];
  const float* ln1_g = (const float*)d_in[1];
  const float* ln1_b = (const float*)d_in[2];
  const float* qkv_w = (const float*)d_in[3];
  const float* qkv_b = (const float*)d_in[4];
  const float* proj_w = (const float*)d_in[5];
  const float* proj_b = (const float*)d_in[6];
  const float* ln2_g = (const float*)d_in[7];
  const float* ln2_b = (const float*)d_in[8];
  const float* fc1_w = (const float*)d_in[9];
  const float* fc1_b = (const float*)d_in[10];
  const float* ffln_g = (const float*)d_in[11];
  const float* ffln_b = (const float*)d_in[12];
  const float* fc2_w = (const float*)d_in[13];
  const float* fc2_b = (const float*)d_in[14];
  float* out = (float*)d_out;

  float *x1, *h1;
  __half *ah, *al, *atth, *attl;
  __half *qh, *ql, *kh, *vh;
  __half *wq, *wp, *w1, *w2;
  cudaGetSymbolAddress((void**)&x1, g_x1);
  cudaGetSymbolAddress((void**)&h1, g_h1);
  cudaGetSymbolAddress((void**)&ah, g_ah);
  cudaGetSymbolAddress((void**)&al, g_al);
  cudaGetSymbolAddress((void**)&atth, g_atth);
  cudaGetSymbolAddress((void**)&attl, g_attl);
  cudaGetSymbolAddress((void**)&qh, g_qh2);
  cudaGetSymbolAddress((void**)&ql, g_ql2);
  cudaGetSymbolAddress((void**)&kh, g_kh2);
  cudaGetSymbolAddress((void**)&vh, g_vh2);
  cudaGetSymbolAddress((void**)&wq, g_wq);
  cudaGetSymbolAddress((void**)&wp, g_wp);
  cudaGetSymbolAddress((void**)&w1, g_w1);
  cudaGetSymbolAddress((void**)&w2, g_w2);

  cudaFuncSetAttribute(gemm_mma<0>, cudaFuncAttributeMaxDynamicSharedMemorySize, GEMM_SMEM);
  cudaFuncSetAttribute(gemm_mma<1>, cudaFuncAttributeMaxDynamicSharedMemorySize, GEMM_SMEM);
  cudaFuncSetAttribute(gemm_mma<2>, cudaFuncAttributeMaxDynamicSharedMemorySize, GEMM_SMEM);
  cudaFuncSetAttribute(gemm_mma<3>, cudaFuncAttributeMaxDynamicSharedMemorySize, GEMM_SMEM);
  cudaFuncSetAttribute(attn_mma, cudaFuncAttributeMaxDynamicSharedMemorySize, ATTN_SMEM);

  wconv_kernel<<<dim3(3072 / 32, 1024 / 32), 256>>>(qkv_w, wq, 1024, 3072);
  wconv_kernel<<<dim3(1024 / 32, 1024 / 32), 256>>>(proj_w, wp, 1024, 1024);
  wconv_kernel<<<dim3(4096 / 32, 1024 / 32), 256>>>(fc1_w, w1, 1024, 4096);
  wconv_kernel<<<dim3(1024 / 32, 4096 / 32), 256>>>(fc2_w, w2, 4096, 1024);

  // 1) LN1 -> fp16 hi/lo
  ln_h_kernel<1><<<ROWS, 256>>>(x, ln1_g, ln1_b, ah, al);
  // 2) QKV GEMM + RoPE + split write (EPI 3)
  gemm_mma<3><<<dim3(3072 / 128, ROWS / 128), 256, GEMM_SMEM>>>(
      ah, al, wq, qkv_b, nullptr, nullptr, 1024, 3072, qh, ql, kh, vh);
  // 3) attention (fp16 2-term flash)
  attn_mma<<<dim3(NNq / 64, BB * HHn), 256, ATTN_SMEM>>>(
      qh, ql, kh, vh, atth, attl);
  // 4) proj + residual(x) -> x1
  gemm_mma<2><<<dim3(1024 / 128, ROWS / 128), 256, GEMM_SMEM>>>(
      atth, attl, wp, proj_b, x, x1, 1024, 1024,
      nullptr, nullptr, nullptr, nullptr);
  // 5) LN2 -> fp16 hi/lo
  ln_h_kernel<1><<<ROWS, 256>>>(x1, ln2_g, ln2_b, ah, al);
  // 6) fc1 + GELU -> fp32 h1
  gemm_mma<1><<<dim3(4096 / 128, ROWS / 128), 256, GEMM_SMEM>>>(
      ah, al, w1, fc1_b, nullptr, h1, 1024, 4096,
      nullptr, nullptr, nullptr, nullptr);
  // 7) ffn LN (4096 wide) -> fp16 hi/lo
  ln_h_kernel<4><<<ROWS, 256>>>(h1, ffln_g, ffln_b, ah, al);
  // 8) fc2 + residual(x1) -> out
  gemm_mma<2><<<dim3(1024 / 128, ROWS / 128), 256, GEMM_SMEM>>>(
      ah, al, w2, fc2_b, x1, out, 4096, 1024,
      nullptr, nullptr, nullptr, nullptr);
}

// round 7
// speedup vs baseline: 1.4706x; 1.0024x over previous
#include <cuda_runtime.h>
#include <cuda_fp16.h>
#include <math.h>
#include <stdint.h>

#define BB 2
#define NNq 2048
#define CCd 1024
#define HHn 16
#define HIDd 4096
#define ROWS (BB * NNq)   // 4096

// ================= scratch (device globals) =================
__device__ float g_x1[ROWS * CCd];
__device__ float g_h1[ROWS * HIDd];
__device__ __half g_ah[ROWS * HIDd];           // activation hi
__device__ __half g_al[ROWS * HIDd];           // activation lo
__device__ __half g_atth[ROWS * CCd];
__device__ __half g_attl[ROWS * CCd];
__device__ __half g_qh2[ROWS * CCd], g_ql2[ROWS * CCd];   // q hi/lo [B,H,N,D]
__device__ __half g_kh2[ROWS * CCd];                      // k hi only
__device__ __half g_vh2[ROWS * CCd];                      // v hi only
__device__ __half g_wq[3072 * 1024];
__device__ __half g_wp[1024 * 1024];
__device__ __half g_w1[4096 * 1024];
__device__ __half g_w2[1024 * 4096];

// ================= helpers =================
__device__ __forceinline__ uint32_t smem_u32(const void* p) {
  uint32_t a;
  asm("{ .reg .u64 t; cvta.to.shared.u64 t, %1; cvt.u32.u64 %0, t; }"
      : "=r"(a) : "l"(p));
  return a;
}

#define CP_ASYNC16(sm, gp) \
  asm volatile("cp.async.cg.shared.global [%0], [%1], 16;" \
               :: "r"(sm), "l"(gp) : "memory")
#define CP_COMMIT() asm volatile("cp.async.commit_group;" ::: "memory")
#define CP_WAIT0() asm volatile("cp.async.wait_group 0;" ::: "memory")
#define CP_WAIT1() asm volatile("cp.async.wait_group 1;" ::: "memory")
#define CP_WAIT2() asm volatile("cp.async.wait_group 2;" ::: "memory")

#define LDSM_X4(r0, r1, r2, r3, a) \
  asm volatile("ldmatrix.sync.aligned.m8n8.x4.shared.b16 {%0,%1,%2,%3}, [%4];" \
               : "=r"(r0), "=r"(r1), "=r"(r2), "=r"(r3) : "r"(a))
#define LDSM_X4_T(r0, r1, r2, r3, a) \
  asm volatile("ldmatrix.sync.aligned.m8n8.x4.trans.shared.b16 {%0,%1,%2,%3}, [%4];" \
               : "=r"(r0), "=r"(r1), "=r"(r2), "=r"(r3) : "r"(a))

#define MMA16816(d, a0, a1, a2, a3, b0, b1) \
  asm volatile("mma.sync.aligned.m16n8k16.row.col.f32.f16.f16.f32 " \
               "{%0,%1,%2,%3}, {%4,%5,%6,%7}, {%8,%9}, {%0,%1,%2,%3};" \
               : "+f"((d)[0]), "+f"((d)[1]), "+f"((d)[2]), "+f"((d)[3]) \
               : "r"(a0), "r"(a1), "r"(a2), "r"(a3), "r"(b0), "r"(b1))

__device__ __forceinline__ float gelu_f(float v) {
  return 0.5f * v * (1.f + erff(v * 0.70710678118654752f));
}

// ================= weight convert + transpose (fp32 [K,N] -> fp16 [N,K]) ===
__global__ __launch_bounds__(256) void wconv_kernel(
    const float* __restrict__ W, __half* __restrict__ th, int K, int N) {
  __shared__ float t[32][33];
  int n0 = blockIdx.x * 32, k0 = blockIdx.y * 32;
  int tx = threadIdx.x & 31, ty = threadIdx.x >> 5;
#pragma unroll
  for (int i = 0; i < 4; i++)
    t[ty + i * 8][tx] = W[(size_t)(k0 + ty + i * 8) * N + n0 + tx];
  __syncthreads();
#pragma unroll
  for (int i = 0; i < 4; i++) {
    float v = t[tx][ty + i * 8];
    th[(size_t)(n0 + ty + i * 8) * K + k0 + tx] = __float2half_rn(v);
  }
}

// ================= LayerNorm -> fp16 hi/lo =================
template <int NIT>
__global__ __launch_bounds__(256) void ln_h_kernel(
    const float* __restrict__ in, const float* __restrict__ gw,
    const float* __restrict__ bw, __half* __restrict__ oh,
    __half* __restrict__ ol) {
  const int cols = NIT * 1024;
  int row = blockIdx.x;
  const float* rp = in + (size_t)row * cols;
  float4 buf[NIT];
  float s = 0.f, sq = 0.f;
#pragma unroll
  for (int it = 0; it < NIT; it++) {
    int c = (it * 256 + threadIdx.x) * 4;
    float4 v = *(const float4*)(rp + c);
    buf[it] = v;
    s += v.x + v.y + v.z + v.w;
    sq += v.x * v.x + v.y * v.y + v.z * v.z + v.w * v.w;
  }
  __shared__ float red0[8], red1[8];
#pragma unroll
  for (int o = 16; o; o >>= 1) {
    s += __shfl_xor_sync(0xffffffff, s, o);
    sq += __shfl_xor_sync(0xffffffff, sq, o);
  }
  int warp = threadIdx.x >> 5, lane = threadIdx.x & 31;
  if (lane == 0) { red0[warp] = s; red1[warp] = sq; }
  __syncthreads();
  __shared__ float s_mu, s_ri;
  if (threadIdx.x == 0) {
    float ts = 0.f, tq = 0.f;
#pragma unroll
    for (int i = 0; i < 8; i++) { ts += red0[i]; tq += red1[i]; }
    float mu = ts / (float)cols;
    float var = tq / (float)cols - mu * mu;
    s_mu = mu;
    s_ri = rsqrtf(var + 1e-5f);
  }
  __syncthreads();
  float mu = s_mu, ri = s_ri;
#pragma unroll
  for (int it = 0; it < NIT; it++) {
    int c = (it * 256 + threadIdx.x) * 4;
    float4 v = buf[it];
    float4 g4 = *(const float4*)(gw + c);
    float4 b4 = *(const float4*)(bw + c);
    float o0 = (v.x - mu) * ri * g4.x + b4.x;
    float o1 = (v.y - mu) * ri * g4.y + b4.y;
    float o2 = (v.z - mu) * ri * g4.z + b4.z;
    float o3 = (v.w - mu) * ri * g4.w + b4.w;
    __half2 h01, h23, l01, l23;
    h01.x = __float2half_rn(o0); h01.y = __float2half_rn(o1);
    h23.x = __float2half_rn(o2); h23.y = __float2half_rn(o3);
    l01.x = __float2half_rn(o0 - __half2float(h01.x));
    l01.y = __float2half_rn(o1 - __half2float(h01.y));
    l23.x = __float2half_rn(o2 - __half2float(h23.x));
    l23.y = __float2half_rn(o3 - __half2float(h23.y));
    size_t o = (size_t)row * cols + c;
    *(__half2*)(oh + o) = h01;
    *(__half2*)(oh + o + 2) = h23;
    *(__half2*)(ol + o) = l01;
    *(__half2*)(ol + o + 2) = l23;
  }
}

// ================= mma.sync fp16 2-term GEMM (3-stage pipeline) =========
// C = (Ah+Al)[M,K] @ Bh^T + bias, Bh stored [N,K] (weights truncated fp16).
// Tile 128x128x32, 8 warps (2m x 4n), warp 64x32, 3-stage cp.async, 2 CTA/SM.
// EPI 0: bias; 1: +GELU; 2: +residual; 3: QKV (bias + RoPE + split write).
#define TILE_H 10240                // 128 rows * 40 pitch * 2B
#define STAGE_H (3 * TILE_H)        // Ah, Al, Bh

template <int EPI>
__global__ __launch_bounds__(256, 2) void gemm_mma(
    const __half* __restrict__ Ah, const __half* __restrict__ Al,
    const __half* __restrict__ Bh,
    const float* __restrict__ bias, const float* __restrict__ res,
    float* __restrict__ C, int K, int N,
    __half* qh_, __half* ql_, __half* kh_, __half* vh_) {
  extern __shared__ char smem[];
  uint32_t sb = smem_u32(smem);
  int tid = threadIdx.x, wid = tid >> 5, lane = tid & 31;
  int m0 = blockIdx.y * 128, n0 = blockIdx.x * 128;
  int wm = wid & 1, wn = wid >> 1;
  int lrow = lane & 15, lc8 = (lane >> 4) * 8;

  float acc[4][4][4];
#pragma unroll
  for (int i = 0; i < 4; i++)
#pragma unroll
    for (int j = 0; j < 4; j++)
#pragma unroll
      for (int t = 0; t < 4; t++) acc[i][j][t] = 0.f;

  int NCH = K >> 5;

#define GEMM_LOADS(stgbase, ktv)                                             \
  {                                                                          \
    uint32_t stg = (stgbase);                                                \
    int kt = (ktv);                                                          \
    _Pragma("unroll") for (int i = 0; i < 2; i++) {                          \
      int c = tid + i * 256;                                                 \
      int r = c >> 2, q = c & 3;                                             \
      uint32_t so = (uint32_t)(r * 80 + q * 16);                             \
      CP_ASYNC16(stg + so, Ah + (size_t)(m0 + r) * K + kt + q * 8);          \
      CP_ASYNC16(stg + TILE_H + so, Al + (size_t)(m0 + r) * K + kt + q * 8); \
      CP_ASYNC16(stg + 2 * TILE_H + so,                                      \
                 Bh + (size_t)(n0 + r) * K + kt + q * 8);                    \
    }                                                                        \
    CP_COMMIT();                                                             \
  }

  // prologue: 2 chunks in flight
  GEMM_LOADS(sb, 0);
  GEMM_LOADS(sb + STAGE_H, 32);

  for (int kc = 0; kc < NCH; kc++) {
    int cur = kc % 3;
    if (kc + 2 < NCH) {
      GEMM_LOADS(sb + ((kc + 2) % 3) * STAGE_H, (kc + 2) * 32);
      CP_WAIT2();
    } else if (kc + 1 < NCH) {
      CP_WAIT1();
    } else {
      CP_WAIT0();
    }
    __syncthreads();

    uint32_t stA = sb + cur * STAGE_H;
    uint32_t stAl = stA + TILE_H;
    uint32_t stB = stA + 2 * TILE_H;

#pragma unroll
    for (int ks = 0; ks < 32; ks += 16) {
      uint32_t bhf[8];
      uint32_t boff0 = (uint32_t)((wn * 32 + lrow) * 80 + (ks + lc8) * 2);
      uint32_t boff1 = (uint32_t)((wn * 32 + 16 + lrow) * 80 + (ks + lc8) * 2);
      LDSM_X4(bhf[0], bhf[1], bhf[2], bhf[3], stB + boff0);
      LDSM_X4(bhf[4], bhf[5], bhf[6], bhf[7], stB + boff1);
#pragma unroll
      for (int mb = 0; mb < 4; mb++) {
        uint32_t ah[4], al[4];
        uint32_t aoff = (uint32_t)((wm * 64 + mb * 16 + lrow) * 80 + (ks + lc8) * 2);
        LDSM_X4(ah[0], ah[1], ah[2], ah[3], stA + aoff);
        LDSM_X4(al[0], al[1], al[2], al[3], stAl + aoff);
#pragma unroll
        for (int nb = 0; nb < 4; nb++) {
          int pi = (nb >> 1) * 4, od = nb & 1;
          uint32_t b0 = bhf[pi + od], b1 = bhf[pi + 2 + od];
          MMA16816(acc[mb][nb], ah[0], ah[1], ah[2], ah[3], b0, b1);
          MMA16816(acc[mb][nb], al[0], al[1], al[2], al[3], b0, b1);
        }
      }
    }
    __syncthreads();
  }

  int erow = lane >> 2, ecol = (lane & 3) * 2;
#pragma unroll
  for (int mb = 0; mb < 4; mb++) {
#pragma unroll
    for (int nb = 0; nb < 4; nb++) {
      float* d = acc[mb][nb];
      int gr = m0 + wm * 64 + mb * 16 + erow;
      int gc = n0 + wn * 32 + nb * 8 + ecol;
      float2 b2 = *(const float2*)(bias + gc);
      float v0 = d[0] + b2.x, v1 = d[1] + b2.y;
      float v2 = d[2] + b2.x, v3 = d[3] + b2.y;
      if (EPI == 1) {
        v0 = gelu_f(v0); v1 = gelu_f(v1);
        v2 = gelu_f(v2); v3 = gelu_f(v3);
      } else if (EPI == 2) {
        float2 r0 = *(const float2*)(res + (size_t)gr * N + gc);
        float2 r1 = *(const float2*)(res + (size_t)(gr + 8) * N + gc);
        v0 += r0.x; v1 += r0.y; v2 += r1.x; v3 += r1.y;
      }
      if (EPI == 3) {
        int region = gc >> 10;           // 0 q, 1 k, 2 v
        int hh = (gc & 1023) >> 6;
        int dd = gc & 63;
        int b = gr >> 11;
        int n = gr & 2047;
        if (region < 2) {
          float inv = 1.0f / powf(10000.0f, (float)(dd & ~1) / 64.0f);
          float c0, s0, c1, s1;
          sincosf((float)n * inv, &s0, &c0);
          sincosf((float)(n + 8) * inv, &s1, &c1);
          float r0 = v0 * c0 - v1 * s0, r1 = v1 * c0 + v0 * s0;
          float r2 = v2 * c1 - v3 * s1, r3 = v3 * c1 + v2 * s1;
          v0 = r0; v1 = r1; v2 = r2; v3 = r3;
        }
        size_t o0 = ((size_t)((b * 16 + hh) * 2048 + n)) * 64 + dd;
        size_t o1 = o0 + 8 * 64;
        if (region == 0) {
          __half2 h01, h23, l01, l23;
          h01.x = __float2half_rn(v0); h01.y = __float2half_rn(v1);
          h23.x = __float2half_rn(v2); h23.y = __float2half_rn(v3);
          l01.x = __float2half_rn(v0 - __half2float(h01.x));
          l01.y = __float2half_rn(v1 - __half2float(h01.y));
          l23.x = __float2half_rn(v2 - __half2float(h23.x));
          l23.y = __float2half_rn(v3 - __half2float(h23.y));
          *(__half2*)(qh_ + o0) = h01;
          *(__half2*)(ql_ + o0) = l01;
          *(__half2*)(qh_ + o1) = h23;
          *(__half2*)(ql_ + o1) = l23;
        } else {
          __half* dst = (region == 1) ? kh_ : vh_;
          __half2 h01, h23;
          h01.x = __float2half_rn(v0); h01.y = __float2half_rn(v1);
          h23.x = __float2half_rn(v2); h23.y = __float2half_rn(v3);
          *(__half2*)(dst + o0) = h01;
          *(__half2*)(dst + o1) = h23;
        }
      } else {
        float2 o0 = {v0, v1}, o1 = {v2, v3};
        *(float2*)(C + (size_t)gr * N + gc) = o0;
        *(float2*)(C + (size_t)(gr + 8) * N + gc) = o1;
      }
    }
  }
}

// ================= mma.sync flash attention (fp16 2-term, 3-stage KV) =====
// 64-query tiles, 256 threads (2m x 4n warps), Q full (hi/lo), K/V truncated,
// P full (hi/lo). Triple-buffered K/V cp.async. 2 CTAs/SM.
#define APB 144   // bytes per smem row (72 fp16)
#define A_oQh 0
#define A_oQl 9216
#define A_oKV 18432          // 3 stages x (K 9216 + V 9216)
#define A_oPh 73728
#define A_oPl 82944
#define A_oSf 92160          // 64 x 68 fp32 = 17408
#define A_oSt 109568
#define ATTN_SMEM 110592

__global__ __launch_bounds__(256, 2) void attn_mma(
    const __half* __restrict__ qh, const __half* __restrict__ ql,
    const __half* __restrict__ kh, const __half* __restrict__ vh,
    __half* __restrict__ oh, __half* __restrict__ ol) {
  extern __shared__ char sm[];
  uint32_t sb = smem_u32(sm);
  float* Sf = (float*)(sm + A_oSf);
  float* m_s = (float*)(sm + A_oSt);
  float* l_s = m_s + 64;
  float* c_s = l_s + 64;

  int tid = threadIdx.x, wid = tid >> 5, lane = tid & 31;
  int wm = wid & 1, wn = wid >> 1;
  int lrow = lane & 15, lc8 = (lane >> 4) * 8;
  int erow = lane >> 2, ecol = (lane & 3) * 2;
  int bh = blockIdx.y, qt = blockIdx.x;
  size_t base = (size_t)bh * (2048 * 64);

  // Q tiles (hi/lo) — group 1
  {
    const __half* gqh = qh + base + (size_t)(qt * 64) * 64;
    const __half* gql = ql + base + (size_t)(qt * 64) * 64;
#pragma unroll
    for (int i = 0; i < 2; i++) {
      int f = tid + i * 256;
      int r = f >> 3, c8 = f & 7;
      uint32_t so = (uint32_t)(r * APB + c8 * 16);
      CP_ASYNC16(sb + A_oQh + so, gqh + r * 64 + c8 * 8);
      CP_ASYNC16(sb + A_oQl + so, gql + r * 64 + c8 * 8);
    }
    CP_COMMIT();
  }

#define ATTN_KV_LOADS(stg, ktv)                                              \
  {                                                                          \
    int kt_ = (ktv);                                                         \
    uint32_t d0 = sb + A_oKV + (stg) * 18432;                                \
    _Pragma("unroll") for (int i = 0; i < 2; i++) {                          \
      int f = tid + i * 256;                                                 \
      int r = f >> 3, c8 = f & 7;                                            \
      uint32_t so = (uint32_t)(r * APB + c8 * 16);                           \
      size_t go = base + (size_t)(kt_ * 64 + r) * 64 + c8 * 8;               \
      CP_ASYNC16(d0 + so, kh + go);                                          \
      CP_ASYNC16(d0 + 9216 + so, vh + go);                                   \
    }                                                                        \
    CP_COMMIT();                                                             \
  }

  ATTN_KV_LOADS(0, 0);
  ATTN_KV_LOADS(1, 1);

  if (tid < 64) { m_s[tid] = -INFINITY; l_s[tid] = 0.f; }

  float oacc[2][2][4];
#pragma unroll
  for (int a = 0; a < 2; a++)
#pragma unroll
    for (int b = 0; b < 2; b++)
#pragma unroll
      for (int t = 0; t < 4; t++) oacc[a][b][t] = 0.f;

  const float scale = 0.125f;
  int q_s = tid >> 2, kg = tid & 3;

  for (int kt = 0; kt < 32; kt++) {
    if (kt) __syncthreads();  // all warps done with the stage being refilled
    uint32_t sK = sb + A_oKV + (kt % 3) * 18432;
    uint32_t sV = sK + 9216;
    if (kt + 2 < 32) {
      ATTN_KV_LOADS((kt + 2) % 3, kt + 2);
      CP_WAIT2();
    } else if (kt + 1 < 32) {
      CP_WAIT1();
    } else {
      CP_WAIT0();
    }
    __syncthreads();

    // ---- S = scale * (Qh+Ql) Kh^T ----
    float sacc[2][2][4];
#pragma unroll
    for (int a = 0; a < 2; a++)
#pragma unroll
      for (int b = 0; b < 2; b++)
#pragma unroll
        for (int t = 0; t < 4; t++) sacc[a][b][t] = 0.f;
#pragma unroll
    for (int ks = 0; ks < 64; ks += 16) {
      uint32_t bhf[4];
      uint32_t boff = (uint32_t)((wn * 16 + lrow) * APB + (ks + lc8) * 2);
      LDSM_X4(bhf[0], bhf[1], bhf[2], bhf[3], sK + boff);
#pragma unroll
      for (int mb = 0; mb < 2; mb++) {
        uint32_t ahf[4], alf[4];
        uint32_t aoff = (uint32_t)((wm * 32 + mb * 16 + lrow) * APB + (ks + lc8) * 2);
        LDSM_X4(ahf[0], ahf[1], ahf[2], ahf[3], sb + A_oQh + aoff);
        LDSM_X4(alf[0], alf[1], alf[2], alf[3], sb + A_oQl + aoff);
#pragma unroll
        for (int nb = 0; nb < 2; nb++) {
          uint32_t b0 = bhf[nb], b1 = bhf[nb + 2];
          MMA16816(sacc[mb][nb], ahf[0], ahf[1], ahf[2], ahf[3], b0, b1);
          MMA16816(sacc[mb][nb], alf[0], alf[1], alf[2], alf[3], b0, b1);
        }
      }
    }
#pragma unroll
    for (int mb = 0; mb < 2; mb++)
#pragma unroll
      for (int nb = 0; nb < 2; nb++) {
        int q = wm * 32 + mb * 16 + erow;
        int k = wn * 16 + nb * 8 + ecol;
        float2 s01 = {sacc[mb][nb][0] * scale, sacc[mb][nb][1] * scale};
        float2 s23 = {sacc[mb][nb][2] * scale, sacc[mb][nb][3] * scale};
        *(float2*)(&Sf[q * 68 + k]) = s01;
        *(float2*)(&Sf[(q + 8) * 68 + k]) = s23;
      }
    __syncthreads();

    // ---- online softmax (4 threads per query row) ----
    {
      float rowmax = -INFINITY;
#pragma unroll
      for (int j = 0; j < 16; j++)
        rowmax = fmaxf(rowmax, Sf[q_s * 68 + kg * 16 + j]);
      rowmax = fmaxf(rowmax, __shfl_xor_sync(0xffffffff, rowmax, 1));
      rowmax = fmaxf(rowmax, __shfl_xor_sync(0xffffffff, rowmax, 2));
      float mold = m_s[q_s];
      float newm = fmaxf(mold, rowmax);
      float c = __expf(mold - newm);
      float part = 0.f;
#pragma unroll
      for (int j = 0; j < 16; j += 2) {
        int k = kg * 16 + j;
        float p0 = __expf(Sf[q_s * 68 + k] - newm);
        float p1 = __expf(Sf[q_s * 68 + k + 1] - newm);
        part += p0 + p1;
        __half2 ph2, pl2;
        ph2.x = __float2half_rn(p0); ph2.y = __float2half_rn(p1);
        pl2.x = __float2half_rn(p0 - __half2float(ph2.x));
        pl2.y = __float2half_rn(p1 - __half2float(ph2.y));
        *(__half2*)(sm + A_oPh + q_s * APB + k * 2) = ph2;
        *(__half2*)(sm + A_oPl + q_s * APB + k * 2) = pl2;
      }
      part += __shfl_xor_sync(0xffffffff, part, 1);
      part += __shfl_xor_sync(0xffffffff, part, 2);
      if (kg == 0) {
        m_s[q_s] = newm;
        c_s[q_s] = c;
        l_s[q_s] = l_s[q_s] * c + part;
      }
    }
    __syncthreads();

    // ---- O = O*c + (Ph+Pl) Vh ----
#pragma unroll
    for (int mb = 0; mb < 2; mb++) {
      float cc0 = c_s[wm * 32 + mb * 16 + erow];
      float cc1 = c_s[wm * 32 + mb * 16 + erow + 8];
#pragma unroll
      for (int nb = 0; nb < 2; nb++) {
        oacc[mb][nb][0] *= cc0; oacc[mb][nb][1] *= cc0;
        oacc[mb][nb][2] *= cc1; oacc[mb][nb][3] *= cc1;
      }
    }
#pragma unroll
    for (int ks = 0; ks < 64; ks += 16) {
      uint32_t vbh[4];
      uint32_t voff = (uint32_t)((ks + lrow) * APB + (wn * 16 + lc8) * 2);
      LDSM_X4_T(vbh[0], vbh[1], vbh[2], vbh[3], sV + voff);
#pragma unroll
      for (int mb = 0; mb < 2; mb++) {
        uint32_t pa[4], pla[4];
        uint32_t poff = (uint32_t)((wm * 32 + mb * 16 + lrow) * APB + (ks + lc8) * 2);
        LDSM_X4(pa[0], pa[1], pa[2], pa[3], sb + A_oPh + poff);
        LDSM_X4(pla[0], pla[1], pla[2], pla[3], sb + A_oPl + poff);
#pragma unroll
        for (int nb = 0; nb < 2; nb++) {
          uint32_t b0 = vbh[nb * 2], b1 = vbh[nb * 2 + 1];
          MMA16816(oacc[mb][nb], pa[0], pa[1], pa[2], pa[3], b0, b1);
          MMA16816(oacc[mb][nb], pla[0], pla[1], pla[2], pla[3], b0, b1);
        }
      }
    }
  }
  __syncthreads();

  // ---- output: O / l -> fp16 hi/lo at [B,N,C] ----
  int b = bh >> 4, h = bh & 15;
#pragma unroll
  for (int mb = 0; mb < 2; mb++) {
    int q = wm * 32 + mb * 16 + erow;
    float il0 = 1.f / l_s[q];
    float il1 = 1.f / l_s[q + 8];
#pragma unroll
    for (int nb = 0; nb < 2; nb++) {
      int d = wn * 16 + nb * 8 + ecol;
      float v0 = oacc[mb][nb][0] * il0, v1 = oacc[mb][nb][1] * il0;
      float v2 = oacc[mb][nb][2] * il1, v3 = oacc[mb][nb][3] * il1;
      size_t off0 = ((size_t)(b * 2048 + qt * 64 + q)) * 1024 + h * 64 + d;
      size_t off8 = off0 + 8 * 1024;
      __half2 h01, h23, l01, l23;
      h01.x = __float2half_rn(v0); h01.y = __float2half_rn(v1);
      h23.x = __float2half_rn(v2); h23.y = __float2half_rn(v3);
      l01.x = __float2half_rn(v0 - __half2float(h01.x));
      l01.y = __float2half_rn(v1 - __half2float(h01.y));
      l23.x = __float2half_rn(v2 - __half2float(h23.x));
      l23.y = __float2half_rn(v3 - __half2float(h23.y));
      *(__half2*)(oh + off0) = h01;
      *(__half2*)(ol + off0) = l01;
      *(__half2*)(oh + off8) = h23;
      *(__half2*)(ol + off8) = l23;
    }
  }
}

// ================= launch =================
#define GEMM_SMEM (3 * STAGE_H)   // 92160 bytes

extern "C" void kernel_launch(void* const* d_in, const int* in_sizes, int n_in,
                              void* d_out, int out_size) {
  const float* x = (const float*)d_in[0];
  const float* ln1_g = (const float*)d_in[1];
  const float* ln1_b = (const float*)d_in[2];
  const float* qkv_w = (const float*)d_in[3];
  const float* qkv_b = (const float*)d_in[4];
  const float* proj_w = (const float*)d_in[5];
  const float* proj_b = (const float*)d_in[6];
  const float* ln2_g = (const float*)d_in[7];
  const float* ln2_b = (const float*)d_in[8];
  const float* fc1_w = (const float*)d_in[9];
  const float* fc1_b = (const float*)d_in[10];
  const float* ffln_g = (const float*)d_in[11];
  const float* ffln_b = (const float*)d_in[12];
  const float* fc2_w = (const float*)d_in[13];
  const float* fc2_b = (const float*)d_in[14];
  float* out = (float*)d_out;

  float *x1, *h1;
  __half *ah, *al, *atth, *attl;
  __half *qh, *ql, *kh, *vh;
  __half *wq, *wp, *w1, *w2;
  cudaGetSymbolAddress((void**)&x1, g_x1);
  cudaGetSymbolAddress((void**)&h1, g_h1);
  cudaGetSymbolAddress((void**)&ah, g_ah);
  cudaGetSymbolAddress((void**)&al, g_al);
  cudaGetSymbolAddress((void**)&atth, g_atth);
  cudaGetSymbolAddress((void**)&attl, g_attl);
  cudaGetSymbolAddress((void**)&qh, g_qh2);
  cudaGetSymbolAddress((void**)&ql, g_ql2);
  cudaGetSymbolAddress((void**)&kh, g_kh2);
  cudaGetSymbolAddress((void**)&vh, g_vh2);
  cudaGetSymbolAddress((void**)&wq, g_wq);
  cudaGetSymbolAddress((void**)&wp, g_wp);
  cudaGetSymbolAddress((void**)&w1, g_w1);
  cudaGetSymbolAddress((void**)&w2, g_w2);

  cudaFuncSetAttribute(gemm_mma<0>, cudaFuncAttributeMaxDynamicSharedMemorySize, GEMM_SMEM);
  cudaFuncSetAttribute(gemm_mma<1>, cudaFuncAttributeMaxDynamicSharedMemorySize, GEMM_SMEM);
  cudaFuncSetAttribute(gemm_mma<2>, cudaFuncAttributeMaxDynamicSharedMemorySize, GEMM_SMEM);
  cudaFuncSetAttribute(gemm_mma<3>, cudaFuncAttributeMaxDynamicSharedMemorySize, GEMM_SMEM);
  cudaFuncSetAttribute(attn_mma, cudaFuncAttributeMaxDynamicSharedMemorySize, ATTN_SMEM);

  wconv_kernel<<<dim3(3072 / 32, 1024 / 32), 256>>>(qkv_w, wq, 1024, 3072);
  wconv_kernel<<<dim3(1024 / 32, 1024 / 32), 256>>>(proj_w, wp, 1024, 1024);
  wconv_kernel<<<dim3(4096 / 32, 1024 / 32), 256>>>(fc1_w, w1, 1024, 4096);
  wconv_kernel<<<dim3(1024 / 32, 4096 / 32), 256>>>(fc2_w, w2, 4096, 1024);

  // 1) LN1 -> fp16 hi/lo
  ln_h_kernel<1><<<ROWS, 256>>>(x, ln1_g, ln1_b, ah, al);
  // 2) QKV GEMM + RoPE + split write (EPI 3)
  gemm_mma<3><<<dim3(3072 / 128, ROWS / 128), 256, GEMM_SMEM>>>(
      ah, al, wq, qkv_b, nullptr, nullptr, 1024, 3072, qh, ql, kh, vh);
  // 3) attention (fp16 2-term flash)
  attn_mma<<<dim3(NNq / 64, BB * HHn), 256, ATTN_SMEM>>>(
      qh, ql, kh, vh, atth, attl);
  // 4) proj + residual(x) -> x1
  gemm_mma<2><<<dim3(1024 / 128, ROWS / 128), 256, GEMM_SMEM>>>(
      atth, attl, wp, proj_b, x, x1, 1024, 1024,
      nullptr, nullptr, nullptr, nullptr);
  // 5) LN2 -> fp16 hi/lo
  ln_h_kernel<1><<<ROWS, 256>>>(x1, ln2_g, ln2_b, ah, al);
  // 6) fc1 + GELU -> fp32 h1
  gemm_mma<1><<<dim3(4096 / 128, ROWS / 128), 256, GEMM_SMEM>>>(
      ah, al, w1, fc1_b, nullptr, h1, 1024, 4096,
      nullptr, nullptr, nullptr, nullptr);
  // 7) ffn LN (4096 wide) -> fp16 hi/lo
  ln_h_kernel<4><<<ROWS, 256>>>(h1, ffln_g, ffln_b, ah, al);
  // 8) fc2 + residual(x1) -> out
  gemm_mma<2><<<dim3(1024 / 128, ROWS / 128), 256, GEMM_SMEM>>>(
      ah, al, w2, fc2_b, x1, out, 4096, 1024,
      nullptr, nullptr, nullptr, nullptr);
}

// round 8
// speedup vs baseline: 2.2899x; 1.5571x over previous
#include <cuda_runtime.h>
#include <cuda_fp16.h>
#include <math.h>
#include <stdint.h>

#define BB 2
#define NNq 2048
#define CCd 1024
#define HHn 16
#define HIDd 4096
#define ROWS (BB * NNq)   // 4096

// ================= scratch (device globals) =================
__device__ float g_x1[ROWS * CCd];
__device__ float g_h1[ROWS * HIDd];
__device__ __half g_ah[ROWS * HIDd];           // activations (fp16)
__device__ __half g_att[ROWS * CCd];           // attention out
__device__ __half g_q2[ROWS * CCd];            // q [B,H,N,D] (RoPE applied)
__device__ __half g_k2[ROWS * CCd];            // k
__device__ __half g_v2[ROWS * CCd];            // v
__device__ __half g_wq[3072 * 1024];
__device__ __half g_wp[1024 * 1024];
__device__ __half g_w1[4096 * 1024];
__device__ __half g_w2[1024 * 4096];

// ================= helpers =================
__device__ __forceinline__ uint32_t smem_u32(const void* p) {
  uint32_t a;
  asm("{ .reg .u64 t; cvta.to.shared.u64 t, %1; cvt.u32.u64 %0, t; }"
      : "=r"(a) : "l"(p));
  return a;
}

#define CP_ASYNC16(sm, gp) \
  asm volatile("cp.async.cg.shared.global [%0], [%1], 16;" \
               :: "r"(sm), "l"(gp) : "memory")
#define CP_COMMIT() asm volatile("cp.async.commit_group;" ::: "memory")
#define CP_WAIT0() asm volatile("cp.async.wait_group 0;" ::: "memory")
#define CP_WAIT1() asm volatile("cp.async.wait_group 1;" ::: "memory")

#define LDSM_X4(r0, r1, r2, r3, a) \
  asm volatile("ldmatrix.sync.aligned.m8n8.x4.shared.b16 {%0,%1,%2,%3}, [%4];" \
               : "=r"(r0), "=r"(r1), "=r"(r2), "=r"(r3) : "r"(a))
#define LDSM_X4_T(r0, r1, r2, r3, a) \
  asm volatile("ldmatrix.sync.aligned.m8n8.x4.trans.shared.b16 {%0,%1,%2,%3}, [%4];" \
               : "=r"(r0), "=r"(r1), "=r"(r2), "=r"(r3) : "r"(a))

#define MMA16816(d, a0, a1, a2, a3, b0, b1) \
  asm volatile("mma.sync.aligned.m16n8k16.row.col.f32.f16.f16.f32 " \
               "{%0,%1,%2,%3}, {%4,%5,%6,%7}, {%8,%9}, {%0,%1,%2,%3};" \
               : "+f"((d)[0]), "+f"((d)[1]), "+f"((d)[2]), "+f"((d)[3]) \
               : "r"(a0), "r"(a1), "r"(a2), "r"(a3), "r"(b0), "r"(b1))

__device__ __forceinline__ float gelu_f(float v) {
  return 0.5f * v * (1.f + erff(v * 0.70710678118654752f));
}

// ================= weight convert + transpose (fp32 [K,N] -> fp16 [N,K]) ===
__global__ __launch_bounds__(256) void wconv_kernel(
    const float* __restrict__ W, __half* __restrict__ th, int K, int N) {
  __shared__ float t[32][33];
  int n0 = blockIdx.x * 32, k0 = blockIdx.y * 32;
  int tx = threadIdx.x & 31, ty = threadIdx.x >> 5;
#pragma unroll
  for (int i = 0; i < 4; i++)
    t[ty + i * 8][tx] = W[(size_t)(k0 + ty + i * 8) * N + n0 + tx];
  __syncthreads();
#pragma unroll
  for (int i = 0; i < 4; i++) {
    float v = t[tx][ty + i * 8];
    th[(size_t)(n0 + ty + i * 8) * K + k0 + tx] = __float2half_rn(v);
  }
}

// ================= LayerNorm -> fp16 =================
template <int NIT>
__global__ __launch_bounds__(256) void ln_h_kernel(
    const float* __restrict__ in, const float* __restrict__ gw,
    const float* __restrict__ bw, __half* __restrict__ oh) {
  const int cols = NIT * 1024;
  int row = blockIdx.x;
  const float* rp = in + (size_t)row * cols;
  float4 buf[NIT];
  float s = 0.f, sq = 0.f;
#pragma unroll
  for (int it = 0; it < NIT; it++) {
    int c = (it * 256 + threadIdx.x) * 4;
    float4 v = *(const float4*)(rp + c);
    buf[it] = v;
    s += v.x + v.y + v.z + v.w;
    sq += v.x * v.x + v.y * v.y + v.z * v.z + v.w * v.w;
  }
  __shared__ float red0[8], red1[8];
#pragma unroll
  for (int o = 16; o; o >>= 1) {
    s += __shfl_xor_sync(0xffffffff, s, o);
    sq += __shfl_xor_sync(0xffffffff, sq, o);
  }
  int warp = threadIdx.x >> 5, lane = threadIdx.x & 31;
  if (lane == 0) { red0[warp] = s; red1[warp] = sq; }
  __syncthreads();
  __shared__ float s_mu, s_ri;
  if (threadIdx.x == 0) {
    float ts = 0.f, tq = 0.f;
#pragma unroll
    for (int i = 0; i < 8; i++) { ts += red0[i]; tq += red1[i]; }
    float mu = ts / (float)cols;
    float var = tq / (float)cols - mu * mu;
    s_mu = mu;
    s_ri = rsqrtf(var + 1e-5f);
  }
  __syncthreads();
  float mu = s_mu, ri = s_ri;
#pragma unroll
  for (int it = 0; it < NIT; it++) {
    int c = (it * 256 + threadIdx.x) * 4;
    float4 v = buf[it];
    float4 g4 = *(const float4*)(gw + c);
    float4 b4 = *(const float4*)(bw + c);
    __half2 h01, h23;
    h01.x = __float2half_rn((v.x - mu) * ri * g4.x + b4.x);
    h01.y = __float2half_rn((v.y - mu) * ri * g4.y + b4.y);
    h23.x = __float2half_rn((v.z - mu) * ri * g4.z + b4.z);
    h23.y = __float2half_rn((v.w - mu) * ri * g4.w + b4.w);
    size_t o = (size_t)row * cols + c;
    *(__half2*)(oh + o) = h01;
    *(__half2*)(oh + o + 2) = h23;
  }
}

// ================= mma.sync fp16 single-term GEMM (3-stage, 1 sync/iter) ==
// C = A[M,K] @ B^T + bias, B stored [N,K]. Tile 128x128x32, 8 warps (2m x 4n),
// warp 64x32, 3-stage cp.async ring, 2 CTAs/SM.
// EPI 0: bias; 1: +GELU; 2: +residual; 3: QKV (bias + RoPE + split write).
#define TILE_H 10240                // 128 rows * 40 pitch * 2B
#define STAGE_H (2 * TILE_H)        // A, B

template <int EPI>
__global__ __launch_bounds__(256, 2) void gemm_mma(
    const __half* __restrict__ Ah, const __half* __restrict__ Bh,
    const float* __restrict__ bias, const float* __restrict__ res,
    float* __restrict__ C, int K, int N,
    __half* q_, __half* k_, __half* v_) {
  extern __shared__ char smem[];
  uint32_t sb = smem_u32(smem);
  int tid = threadIdx.x, wid = tid >> 5, lane = tid & 31;
  int m0 = blockIdx.y * 128, n0 = blockIdx.x * 128;
  int wm = wid & 1, wn = wid >> 1;
  int lrow = lane & 15, lc8 = (lane >> 4) * 8;

  float acc[4][4][4];
#pragma unroll
  for (int i = 0; i < 4; i++)
#pragma unroll
    for (int j = 0; j < 4; j++)
#pragma unroll
      for (int t = 0; t < 4; t++) acc[i][j][t] = 0.f;

  int NCH = K >> 5;

#define GEMM_LOADS(stgbase, ktv)                                             \
  {                                                                          \
    uint32_t stg = (stgbase);                                                \
    int kt = (ktv);                                                          \
    _Pragma("unroll") for (int i = 0; i < 2; i++) {                          \
      int c = tid + i * 256;                                                 \
      int r = c >> 2, q = c & 3;                                             \
      uint32_t so = (uint32_t)(r * 80 + q * 16);                             \
      CP_ASYNC16(stg + so, Ah + (size_t)(m0 + r) * K + kt + q * 8);          \
      CP_ASYNC16(stg + TILE_H + so, Bh + (size_t)(n0 + r) * K + kt + q * 8); \
    }                                                                        \
    CP_COMMIT();                                                             \
  }

  // prologue: 2 chunks in flight
  GEMM_LOADS(sb, 0);
  GEMM_LOADS(sb + STAGE_H, 32);

  for (int kc = 0; kc < NCH; kc++) {
    if (kc + 1 < NCH) { CP_WAIT1(); } else { CP_WAIT0(); }
    __syncthreads();   // stage kc%3 visible to all; all warps done with stage (kc-1)%3
    if (kc + 2 < NCH) GEMM_LOADS(sb + ((kc + 2) % 3) * STAGE_H, (kc + 2) * 32);

    uint32_t stA = sb + (kc % 3) * STAGE_H;
    uint32_t stB = stA + TILE_H;

#pragma unroll
    for (int ks = 0; ks < 32; ks += 16) {
      uint32_t bhf[8];
      uint32_t boff0 = (uint32_t)((wn * 32 + lrow) * 80 + (ks + lc8) * 2);
      uint32_t boff1 = (uint32_t)((wn * 32 + 16 + lrow) * 80 + (ks + lc8) * 2);
      LDSM_X4(bhf[0], bhf[1], bhf[2], bhf[3], stB + boff0);
      LDSM_X4(bhf[4], bhf[5], bhf[6], bhf[7], stB + boff1);
#pragma unroll
      for (int mb = 0; mb < 4; mb++) {
        uint32_t ah[4];
        uint32_t aoff = (uint32_t)((wm * 64 + mb * 16 + lrow) * 80 + (ks + lc8) * 2);
        LDSM_X4(ah[0], ah[1], ah[2], ah[3], stA + aoff);
#pragma unroll
        for (int nb = 0; nb < 4; nb++) {
          int pi = (nb >> 1) * 4, od = nb & 1;
          MMA16816(acc[mb][nb], ah[0], ah[1], ah[2], ah[3],
                   bhf[pi + od], bhf[pi + 2 + od]);
        }
      }
    }
  }

  int erow = lane >> 2, ecol = (lane & 3) * 2;
#pragma unroll
  for (int mb = 0; mb < 4; mb++) {
#pragma unroll
    for (int nb = 0; nb < 4; nb++) {
      float* d = acc[mb][nb];
      int gr = m0 + wm * 64 + mb * 16 + erow;
      int gc = n0 + wn * 32 + nb * 8 + ecol;
      float2 b2 = *(const float2*)(bias + gc);
      float v0 = d[0] + b2.x, v1 = d[1] + b2.y;
      float v2 = d[2] + b2.x, v3 = d[3] + b2.y;
      if (EPI == 1) {
        v0 = gelu_f(v0); v1 = gelu_f(v1);
        v2 = gelu_f(v2); v3 = gelu_f(v3);
      } else if (EPI == 2) {
        float2 r0 = *(const float2*)(res + (size_t)gr * N + gc);
        float2 r1 = *(const float2*)(res + (size_t)(gr + 8) * N + gc);
        v0 += r0.x; v1 += r0.y; v2 += r1.x; v3 += r1.y;
      }
      if (EPI == 3) {
        int region = gc >> 10;           // 0 q, 1 k, 2 v
        int hh = (gc & 1023) >> 6;
        int dd = gc & 63;
        int b = gr >> 11;
        int n = gr & 2047;
        if (region < 2) {
          float inv = 1.0f / powf(10000.0f, (float)(dd & ~1) / 64.0f);
          float c0, s0, c1, s1;
          sincosf((float)n * inv, &s0, &c0);
          sincosf((float)(n + 8) * inv, &s1, &c1);
          float r0 = v0 * c0 - v1 * s0, r1 = v1 * c0 + v0 * s0;
          float r2 = v2 * c1 - v3 * s1, r3 = v3 * c1 + v2 * s1;
          v0 = r0; v1 = r1; v2 = r2; v3 = r3;
        }
        __half* dst = (region == 0) ? q_ : (region == 1) ? k_ : v_;
        size_t o0 = ((size_t)((b * 16 + hh) * 2048 + n)) * 64 + dd;
        size_t o1 = o0 + 8 * 64;
        __half2 h01, h23;
        h01.x = __float2half_rn(v0); h01.y = __float2half_rn(v1);
        h23.x = __float2half_rn(v2); h23.y = __float2half_rn(v3);
        *(__half2*)(dst + o0) = h01;
        *(__half2*)(dst + o1) = h23;
      } else {
        float2 o0 = {v0, v1}, o1 = {v2, v3};
        *(float2*)(C + (size_t)gr * N + gc) = o0;
        *(float2*)(C + (size_t)(gr + 8) * N + gc) = o1;
      }
    }
  }
}

// ================= mma.sync flash attention (fp16 1-term, 3-stage KV) =====
// 64-query tiles, 256 threads (2m x 4n warps). 2 CTAs/SM.
#define APB 144   // bytes per smem row (72 fp16)
#define A_oQ 0
#define A_oKV 9216           // 3 stages x (K 9216 + V 9216) = 55296
#define A_oP 64512
#define A_oSf 73728          // 64 x 68 fp32 = 17408
#define A_oSt 91136          // m/l/c: 3*64*4 = 768
#define ATTN_SMEM 92160

__global__ __launch_bounds__(256, 2) void attn_mma(
    const __half* __restrict__ qg, const __half* __restrict__ kg_,
    const __half* __restrict__ vg, __half* __restrict__ og) {
  extern __shared__ char sm[];
  uint32_t sb = smem_u32(sm);
  float* Sf = (float*)(sm + A_oSf);
  float* m_s = (float*)(sm + A_oSt);
  float* l_s = m_s + 64;
  float* c_s = l_s + 64;

  int tid = threadIdx.x, wid = tid >> 5, lane = tid & 31;
  int wm = wid & 1, wn = wid >> 1;
  int lrow = lane & 15, lc8 = (lane >> 4) * 8;
  int erow = lane >> 2, ecol = (lane & 3) * 2;
  int bh = blockIdx.y, qt = blockIdx.x;
  size_t base = (size_t)bh * (2048 * 64);

  // Q tile — first commit group
  {
    const __half* gq = qg + base + (size_t)(qt * 64) * 64;
#pragma unroll
    for (int i = 0; i < 2; i++) {
      int f = tid + i * 256;
      int r = f >> 3, c8 = f & 7;
      CP_ASYNC16(sb + A_oQ + (uint32_t)(r * APB + c8 * 16), gq + r * 64 + c8 * 8);
    }
    CP_COMMIT();
  }

#define ATTN_KV_LOADS(stg, ktv)                                              \
  {                                                                          \
    int kt_ = (ktv);                                                         \
    uint32_t d0 = sb + A_oKV + (stg) * 18432;                                \
    _Pragma("unroll") for (int i = 0; i < 2; i++) {                          \
      int f = tid + i * 256;                                                 \
      int r = f >> 3, c8 = f & 7;                                            \
      uint32_t so = (uint32_t)(r * APB + c8 * 16);                           \
      size_t go = base + (size_t)(kt_ * 64 + r) * 64 + c8 * 8;               \
      CP_ASYNC16(d0 + so, kg_ + go);                                         \
      CP_ASYNC16(d0 + 9216 + so, vg + go);                                   \
    }                                                                        \
    CP_COMMIT();                                                             \
  }

  ATTN_KV_LOADS(0, 0);
  ATTN_KV_LOADS(1, 1);

  if (tid < 64) { m_s[tid] = -INFINITY; l_s[tid] = 0.f; }

  float oacc[2][2][4];
#pragma unroll
  for (int a = 0; a < 2; a++)
#pragma unroll
    for (int b = 0; b < 2; b++)
#pragma unroll
      for (int t = 0; t < 4; t++) oacc[a][b][t] = 0.f;

  const float scale = 0.125f;
  int q_s = tid >> 2, kg = tid & 3;

  for (int kt = 0; kt < 32; kt++) {
    if (kt + 1 < 32) { CP_WAIT1(); } else { CP_WAIT0(); }
    __syncthreads();  // KV stage kt%3 (and Q at kt=0) visible; prior PV done
    if (kt + 2 < 32) ATTN_KV_LOADS((kt + 2) % 3, kt + 2);

    uint32_t sK = sb + A_oKV + (kt % 3) * 18432;
    uint32_t sV = sK + 9216;

    // ---- S = scale * Q K^T ----
    float sacc[2][2][4];
#pragma unroll
    for (int a = 0; a < 2; a++)
#pragma unroll
      for (int b = 0; b < 2; b++)
#pragma unroll
        for (int t = 0; t < 4; t++) sacc[a][b][t] = 0.f;
#pragma unroll
    for (int ks = 0; ks < 64; ks += 16) {
      uint32_t bhf[4];
      uint32_t boff = (uint32_t)((wn * 16 + lrow) * APB + (ks + lc8) * 2);
      LDSM_X4(bhf[0], bhf[1], bhf[2], bhf[3], sK + boff);
#pragma unroll
      for (int mb = 0; mb < 2; mb++) {
        uint32_t ahf[4];
        uint32_t aoff = (uint32_t)((wm * 32 + mb * 16 + lrow) * APB + (ks + lc8) * 2);
        LDSM_X4(ahf[0], ahf[1], ahf[2], ahf[3], sb + A_oQ + aoff);
#pragma unroll
        for (int nb = 0; nb < 2; nb++)
          MMA16816(sacc[mb][nb], ahf[0], ahf[1], ahf[2], ahf[3],
                   bhf[nb], bhf[nb + 2]);
      }
    }
#pragma unroll
    for (int mb = 0; mb < 2; mb++)
#pragma unroll
      for (int nb = 0; nb < 2; nb++) {
        int q = wm * 32 + mb * 16 + erow;
        int k = wn * 16 + nb * 8 + ecol;
        float2 s01 = {sacc[mb][nb][0] * scale, sacc[mb][nb][1] * scale};
        float2 s23 = {sacc[mb][nb][2] * scale, sacc[mb][nb][3] * scale};
        *(float2*)(&Sf[q * 68 + k]) = s01;
        *(float2*)(&Sf[(q + 8) * 68 + k]) = s23;
      }
    __syncthreads();

    // ---- online softmax (4 threads per query row) ----
    {
      float rowmax = -INFINITY;
#pragma unroll
      for (int j = 0; j < 16; j++)
        rowmax = fmaxf(rowmax, Sf[q_s * 68 + kg * 16 + j]);
      rowmax = fmaxf(rowmax, __shfl_xor_sync(0xffffffff, rowmax, 1));
      rowmax = fmaxf(rowmax, __shfl_xor_sync(0xffffffff, rowmax, 2));
      float mold = m_s[q_s];
      float newm = fmaxf(mold, rowmax);
      float c = __expf(mold - newm);
      float part = 0.f;
#pragma unroll
      for (int j = 0; j < 16; j += 2) {
        int k = kg * 16 + j;
        float p0 = __expf(Sf[q_s * 68 + k] - newm);
        float p1 = __expf(Sf[q_s * 68 + k + 1] - newm);
        part += p0 + p1;
        __half2 ph2;
        ph2.x = __float2half_rn(p0);
        ph2.y = __float2half_rn(p1);
        *(__half2*)(sm + A_oP + q_s * APB + k * 2) = ph2;
      }
      part += __shfl_xor_sync(0xffffffff, part, 1);
      part += __shfl_xor_sync(0xffffffff, part, 2);
      if (kg == 0) {
        m_s[q_s] = newm;
        c_s[q_s] = c;
        l_s[q_s] = l_s[q_s] * c + part;
      }
    }
    __syncthreads();

    // ---- O = O*c + P V ----
#pragma unroll
    for (int mb = 0; mb < 2; mb++) {
      float cc0 = c_s[wm * 32 + mb * 16 + erow];
      float cc1 = c_s[wm * 32 + mb * 16 + erow + 8];
#pragma unroll
      for (int nb = 0; nb < 2; nb++) {
        oacc[mb][nb][0] *= cc0; oacc[mb][nb][1] *= cc0;
        oacc[mb][nb][2] *= cc1; oacc[mb][nb][3] *= cc1;
      }
    }
#pragma unroll
    for (int ks = 0; ks < 64; ks += 16) {
      uint32_t vbh[4];
      uint32_t voff = (uint32_t)((ks + lrow) * APB + (wn * 16 + lc8) * 2);
      LDSM_X4_T(vbh[0], vbh[1], vbh[2], vbh[3], sV + voff);
#pragma unroll
      for (int mb = 0; mb < 2; mb++) {
        uint32_t pa[4];
        uint32_t poff = (uint32_t)((wm * 32 + mb * 16 + lrow) * APB + (ks + lc8) * 2);
        LDSM_X4(pa[0], pa[1], pa[2], pa[3], sb + A_oP + poff);
#pragma unroll
        for (int nb = 0; nb < 2; nb++)
          MMA16816(oacc[mb][nb], pa[0], pa[1], pa[2], pa[3],
                   vbh[nb * 2], vbh[nb * 2 + 1]);
      }
    }
  }
  __syncthreads();

  // ---- output: O / l -> fp16 at [B,N,C] ----
  int b = bh >> 4, h = bh & 15;
#pragma unroll
  for (int mb = 0; mb < 2; mb++) {
    int q = wm * 32 + mb * 16 + erow;
    float il0 = 1.f / l_s[q];
    float il1 = 1.f / l_s[q + 8];
#pragma unroll
    for (int nb = 0; nb < 2; nb++) {
      int d = wn * 16 + nb * 8 + ecol;
      float v0 = oacc[mb][nb][0] * il0, v1 = oacc[mb][nb][1] * il0;
      float v2 = oacc[mb][nb][2] * il1, v3 = oacc[mb][nb][3] * il1;
      size_t off0 = ((size_t)(b * 2048 + qt * 64 + q)) * 1024 + h * 64 + d;
      size_t off8 = off0 + 8 * 1024;
      __half2 h01, h23;
      h01.x = __float2half_rn(v0); h01.y = __float2half_rn(v1);
      h23.x = __float2half_rn(v2); h23.y = __float2half_rn(v3);
      *(__half2*)(og + off0) = h01;
      *(__half2*)(og + off8) = h23;
    }
  }
}

// ================= launch =================
#define GEMM_SMEM (3 * STAGE_H)   // 61440 bytes

extern "C" void kernel_launch(void* const* d_in, const int* in_sizes, int n_in,
                              void* d_out, int out_size) {
  const float* x = (const float*)d_in[0];
  const float* ln1_g = (const float*)d_in[1];
  const float* ln1_b = (const float*)d_in[2];
  const float* qkv_w = (const float*)d_in[3];
  const float* qkv_b = (const float*)d_in[4];
  const float* proj_w = (const float*)d_in[5];
  const float* proj_b = (const float*)d_in[6];
  const float* ln2_g = (const float*)d_in[7];
  const float* ln2_b = (const float*)d_in[8];
  const float* fc1_w = (const float*)d_in[9];
  const float* fc1_b = (const float*)d_in[10];
  const float* ffln_g = (const float*)d_in[11];
  const float* ffln_b = (const float*)d_in[12];
  const float* fc2_w = (const float*)d_in[13];
  const float* fc2_b = (const float*)d_in[14];
  float* out = (float*)d_out;

  float *x1, *h1;
  __half *ah, *att, *q, *k, *v;
  __half *wq, *wp, *w1, *w2;
  cudaGetSymbolAddress((void**)&x1, g_x1);
  cudaGetSymbolAddress((void**)&h1, g_h1);
  cudaGetSymbolAddress((void**)&ah, g_ah);
  cudaGetSymbolAddress((void**)&att, g_att);
  cudaGetSymbolAddress((void**)&q, g_q2);
  cudaGetSymbolAddress((void**)&k, g_k2);
  cudaGetSymbolAddress((void**)&v, g_v2);
  cudaGetSymbolAddress((void**)&wq, g_wq);
  cudaGetSymbolAddress((void**)&wp, g_wp);
  cudaGetSymbolAddress((void**)&w1, g_w1);
  cudaGetSymbolAddress((void**)&w2, g_w2);

  cudaFuncSetAttribute(gemm_mma<0>, cudaFuncAttributeMaxDynamicSharedMemorySize, GEMM_SMEM);
  cudaFuncSetAttribute(gemm_mma<1>, cudaFuncAttributeMaxDynamicSharedMemorySize, GEMM_SMEM);
  cudaFuncSetAttribute(gemm_mma<2>, cudaFuncAttributeMaxDynamicSharedMemorySize, GEMM_SMEM);
  cudaFuncSetAttribute(gemm_mma<3>, cudaFuncAttributeMaxDynamicSharedMemorySize, GEMM_SMEM);
  cudaFuncSetAttribute(attn_mma, cudaFuncAttributeMaxDynamicSharedMemorySize, ATTN_SMEM);

  wconv_kernel<<<dim3(3072 / 32, 1024 / 32), 256>>>(qkv_w, wq, 1024, 3072);
  wconv_kernel<<<dim3(1024 / 32, 1024 / 32), 256>>>(proj_w, wp, 1024, 1024);
  wconv_kernel<<<dim3(4096 / 32, 1024 / 32), 256>>>(fc1_w, w1, 1024, 4096);
  wconv_kernel<<<dim3(1024 / 32, 4096 / 32), 256>>>(fc2_w, w2, 4096, 1024);

  // 1) LN1 -> fp16
  ln_h_kernel<1><<<ROWS, 256>>>(x, ln1_g, ln1_b, ah);
  // 2) QKV GEMM + RoPE + split write (EPI 3)
  gemm_mma<3><<<dim3(3072 / 128, ROWS / 128), 256, GEMM_SMEM>>>(
      ah, wq, qkv_b, nullptr, nullptr, 1024, 3072, q, k, v);
  // 3) attention (fp16 flash)
  attn_mma<<<dim3(NNq / 64, BB * HHn), 256, ATTN_SMEM>>>(q, k, v, att);
  // 4) proj + residual(x) -> x1
  gemm_mma<2><<<dim3(1024 / 128, ROWS / 128), 256, GEMM_SMEM>>>(
      att, wp, proj_b, x, x1, 1024, 1024, nullptr, nullptr, nullptr);
  // 5) LN2 -> fp16
  ln_h_kernel<1><<<ROWS, 256>>>(x1, ln2_g, ln2_b, ah);
  // 6) fc1 + GELU -> fp32 h1
  gemm_mma<1><<<dim3(4096 / 128, ROWS / 128), 256, GEMM_SMEM>>>(
      ah, w1, fc1_b, nullptr, h1, 1024, 4096, nullptr, nullptr, nullptr);
  // 7) ffn LN (4096 wide) -> fp16
  ln_h_kernel<4><<<ROWS, 256>>>(h1, ffln_g, ffln_b, ah);
  // 8) fc2 + residual(x1) -> out
  gemm_mma<2><<<dim3(1024 / 128, ROWS / 128), 256, GEMM_SMEM>>>(
      ah, w2, fc2_b, x1, out, 4096, 1024, nullptr, nullptr, nullptr);
}

// round 9
// speedup vs baseline: 2.7265x; 1.1907x over previous
#include <cuda_runtime.h>
#include <cuda_fp16.h>
#include <math.h>
#include <stdint.h>

#define BB 2
#define NNq 2048
#define CCd 1024
#define HHn 16
#define HIDd 4096
#define ROWS (BB * NNq)   // 4096

// ================= scratch (device globals) =================
__device__ float g_x1[ROWS * CCd];
__device__ __half g_h1h[ROWS * HIDd];          // fc1+gelu out (fp16)
__device__ __half g_ah[ROWS * HIDd];           // activations (fp16)
__device__ __half g_att[ROWS * CCd];           // attention out
__device__ __half g_q2[ROWS * CCd];            // q [B,H,N,D] (RoPE+scale)
__device__ __half g_k2[ROWS * CCd];            // k
__device__ __half g_v2[ROWS * CCd];            // v
__device__ __half g_wq[3072 * 1024];
__device__ __half g_wp[1024 * 1024];
__device__ __half g_w1[4096 * 1024];
__device__ __half g_w2[1024 * 4096];

// ================= helpers =================
__device__ __forceinline__ uint32_t smem_u32(const void* p) {
  uint32_t a;
  asm("{ .reg .u64 t; cvta.to.shared.u64 t, %1; cvt.u32.u64 %0, t; }"
      : "=r"(a) : "l"(p));
  return a;
}

#define CP_ASYNC16(sm, gp) \
  asm volatile("cp.async.cg.shared.global [%0], [%1], 16;" \
               :: "r"(sm), "l"(gp) : "memory")
#define CP_COMMIT() asm volatile("cp.async.commit_group;" ::: "memory")
#define CP_WAIT0() asm volatile("cp.async.wait_group 0;" ::: "memory")
#define CP_WAIT1() asm volatile("cp.async.wait_group 1;" ::: "memory")

#define LDSM_X4(r0, r1, r2, r3, a) \
  asm volatile("ldmatrix.sync.aligned.m8n8.x4.shared.b16 {%0,%1,%2,%3}, [%4];" \
               : "=r"(r0), "=r"(r1), "=r"(r2), "=r"(r3) : "r"(a))
#define LDSM_X4_T(r0, r1, r2, r3, a) \
  asm volatile("ldmatrix.sync.aligned.m8n8.x4.trans.shared.b16 {%0,%1,%2,%3}, [%4];" \
               : "=r"(r0), "=r"(r1), "=r"(r2), "=r"(r3) : "r"(a))

#define MMA16816(d, a0, a1, a2, a3, b0, b1) \
  asm volatile("mma.sync.aligned.m16n8k16.row.col.f32.f16.f16.f32 " \
               "{%0,%1,%2,%3}, {%4,%5,%6,%7}, {%8,%9}, {%0,%1,%2,%3};" \
               : "+f"((d)[0]), "+f"((d)[1]), "+f"((d)[2]), "+f"((d)[3]) \
               : "r"(a0), "r"(a1), "r"(a2), "r"(a3), "r"(b0), "r"(b1))

__device__ __forceinline__ float gelu_f(float v) {
  return 0.5f * v * (1.f + erff(v * 0.70710678118654752f));
}

// ================= weight convert + transpose (fp32 [K,N] -> fp16 [N,K]) ===
__global__ __launch_bounds__(256) void wconv_kernel(
    const float* __restrict__ W, __half* __restrict__ th, int K, int N) {
  __shared__ float t[32][33];
  int n0 = blockIdx.x * 32, k0 = blockIdx.y * 32;
  int tx = threadIdx.x & 31, ty = threadIdx.x >> 5;
#pragma unroll
  for (int i = 0; i < 4; i++)
    t[ty + i * 8][tx] = W[(size_t)(k0 + ty + i * 8) * N + n0 + tx];
  __syncthreads();
#pragma unroll
  for (int i = 0; i < 4; i++) {
    float v = t[tx][ty + i * 8];
    th[(size_t)(n0 + ty + i * 8) * K + k0 + tx] = __float2half_rn(v);
  }
}

// ================= LayerNorm (fp32 in) -> fp16 =================
__global__ __launch_bounds__(256) void ln_h_kernel(
    const float* __restrict__ in, const float* __restrict__ gw,
    const float* __restrict__ bw, __half* __restrict__ oh) {
  const int cols = 1024;
  int row = blockIdx.x;
  const float* rp = in + (size_t)row * cols;
  int c = threadIdx.x * 4;
  float4 v = *(const float4*)(rp + c);
  float s = v.x + v.y + v.z + v.w;
  float sq = v.x * v.x + v.y * v.y + v.z * v.z + v.w * v.w;
  __shared__ float red0[8], red1[8];
#pragma unroll
  for (int o = 16; o; o >>= 1) {
    s += __shfl_xor_sync(0xffffffff, s, o);
    sq += __shfl_xor_sync(0xffffffff, sq, o);
  }
  int warp = threadIdx.x >> 5, lane = threadIdx.x & 31;
  if (lane == 0) { red0[warp] = s; red1[warp] = sq; }
  __syncthreads();
  __shared__ float s_mu, s_ri;
  if (threadIdx.x == 0) {
    float ts = 0.f, tq = 0.f;
#pragma unroll
    for (int i = 0; i < 8; i++) { ts += red0[i]; tq += red1[i]; }
    float mu = ts / (float)cols;
    float var = tq / (float)cols - mu * mu;
    s_mu = mu;
    s_ri = rsqrtf(var + 1e-5f);
  }
  __syncthreads();
  float mu = s_mu, ri = s_ri;
  float4 g4 = *(const float4*)(gw + c);
  float4 b4 = *(const float4*)(bw + c);
  __half2 h01, h23;
  h01.x = __float2half_rn((v.x - mu) * ri * g4.x + b4.x);
  h01.y = __float2half_rn((v.y - mu) * ri * g4.y + b4.y);
  h23.x = __float2half_rn((v.z - mu) * ri * g4.z + b4.z);
  h23.y = __float2half_rn((v.w - mu) * ri * g4.w + b4.w);
  size_t o = (size_t)row * cols + c;
  *(__half2*)(oh + o) = h01;
  *(__half2*)(oh + o + 2) = h23;
}

// ================= LayerNorm (fp16 in, 4096 wide) -> fp16 =================
__global__ __launch_bounds__(256) void ln_h_in_kernel(
    const __half* __restrict__ in, const float* __restrict__ gw,
    const float* __restrict__ bw, __half* __restrict__ oh) {
  const int cols = 4096;
  int row = blockIdx.x;
  const __half* rp = in + (size_t)row * cols;
  float vals[16];
  float s = 0.f, sq = 0.f;
#pragma unroll
  for (int it = 0; it < 2; it++) {
    int c = (it * 256 + threadIdx.x) * 8;
    uint4 raw = *(const uint4*)(rp + c);
    const __half2* h2 = (const __half2*)&raw;
#pragma unroll
    for (int j = 0; j < 4; j++) {
      float2 f = __half22float2(h2[j]);
      vals[it * 8 + j * 2] = f.x;
      vals[it * 8 + j * 2 + 1] = f.y;
      s += f.x + f.y;
      sq += f.x * f.x + f.y * f.y;
    }
  }
  __shared__ float red0[8], red1[8];
#pragma unroll
  for (int o = 16; o; o >>= 1) {
    s += __shfl_xor_sync(0xffffffff, s, o);
    sq += __shfl_xor_sync(0xffffffff, sq, o);
  }
  int warp = threadIdx.x >> 5, lane = threadIdx.x & 31;
  if (lane == 0) { red0[warp] = s; red1[warp] = sq; }
  __syncthreads();
  __shared__ float s_mu, s_ri;
  if (threadIdx.x == 0) {
    float ts = 0.f, tq = 0.f;
#pragma unroll
    for (int i = 0; i < 8; i++) { ts += red0[i]; tq += red1[i]; }
    float mu = ts / (float)cols;
    float var = tq / (float)cols - mu * mu;
    s_mu = mu;
    s_ri = rsqrtf(var + 1e-5f);
  }
  __syncthreads();
  float mu = s_mu, ri = s_ri;
#pragma unroll
  for (int it = 0; it < 2; it++) {
    int c = (it * 256 + threadIdx.x) * 8;
    uint4 outw;
    __half2* oh2 = (__half2*)&outw;
#pragma unroll
    for (int j = 0; j < 4; j++) {
      float2 g2 = *(const float2*)(gw + c + j * 2);
      float2 b2 = *(const float2*)(bw + c + j * 2);
      float o0 = (vals[it * 8 + j * 2] - mu) * ri * g2.x + b2.x;
      float o1 = (vals[it * 8 + j * 2 + 1] - mu) * ri * g2.y + b2.y;
      oh2[j] = __floats2half2_rn(o0, o1);
    }
    *(uint4*)(oh + (size_t)row * cols + c) = outw;
  }
}

// ================= mma.sync fp16 GEMM (3-stage, 1 sync/iter) =============
// C = A[M,K] @ B^T + bias, B stored [N,K]. Tile 128x128x32, 8 warps (2m x 4n),
// warp 64x32, 3-stage cp.async ring, 2 CTAs/SM.
// EPI 0: bias->fp32; 1: bias+GELU->fp16 (q_ used as out); 2: bias+residual->fp32;
// EPI 3: QKV (bias + scale*log2e on q + RoPE + split write fp16).
#define TILE_H 10240                // 128 rows * 40 pitch * 2B
#define STAGE_H (2 * TILE_H)        // A, B
#define QSCALE 0.1803368801111244f  // 0.125 * log2(e)

template <int EPI>
__global__ __launch_bounds__(256, 2) void gemm_mma(
    const __half* __restrict__ Ah, const __half* __restrict__ Bh,
    const float* __restrict__ bias, const float* __restrict__ res,
    float* __restrict__ C, int K, int N,
    __half* q_, __half* k_, __half* v_) {
  extern __shared__ char smem[];
  uint32_t sb = smem_u32(smem);
  int tid = threadIdx.x, wid = tid >> 5, lane = tid & 31;
  int m0 = blockIdx.y * 128, n0 = blockIdx.x * 128;
  int wm = wid & 1, wn = wid >> 1;
  int lrow = lane & 15, lc8 = (lane >> 4) * 8;

  float acc[4][4][4];
#pragma unroll
  for (int i = 0; i < 4; i++)
#pragma unroll
    for (int j = 0; j < 4; j++)
#pragma unroll
      for (int t = 0; t < 4; t++) acc[i][j][t] = 0.f;

  int NCH = K >> 5;

#define GEMM_LOADS(stgbase, ktv)                                             \
  {                                                                          \
    uint32_t stg = (stgbase);                                                \
    int kt = (ktv);                                                          \
    _Pragma("unroll") for (int i = 0; i < 2; i++) {                          \
      int c = tid + i * 256;                                                 \
      int r = c >> 2, q = c & 3;                                             \
      uint32_t so = (uint32_t)(r * 80 + q * 16);                             \
      CP_ASYNC16(stg + so, Ah + (size_t)(m0 + r) * K + kt + q * 8);          \
      CP_ASYNC16(stg + TILE_H + so, Bh + (size_t)(n0 + r) * K + kt + q * 8); \
    }                                                                        \
    CP_COMMIT();                                                             \
  }

  GEMM_LOADS(sb, 0);
  GEMM_LOADS(sb + STAGE_H, 32);

  for (int kc = 0; kc < NCH; kc++) {
    if (kc + 1 < NCH) { CP_WAIT1(); } else { CP_WAIT0(); }
    __syncthreads();
    if (kc + 2 < NCH) GEMM_LOADS(sb + ((kc + 2) % 3) * STAGE_H, (kc + 2) * 32);

    uint32_t stA = sb + (kc % 3) * STAGE_H;
    uint32_t stB = stA + TILE_H;

#pragma unroll
    for (int ks = 0; ks < 32; ks += 16) {
      uint32_t bhf[8];
      uint32_t boff0 = (uint32_t)((wn * 32 + lrow) * 80 + (ks + lc8) * 2);
      uint32_t boff1 = (uint32_t)((wn * 32 + 16 + lrow) * 80 + (ks + lc8) * 2);
      LDSM_X4(bhf[0], bhf[1], bhf[2], bhf[3], stB + boff0);
      LDSM_X4(bhf[4], bhf[5], bhf[6], bhf[7], stB + boff1);
#pragma unroll
      for (int mb = 0; mb < 4; mb++) {
        uint32_t ah[4];
        uint32_t aoff = (uint32_t)((wm * 64 + mb * 16 + lrow) * 80 + (ks + lc8) * 2);
        LDSM_X4(ah[0], ah[1], ah[2], ah[3], stA + aoff);
#pragma unroll
        for (int nb = 0; nb < 4; nb++) {
          int pi = (nb >> 1) * 4, od = nb & 1;
          MMA16816(acc[mb][nb], ah[0], ah[1], ah[2], ah[3],
                   bhf[pi + od], bhf[pi + 2 + od]);
        }
      }
    }
  }

  int erow = lane >> 2, ecol = (lane & 3) * 2;
#pragma unroll
  for (int mb = 0; mb < 4; mb++) {
#pragma unroll
    for (int nb = 0; nb < 4; nb++) {
      float* d = acc[mb][nb];
      int gr = m0 + wm * 64 + mb * 16 + erow;
      int gc = n0 + wn * 32 + nb * 8 + ecol;
      float2 b2 = *(const float2*)(bias + gc);
      float v0 = d[0] + b2.x, v1 = d[1] + b2.y;
      float v2 = d[2] + b2.x, v3 = d[3] + b2.y;
      if (EPI == 1) {
        v0 = gelu_f(v0); v1 = gelu_f(v1);
        v2 = gelu_f(v2); v3 = gelu_f(v3);
        *(__half2*)(q_ + (size_t)gr * N + gc) = __floats2half2_rn(v0, v1);
        *(__half2*)(q_ + (size_t)(gr + 8) * N + gc) = __floats2half2_rn(v2, v3);
      } else if (EPI == 2) {
        float2 r0 = *(const float2*)(res + (size_t)gr * N + gc);
        float2 r1 = *(const float2*)(res + (size_t)(gr + 8) * N + gc);
        v0 += r0.x; v1 += r0.y; v2 += r1.x; v3 += r1.y;
        float2 o0 = {v0, v1}, o1 = {v2, v3};
        *(float2*)(C + (size_t)gr * N + gc) = o0;
        *(float2*)(C + (size_t)(gr + 8) * N + gc) = o1;
      } else if (EPI == 3) {
        int region = gc >> 10;           // 0 q, 1 k, 2 v
        int hh = (gc & 1023) >> 6;
        int dd = gc & 63;
        int b = gr >> 11;
        int n = gr & 2047;
        if (region < 2) {
          float inv = 1.0f / powf(10000.0f, (float)(dd & ~1) / 64.0f);
          float c0, s0, c1, s1;
          sincosf((float)n * inv, &s0, &c0);
          sincosf((float)(n + 8) * inv, &s1, &c1);
          float r0 = v0 * c0 - v1 * s0, r1 = v1 * c0 + v0 * s0;
          float r2 = v2 * c1 - v3 * s1, r3 = v3 * c1 + v2 * s1;
          v0 = r0; v1 = r1; v2 = r2; v3 = r3;
          if (region == 0) { v0 *= QSCALE; v1 *= QSCALE; v2 *= QSCALE; v3 *= QSCALE; }
        }
        __half* dst = (region == 0) ? q_ : (region == 1) ? k_ : v_;
        size_t o0 = ((size_t)((b * 16 + hh) * 2048 + n)) * 64 + dd;
        size_t o1 = o0 + 8 * 64;
        *(__half2*)(dst + o0) = __floats2half2_rn(v0, v1);
        *(__half2*)(dst + o1) = __floats2half2_rn(v2, v3);
      } else {
        float2 o0 = {v0, v1}, o1 = {v2, v3};
        *(float2*)(C + (size_t)gr * N + gc) = o0;
        *(float2*)(C + (size_t)(gr + 8) * N + gc) = o1;
      }
    }
  }
}

// ================= FA2 flash attention (register softmax) =================
// q-tile 128, 8 warps x 16 q-rows, full 64-k per warp. S and P live in
// registers; 1 sync/iter (KV ring). q pre-scaled by 0.125*log2e -> exp2f.
#define APB 144   // bytes per smem row (72 fp16)
#define A_oQ 0                  // 128 * 144 = 18432
#define A_oKV 18432             // 3 stages x (K 9216 + V 9216)
#define ATTN_SMEM (18432 + 3 * 18432)   // 73728

__global__ __launch_bounds__(256, 2) void attn_mma(
    const __half* __restrict__ qg, const __half* __restrict__ kg_,
    const __half* __restrict__ vg, __half* __restrict__ og) {
  extern __shared__ char sm[];
  uint32_t sb = smem_u32(sm);

  int tid = threadIdx.x, wid = tid >> 5, lane = tid & 31;
  int lrow = lane & 15, lc8 = (lane >> 4) * 8;
  int erow = lane >> 2, ecol = (lane & 3) * 2;
  int bh = blockIdx.y, qt = blockIdx.x;
  size_t base = (size_t)bh * (2048 * 64);

  // Q tile (128 rows) — first commit group
  {
    const __half* gq = qg + base + (size_t)(qt * 128) * 64;
#pragma unroll
    for (int i = 0; i < 4; i++) {
      int f = tid + i * 256;
      int r = f >> 3, c8 = f & 7;
      CP_ASYNC16(sb + A_oQ + (uint32_t)(r * APB + c8 * 16), gq + r * 64 + c8 * 8);
    }
    CP_COMMIT();
  }

#define ATTN_KV_LOADS(stg, ktv)                                              \
  {                                                                          \
    int kt_ = (ktv);                                                         \
    uint32_t d0 = sb + A_oKV + (stg) * 18432;                                \
    _Pragma("unroll") for (int i = 0; i < 2; i++) {                          \
      int f = tid + i * 256;                                                 \
      int r = f >> 3, c8 = f & 7;                                            \
      uint32_t so = (uint32_t)(r * APB + c8 * 16);                           \
      size_t go = base + (size_t)(kt_ * 64 + r) * 64 + c8 * 8;               \
      CP_ASYNC16(d0 + so, kg_ + go);                                         \
      CP_ASYNC16(d0 + 9216 + so, vg + go);                                   \
    }                                                                        \
    CP_COMMIT();                                                             \
  }

  ATTN_KV_LOADS(0, 0);
  ATTN_KV_LOADS(1, 1);

  float oacc[8][4];
#pragma unroll
  for (int j = 0; j < 8; j++)
#pragma unroll
    for (int t = 0; t < 4; t++) oacc[j][t] = 0.f;
  float m_lo = -INFINITY, m_hi = -INFINITY, l_lo = 0.f, l_hi = 0.f;

  uint32_t qbase = sb + A_oQ + (uint32_t)((wid * 16 + lrow) * APB + lc8 * 2);

  for (int kt = 0; kt < 32; kt++) {
    if (kt + 1 < 32) { CP_WAIT1(); } else { CP_WAIT0(); }
    __syncthreads();
    if (kt + 2 < 32) ATTN_KV_LOADS((kt + 2) % 3, kt + 2);

    uint32_t sK = sb + A_oKV + (kt % 3) * 18432;
    uint32_t sV = sK + 9216;

    // ---- S = Q' K^T (q pre-scaled) : sacc[8 n8-blocks][4] ----
    float sacc[8][4];
#pragma unroll
    for (int j = 0; j < 8; j++)
#pragma unroll
      for (int t = 0; t < 4; t++) sacc[j][t] = 0.f;
#pragma unroll
    for (int ks = 0; ks < 4; ks++) {
      uint32_t aq[4];
      LDSM_X4(aq[0], aq[1], aq[2], aq[3], qbase + ks * 32);
#pragma unroll
      for (int g = 0; g < 4; g++) {
        uint32_t kb[4];
        uint32_t koff = (uint32_t)((g * 16 + lrow) * APB + (ks * 16 + lc8) * 2);
        LDSM_X4(kb[0], kb[1], kb[2], kb[3], sK + koff);
        MMA16816(sacc[g * 2 + 0], aq[0], aq[1], aq[2], aq[3], kb[0], kb[2]);
        MMA16816(sacc[g * 2 + 1], aq[0], aq[1], aq[2], aq[3], kb[1], kb[3]);
      }
    }

    // ---- register softmax (rows erow, erow+8; log2 domain) ----
    float mx0 = -INFINITY, mx1 = -INFINITY;
#pragma unroll
    for (int j = 0; j < 8; j++) {
      mx0 = fmaxf(mx0, fmaxf(sacc[j][0], sacc[j][1]));
      mx1 = fmaxf(mx1, fmaxf(sacc[j][2], sacc[j][3]));
    }
    mx0 = fmaxf(mx0, __shfl_xor_sync(0xffffffff, mx0, 1));
    mx0 = fmaxf(mx0, __shfl_xor_sync(0xffffffff, mx0, 2));
    mx1 = fmaxf(mx1, __shfl_xor_sync(0xffffffff, mx1, 1));
    mx1 = fmaxf(mx1, __shfl_xor_sync(0xffffffff, mx1, 2));
    float nm0 = fmaxf(m_lo, mx0), nm1 = fmaxf(m_hi, mx1);
    float cf0 = exp2f(m_lo - nm0), cf1 = exp2f(m_hi - nm1);
    m_lo = nm0; m_hi = nm1;

    uint32_t pa[4][4];
    float s0 = 0.f, s1 = 0.f;
#pragma unroll
    for (int g = 0; g < 4; g++) {
#pragma unroll
      for (int hb = 0; hb < 2; hb++) {
        int j = g * 2 + hb;
        float p00 = exp2f(sacc[j][0] - nm0);
        float p01 = exp2f(sacc[j][1] - nm0);
        float p10 = exp2f(sacc[j][2] - nm1);
        float p11 = exp2f(sacc[j][3] - nm1);
        s0 += p00 + p01;
        s1 += p10 + p11;
        __half2 plo = __floats2half2_rn(p00, p01);
        __half2 phi = __floats2half2_rn(p10, p11);
        pa[g][hb * 2 + 0] = *(uint32_t*)&plo;
        pa[g][hb * 2 + 1] = *(uint32_t*)&phi;
      }
    }
    s0 += __shfl_xor_sync(0xffffffff, s0, 1);
    s0 += __shfl_xor_sync(0xffffffff, s0, 2);
    s1 += __shfl_xor_sync(0xffffffff, s1, 1);
    s1 += __shfl_xor_sync(0xffffffff, s1, 2);
    l_lo = l_lo * cf0 + s0;
    l_hi = l_hi * cf1 + s1;

    // ---- O = O*c + P V ----
#pragma unroll
    for (int j = 0; j < 8; j++) {
      oacc[j][0] *= cf0; oacc[j][1] *= cf0;
      oacc[j][2] *= cf1; oacc[j][3] *= cf1;
    }
#pragma unroll
    for (int g = 0; g < 4; g++) {
#pragma unroll
      for (int db = 0; db < 4; db++) {
        uint32_t vb[4];
        uint32_t voff = (uint32_t)((g * 16 + lrow) * APB + (db * 16 + lc8) * 2);
        LDSM_X4_T(vb[0], vb[1], vb[2], vb[3], sV + voff);
        MMA16816(oacc[db * 2 + 0], pa[g][0], pa[g][1], pa[g][2], pa[g][3],
                 vb[0], vb[1]);
        MMA16816(oacc[db * 2 + 1], pa[g][0], pa[g][1], pa[g][2], pa[g][3],
                 vb[2], vb[3]);
      }
    }
  }

  // ---- output: O / l -> fp16 at [B,N,C] ----
  int b = bh >> 4, h = bh & 15;
  float il0 = 1.f / l_lo, il1 = 1.f / l_hi;
  int qrow = qt * 128 + wid * 16 + erow;
  size_t rbase0 = ((size_t)(b * 2048 + qrow)) * 1024 + h * 64;
  size_t rbase1 = rbase0 + 8 * 1024;
#pragma unroll
  for (int db = 0; db < 4; db++) {
#pragma unroll
    for (int nb = 0; nb < 2; nb++) {
      int j = db * 2 + nb;
      int d = db * 16 + nb * 8 + ecol;
      *(__half2*)(og + rbase0 + d) = __floats2half2_rn(oacc[j][0] * il0,
                                                       oacc[j][1] * il0);
      *(__half2*)(og + rbase1 + d) = __floats2half2_rn(oacc[j][2] * il1,
                                                       oacc[j][3] * il1);
    }
  }
}

// ================= launch =================
#define GEMM_SMEM (3 * STAGE_H)   // 61440 bytes

extern "C" void kernel_launch(void* const* d_in, const int* in_sizes, int n_in,
                              void* d_out, int out_size) {
  const float* x = (const float*)d_in[0];
  const float* ln1_g = (const float*)d_in[1];
  const float* ln1_b = (const float*)d_in[2];
  const float* qkv_w = (const float*)d_in[3];
  const float* qkv_b = (const float*)d_in[4];
  const float* proj_w = (const float*)d_in[5];
  const float* proj_b = (const float*)d_in[6];
  const float* ln2_g = (const float*)d_in[7];
  const float* ln2_b = (const float*)d_in[8];
  const float* fc1_w = (const float*)d_in[9];
  const float* fc1_b = (const float*)d_in[10];
  const float* ffln_g = (const float*)d_in[11];
  const float* ffln_b = (const float*)d_in[12];
  const float* fc2_w = (const float*)d_in[13];
  const float* fc2_b = (const float*)d_in[14];
  float* out = (float*)d_out;

  float* x1;
  __half *h1h, *ah, *att, *q, *k, *v;
  __half *wq, *wp, *w1, *w2;
  cudaGetSymbolAddress((void**)&x1, g_x1);
  cudaGetSymbolAddress((void**)&h1h, g_h1h);
  cudaGetSymbolAddress((void**)&ah, g_ah);
  cudaGetSymbolAddress((void**)&att, g_att);
  cudaGetSymbolAddress((void**)&q, g_q2);
  cudaGetSymbolAddress((void**)&k, g_k2);
  cudaGetSymbolAddress((void**)&v, g_v2);
  cudaGetSymbolAddress((void**)&wq, g_wq);
  cudaGetSymbolAddress((void**)&wp, g_wp);
  cudaGetSymbolAddress((void**)&w1, g_w1);
  cudaGetSymbolAddress((void**)&w2, g_w2);

  cudaFuncSetAttribute(gemm_mma<0>, cudaFuncAttributeMaxDynamicSharedMemorySize, GEMM_SMEM);
  cudaFuncSetAttribute(gemm_mma<1>, cudaFuncAttributeMaxDynamicSharedMemorySize, GEMM_SMEM);
  cudaFuncSetAttribute(gemm_mma<2>, cudaFuncAttributeMaxDynamicSharedMemorySize, GEMM_SMEM);
  cudaFuncSetAttribute(gemm_mma<3>, cudaFuncAttributeMaxDynamicSharedMemorySize, GEMM_SMEM);
  cudaFuncSetAttribute(attn_mma, cudaFuncAttributeMaxDynamicSharedMemorySize, ATTN_SMEM);

  wconv_kernel<<<dim3(3072 / 32, 1024 / 32), 256>>>(qkv_w, wq, 1024, 3072);
  wconv_kernel<<<dim3(1024 / 32, 1024 / 32), 256>>>(proj_w, wp, 1024, 1024);
  wconv_kernel<<<dim3(4096 / 32, 1024 / 32), 256>>>(fc1_w, w1, 1024, 4096);
  wconv_kernel<<<dim3(1024 / 32, 4096 / 32), 256>>>(fc2_w, w2, 4096, 1024);

  // 1) LN1 -> fp16
  ln_h_kernel<<<ROWS, 256>>>(x, ln1_g, ln1_b, ah);
  // 2) QKV GEMM + RoPE + scale + split write (EPI 3)
  gemm_mma<3><<<dim3(3072 / 128, ROWS / 128), 256, GEMM_SMEM>>>(
      ah, wq, qkv_b, nullptr, nullptr, 1024, 3072, q, k, v);
  // 3) attention (FA2 register softmax)
  attn_mma<<<dim3(NNq / 128, BB * HHn), 256, ATTN_SMEM>>>(q, k, v, att);
  // 4) proj + residual(x) -> x1 (fp32)
  gemm_mma<2><<<dim3(1024 / 128, ROWS / 128), 256, GEMM_SMEM>>>(
      att, wp, proj_b, x, x1, 1024, 1024, nullptr, nullptr, nullptr);
  // 5) LN2 -> fp16
  ln_h_kernel<<<ROWS, 256>>>(x1, ln2_g, ln2_b, ah);
  // 6) fc1 + GELU -> fp16 h1h (EPI 1)
  gemm_mma<1><<<dim3(4096 / 128, ROWS / 128), 256, GEMM_SMEM>>>(
      ah, w1, fc1_b, nullptr, nullptr, 1024, 4096, h1h, nullptr, nullptr);
  // 7) ffn LN (fp16 in, 4096 wide) -> fp16
  ln_h_in_kernel<<<ROWS, 256>>>(h1h, ffln_g, ffln_b, ah);
  // 8) fc2 + residual(x1) -> out (fp32)
  gemm_mma<2><<<dim3(1024 / 128, ROWS / 128), 256, GEMM_SMEM>>>(
      ah, w2, fc2_b, x1, out, 4096, 1024, nullptr, nullptr, nullptr);
}

// round 11
// speedup vs baseline: 2.9391x; 1.0780x over previous
#include <cuda_runtime.h>
#include <cuda_fp16.h>
#include <math.h>
#include <stdint.h>

#define BB 2
#define NNq 2048
#define CCd 1024
#define HHn 16
#define HIDd 4096
#define ROWS (BB * NNq)   // 4096

// ================= scratch (device globals) =================
__device__ __half g_x1h[ROWS * CCd];           // x + proj(attn), fp16
__device__ __half g_h1h[ROWS * HIDd];          // fc1+gelu out (fp16)
__device__ __half g_ah[ROWS * HIDd];           // activations (fp16)
__device__ __half g_att[ROWS * CCd];           // attention out
__device__ __half g_q2[ROWS * CCd];            // q [B,H,N,D] (RoPE+scale)
__device__ __half g_k2[ROWS * CCd];            // k
__device__ __half g_v2[ROWS * CCd];            // v
__device__ __half g_wq[3072 * 1024];
__device__ __half g_wp[1024 * 1024];
__device__ __half g_w1[4096 * 1024];
__device__ __half g_w2[1024 * 4096];

// ================= helpers =================
__device__ __forceinline__ uint32_t smem_u32(const void* p) {
  uint32_t a;
  asm("{ .reg .u64 t; cvta.to.shared.u64 t, %1; cvt.u32.u64 %0, t; }"
      : "=r"(a) : "l"(p));
  return a;
}

#define CP_ASYNC16(sm, gp) \
  asm volatile("cp.async.cg.shared.global [%0], [%1], 16;" \
               :: "r"(sm), "l"(gp) : "memory")
#define CP_COMMIT() asm volatile("cp.async.commit_group;" ::: "memory")
#define CP_WAIT0() asm volatile("cp.async.wait_group 0;" ::: "memory")
#define CP_WAIT1() asm volatile("cp.async.wait_group 1;" ::: "memory")

#define LDSM_X4(r0, r1, r2, r3, a) \
  asm volatile("ldmatrix.sync.aligned.m8n8.x4.shared.b16 {%0,%1,%2,%3}, [%4];" \
               : "=r"(r0), "=r"(r1), "=r"(r2), "=r"(r3) : "r"(a))
#define LDSM_X4_T(r0, r1, r2, r3, a) \
  asm volatile("ldmatrix.sync.aligned.m8n8.x4.trans.shared.b16 {%0,%1,%2,%3}, [%4];" \
               : "=r"(r0), "=r"(r1), "=r"(r2), "=r"(r3) : "r"(a))

#define MMA16816(d, a0, a1, a2, a3, b0, b1) \
  asm volatile("mma.sync.aligned.m16n8k16.row.col.f32.f16.f16.f32 " \
               "{%0,%1,%2,%3}, {%4,%5,%6,%7}, {%8,%9}, {%0,%1,%2,%3};" \
               : "+f"((d)[0]), "+f"((d)[1]), "+f"((d)[2]), "+f"((d)[3]) \
               : "r"(a0), "r"(a1), "r"(a2), "r"(a3), "r"(b0), "r"(b1))

__device__ __forceinline__ float gelu_f(float v) {
  return 0.5f * v * (1.f + erff(v * 0.70710678118654752f));
}

// ================= weight convert + transpose (fp32 [K,N] -> fp16 [N,K]) ===
__global__ __launch_bounds__(256) void wconv_kernel(
    const float* __restrict__ W, __half* __restrict__ th, int K, int N) {
  __shared__ float t[32][33];
  int n0 = blockIdx.x * 32, k0 = blockIdx.y * 32;
  int tx = threadIdx.x & 31, ty = threadIdx.x >> 5;
#pragma unroll
  for (int i = 0; i < 4; i++)
    t[ty + i * 8][tx] = W[(size_t)(k0 + ty + i * 8) * N + n0 + tx];
  __syncthreads();
#pragma unroll
  for (int i = 0; i < 4; i++) {
    float v = t[tx][ty + i * 8];
    th[(size_t)(n0 + ty + i * 8) * K + k0 + tx] = __float2half_rn(v);
  }
}

// ================= LayerNorm (fp32 in, 1024) -> fp16 =================
__global__ __launch_bounds__(256) void ln_h_kernel(
    const float* __restrict__ in, const float* __restrict__ gw,
    const float* __restrict__ bw, __half* __restrict__ oh) {
  const int cols = 1024;
  int row = blockIdx.x;
  const float* rp = in + (size_t)row * cols;
  int c = threadIdx.x * 4;
  float4 v = *(const float4*)(rp + c);
  float s = v.x + v.y + v.z + v.w;
  float sq = v.x * v.x + v.y * v.y + v.z * v.z + v.w * v.w;
  __shared__ float red0[8], red1[8];
#pragma unroll
  for (int o = 16; o; o >>= 1) {
    s += __shfl_xor_sync(0xffffffff, s, o);
    sq += __shfl_xor_sync(0xffffffff, sq, o);
  }
  int warp = threadIdx.x >> 5, lane = threadIdx.x & 31;
  if (lane == 0) { red0[warp] = s; red1[warp] = sq; }
  __syncthreads();
  __shared__ float s_mu, s_ri;
  if (threadIdx.x == 0) {
    float ts = 0.f, tq = 0.f;
#pragma unroll
    for (int i = 0; i < 8; i++) { ts += red0[i]; tq += red1[i]; }
    float mu = ts / (float)cols;
    float var = tq / (float)cols - mu * mu;
    s_mu = mu;
    s_ri = rsqrtf(var + 1e-5f);
  }
  __syncthreads();
  float mu = s_mu, ri = s_ri;
  float4 g4 = *(const float4*)(gw + c);
  float4 b4 = *(const float4*)(bw + c);
  __half2 h01, h23;
  h01.x = __float2half_rn((v.x - mu) * ri * g4.x + b4.x);
  h01.y = __float2half_rn((v.y - mu) * ri * g4.y + b4.y);
  h23.x = __float2half_rn((v.z - mu) * ri * g4.z + b4.z);
  h23.y = __float2half_rn((v.w - mu) * ri * g4.w + b4.w);
  size_t o = (size_t)row * cols + c;
  *(__half2*)(oh + o) = h01;
  *(__half2*)(oh + o + 2) = h23;
}

// ================= LayerNorm (fp16 in, 1024) -> fp16 =================
__global__ __launch_bounds__(256) void ln_h16_kernel(
    const __half* __restrict__ in, const float* __restrict__ gw,
    const float* __restrict__ bw, __half* __restrict__ oh) {
  const int cols = 1024;
  int row = blockIdx.x;
  const __half* rp = in + (size_t)row * cols;
  int c = threadIdx.x * 4;
  __half2 raw0 = *(const __half2*)(rp + c);
  __half2 raw1 = *(const __half2*)(rp + c + 2);
  float2 f0 = __half22float2(raw0), f1 = __half22float2(raw1);
  float s = f0.x + f0.y + f1.x + f1.y;
  float sq = f0.x * f0.x + f0.y * f0.y + f1.x * f1.x + f1.y * f1.y;
  __shared__ float red0[8], red1[8];
#pragma unroll
  for (int o = 16; o; o >>= 1) {
    s += __shfl_xor_sync(0xffffffff, s, o);
    sq += __shfl_xor_sync(0xffffffff, sq, o);
  }
  int warp = threadIdx.x >> 5, lane = threadIdx.x & 31;
  if (lane == 0) { red0[warp] = s; red1[warp] = sq; }
  __syncthreads();
  __shared__ float s_mu, s_ri;
  if (threadIdx.x == 0) {
    float ts = 0.f, tq = 0.f;
#pragma unroll
    for (int i = 0; i < 8; i++) { ts += red0[i]; tq += red1[i]; }
    float mu = ts / (float)cols;
    float var = tq / (float)cols - mu * mu;
    s_mu = mu;
    s_ri = rsqrtf(var + 1e-5f);
  }
  __syncthreads();
  float mu = s_mu, ri = s_ri;
  float4 g4 = *(const float4*)(gw + c);
  float4 b4 = *(const float4*)(bw + c);
  __half2 h01, h23;
  h01 = __floats2half2_rn((f0.x - mu) * ri * g4.x + b4.x,
                          (f0.y - mu) * ri * g4.y + b4.y);
  h23 = __floats2half2_rn((f1.x - mu) * ri * g4.z + b4.z,
                          (f1.y - mu) * ri * g4.w + b4.w);
  size_t o = (size_t)row * cols + c;
  *(__half2*)(oh + o) = h01;
  *(__half2*)(oh + o + 2) = h23;
}

// ================= LayerNorm (fp16 in, 4096 wide) -> fp16 =================
__global__ __launch_bounds__(256) void ln_h_in_kernel(
    const __half* __restrict__ in, const float* __restrict__ gw,
    const float* __restrict__ bw, __half* __restrict__ oh) {
  const int cols = 4096;
  int row = blockIdx.x;
  const __half* rp = in + (size_t)row * cols;
  float vals[16];
  float s = 0.f, sq = 0.f;
#pragma unroll
  for (int it = 0; it < 2; it++) {
    int c = (it * 256 + threadIdx.x) * 8;
    uint4 raw = *(const uint4*)(rp + c);
    const __half2* h2 = (const __half2*)&raw;
#pragma unroll
    for (int j = 0; j < 4; j++) {
      float2 f = __half22float2(h2[j]);
      vals[it * 8 + j * 2] = f.x;
      vals[it * 8 + j * 2 + 1] = f.y;
      s += f.x + f.y;
      sq += f.x * f.x + f.y * f.y;
    }
  }
  __shared__ float red0[8], red1[8];
#pragma unroll
  for (int o = 16; o; o >>= 1) {
    s += __shfl_xor_sync(0xffffffff, s, o);
    sq += __shfl_xor_sync(0xffffffff, sq, o);
  }
  int warp = threadIdx.x >> 5, lane = threadIdx.x & 31;
  if (lane == 0) { red0[warp] = s; red1[warp] = sq; }
  __syncthreads();
  __shared__ float s_mu, s_ri;
  if (threadIdx.x == 0) {
    float ts = 0.f, tq = 0.f;
#pragma unroll
    for (int i = 0; i < 8; i++) { ts += red0[i]; tq += red1[i]; }
    float mu = ts / (float)cols;
    float var = tq / (float)cols - mu * mu;
    s_mu = mu;
    s_ri = rsqrtf(var + 1e-5f);
  }
  __syncthreads();
  float mu = s_mu, ri = s_ri;
#pragma unroll
  for (int it = 0; it < 2; it++) {
    int c = (it * 256 + threadIdx.x) * 8;
    uint4 outw;
    __half2* oh2 = (__half2*)&outw;
#pragma unroll
    for (int j = 0; j < 4; j++) {
      float2 g2 = *(const float2*)(gw + c + j * 2);
      float2 b2 = *(const float2*)(bw + c + j * 2);
      float o0 = (vals[it * 8 + j * 2] - mu) * ri * g2.x + b2.x;
      float o1 = (vals[it * 8 + j * 2 + 1] - mu) * ri * g2.y + b2.y;
      oh2[j] = __floats2half2_rn(o0, o1);
    }
    *(uint4*)(oh + (size_t)row * cols + c) = outw;
  }
}

// ================= mma.sync fp16 GEMM (BK=64, 3-stage, 1 sync/iter) =======
// C = A[M,K] @ B^T + bias, B stored [N,K]. Tile 128x128x64, 8 warps (2m x 4n),
// warp 64x32. EPI 0: bias->fp32; 1: bias+GELU->fp16(hout);
// EPI 3: QKV (bias + qscale + RoPE + split fp16);
// EPI 4: bias + res(fp32) -> fp16(hout); EPI 5: bias + resh(fp16) -> fp32(C).
#define GPITCH 144                  // bytes per row (72 halves)
#define TILE_H (128 * GPITCH)       // 18432
#define STAGE_H (2 * TILE_H)        // 36864
#define GEMM_SMEM (3 * STAGE_H)     // 110592
#define QSCALE 0.1803368801111244f  // 0.125 * log2(e)

template <int EPI>
__global__ __launch_bounds__(256, 2) void gemm_mma(
    const __half* __restrict__ Ah, const __half* __restrict__ Bh,
    const float* __restrict__ bias, const float* __restrict__ res,
    const __half* __restrict__ resh,
    float* __restrict__ C, int K, int N,
    __half* hout, __half* k_, __half* v_) {
  extern __shared__ char smem[];
  uint32_t sb = smem_u32(smem);
  int tid = threadIdx.x, wid = tid >> 5, lane = tid & 31;
  int m0 = blockIdx.y * 128, n0 = blockIdx.x * 128;
  int wm = wid & 1, wn = wid >> 1;
  int lrow = lane & 15, lc8 = (lane >> 4) * 8;

  float acc[4][4][4];
#pragma unroll
  for (int i = 0; i < 4; i++)
#pragma unroll
    for (int j = 0; j < 4; j++)
#pragma unroll
      for (int t = 0; t < 4; t++) acc[i][j][t] = 0.f;

  int NCH = K >> 6;

  // 128 rows x 8 chunks(16B) per operand; 256 threads x 4 iters covers 1024.
#define GEMM_LOADS(stgbase, ktv)                                             \
  {                                                                          \
    uint32_t stg = (stgbase);                                                \
    int kt = (ktv);                                                          \
    _Pragma("unroll") for (int i = 0; i < 4; i++) {                          \
      int c = tid + i * 256;                                                 \
      int r = c >> 3, q = c & 7;                                             \
      uint32_t so = (uint32_t)(r * GPITCH + q * 16);                         \
      CP_ASYNC16(stg + so, Ah + (size_t)(m0 + r) * K + kt + q * 8);          \
      CP_ASYNC16(stg + TILE_H + so, Bh + (size_t)(n0 + r) * K + kt + q * 8); \
    }                                                                        \
    CP_COMMIT();                                                             \
  }

  GEMM_LOADS(sb, 0);
  GEMM_LOADS(sb + STAGE_H, 64);

  for (int kc = 0; kc < NCH; kc++) {
    if (kc + 1 < NCH) { CP_WAIT1(); } else { CP_WAIT0(); }
    __syncthreads();
    if (kc + 2 < NCH) GEMM_LOADS(sb + ((kc + 2) % 3) * STAGE_H, (kc + 2) * 64);

    uint32_t stA = sb + (kc % 3) * STAGE_H;
    uint32_t stB = stA + TILE_H;

#pragma unroll
    for (int ks = 0; ks < 64; ks += 16) {
      uint32_t bhf[8];
      uint32_t boff0 = (uint32_t)((wn * 32 + lrow) * GPITCH + (ks + lc8) * 2);
      uint32_t boff1 = (uint32_t)((wn * 32 + 16 + lrow) * GPITCH + (ks + lc8) * 2);
      LDSM_X4(bhf[0], bhf[1], bhf[2], bhf[3], stB + boff0);
      LDSM_X4(bhf[4], bhf[5], bhf[6], bhf[7], stB + boff1);
#pragma unroll
      for (int mb = 0; mb < 4; mb++) {
        uint32_t ah[4];
        uint32_t aoff = (uint32_t)((wm * 64 + mb * 16 + lrow) * GPITCH + (ks + lc8) * 2);
        LDSM_X4(ah[0], ah[1], ah[2], ah[3], stA + aoff);
#pragma unroll
        for (int nb = 0; nb < 4; nb++) {
          int pi = (nb >> 1) * 4, od = nb & 1;
          MMA16816(acc[mb][nb], ah[0], ah[1], ah[2], ah[3],
                   bhf[pi + od], bhf[pi + 2 + od]);
        }
      }
    }
  }

  int erow = lane >> 2, ecol = (lane & 3) * 2;
#pragma unroll
  for (int mb = 0; mb < 4; mb++) {
#pragma unroll
    for (int nb = 0; nb < 4; nb++) {
      float* d = acc[mb][nb];
      int gr = m0 + wm * 64 + mb * 16 + erow;
      int gc = n0 + wn * 32 + nb * 8 + ecol;
      float2 b2 = *(const float2*)(bias + gc);
      float v0 = d[0] + b2.x, v1 = d[1] + b2.y;
      float v2 = d[2] + b2.x, v3 = d[3] + b2.y;
      if (EPI == 1) {
        v0 = gelu_f(v0); v1 = gelu_f(v1);
        v2 = gelu_f(v2); v3 = gelu_f(v3);
        *(__half2*)(hout + (size_t)gr * N + gc) = __floats2half2_rn(v0, v1);
        *(__half2*)(hout + (size_t)(gr + 8) * N + gc) = __floats2half2_rn(v2, v3);
      } else if (EPI == 3) {
        int region = gc >> 10;           // 0 q, 1 k, 2 v
        int hh = (gc & 1023) >> 6;
        int dd = gc & 63;
        int b = gr >> 11;
        int n = gr & 2047;
        if (region < 2) {
          float inv = 1.0f / powf(10000.0f, (float)(dd & ~1) / 64.0f);
          float c0, s0, c1, s1;
          sincosf((float)n * inv, &s0, &c0);
          sincosf((float)(n + 8) * inv, &s1, &c1);
          float r0 = v0 * c0 - v1 * s0, r1 = v1 * c0 + v0 * s0;
          float r2 = v2 * c1 - v3 * s1, r3 = v3 * c1 + v2 * s1;
          v0 = r0; v1 = r1; v2 = r2; v3 = r3;
          if (region == 0) { v0 *= QSCALE; v1 *= QSCALE; v2 *= QSCALE; v3 *= QSCALE; }
        }
        __half* dst = (region == 0) ? hout : (region == 1) ? k_ : v_;
        size_t o0 = ((size_t)((b * 16 + hh) * 2048 + n)) * 64 + dd;
        size_t o1 = o0 + 8 * 64;
        *(__half2*)(dst + o0) = __floats2half2_rn(v0, v1);
        *(__half2*)(dst + o1) = __floats2half2_rn(v2, v3);
      } else if (EPI == 4) {
        float2 r0 = *(const float2*)(res + (size_t)gr * N + gc);
        float2 r1 = *(const float2*)(res + (size_t)(gr + 8) * N + gc);
        v0 += r0.x; v1 += r0.y; v2 += r1.x; v3 += r1.y;
        *(__half2*)(hout + (size_t)gr * N + gc) = __floats2half2_rn(v0, v1);
        *(__half2*)(hout + (size_t)(gr + 8) * N + gc) = __floats2half2_rn(v2, v3);
      } else if (EPI == 5) {
        __half2 r0 = *(const __half2*)(resh + (size_t)gr * N + gc);
        __half2 r1 = *(const __half2*)(resh + (size_t)(gr + 8) * N + gc);
        float2 f0 = __half22float2(r0), f1 = __half22float2(r1);
        v0 += f0.x; v1 += f0.y; v2 += f1.x; v3 += f1.y;
        float2 o0 = {v0, v1}, o1 = {v2, v3};
        *(float2*)(C + (size_t)gr * N + gc) = o0;
        *(float2*)(C + (size_t)(gr + 8) * N + gc) = o1;
      } else {
        float2 o0 = {v0, v1}, o1 = {v2, v3};
        *(float2*)(C + (size_t)gr * N + gc) = o0;
        *(float2*)(C + (size_t)(gr + 8) * N + gc) = o1;
      }
    }
  }
}

// ================= FA2 flash attention (register softmax, Q hoisted) ======
#define APB 144   // bytes per smem row (72 fp16)
#define A_oQ 0                  // 128 * 144 = 18432
#define A_oKV 18432             // 3 stages x (K 9216 + V 9216)
#define ATTN_SMEM (18432 + 3 * 18432)   // 73728

__global__ __launch_bounds__(256, 2) void attn_mma(
    const __half* __restrict__ qg, const __half* __restrict__ kg_,
    const __half* __restrict__ vg, __half* __restrict__ og) {
  extern __shared__ char sm[];
  uint32_t sb = smem_u32(sm);

  int tid = threadIdx.x, wid = tid >> 5, lane = tid & 31;
  int lrow = lane & 15, lc8 = (lane >> 4) * 8;
  int erow = lane >> 2, ecol = (lane & 3) * 2;
  int bh = blockIdx.y, qt = blockIdx.x;
  size_t base = (size_t)bh * (2048 * 64);

  // Q tile (128 rows) — first commit group
  {
    const __half* gq = qg + base + (size_t)(qt * 128) * 64;
#pragma unroll
    for (int i = 0; i < 4; i++) {
      int f = tid + i * 256;
      int r = f >> 3, c8 = f & 7;
      CP_ASYNC16(sb + A_oQ + (uint32_t)(r * APB + c8 * 16), gq + r * 64 + c8 * 8);
    }
    CP_COMMIT();
  }

#define ATTN_KV_LOADS(stg, ktv)                                              \
  {                                                                          \
    int kt_ = (ktv);                                                         \
    uint32_t d0 = sb + A_oKV + (stg) * 18432;                                \
    _Pragma("unroll") for (int i = 0; i < 2; i++) {                          \
      int f = tid + i * 256;                                                 \
      int r = f >> 3, c8 = f & 7;                                            \
      uint32_t so = (uint32_t)(r * APB + c8 * 16);                           \
      size_t go = base + (size_t)(kt_ * 64 + r) * 64 + c8 * 8;               \
      CP_ASYNC16(d0 + so, kg_ + go);                                         \
      CP_ASYNC16(d0 + 9216 + so, vg + go);                                   \
    }                                                                        \
    CP_COMMIT();                                                             \
  }

  ATTN_KV_LOADS(0, 0);
  ATTN_KV_LOADS(1, 1);

  float oacc[8][4];
#pragma unroll
  for (int j = 0; j < 8; j++)
#pragma unroll
    for (int t = 0; t < 4; t++) oacc[j][t] = 0.f;
  float m_lo = -INFINITY, m_hi = -INFINITY, l_lo = 0.f, l_hi = 0.f;

  uint32_t qbase = sb + A_oQ + (uint32_t)((wid * 16 + lrow) * APB + lc8 * 2);
  uint32_t aq[4][4];   // Q fragments, hoisted (loop-invariant)

  for (int kt = 0; kt < 32; kt++) {
    if (kt + 1 < 32) { CP_WAIT1(); } else { CP_WAIT0(); }
    __syncthreads();
    if (kt + 2 < 32) ATTN_KV_LOADS((kt + 2) % 3, kt + 2);
    if (kt == 0) {
#pragma unroll
      for (int ks = 0; ks < 4; ks++)
        LDSM_X4(aq[ks][0], aq[ks][1], aq[ks][2], aq[ks][3], qbase + ks * 32);
    }

    uint32_t sK = sb + A_oKV + (kt % 3) * 18432;
    uint32_t sV = sK + 9216;

    // ---- S = Q' K^T (q pre-scaled) ----
    float sacc[8][4];
#pragma unroll
    for (int j = 0; j < 8; j++)
#pragma unroll
      for (int t = 0; t < 4; t++) sacc[j][t] = 0.f;
#pragma unroll
    for (int ks = 0; ks < 4; ks++) {
#pragma unroll
      for (int g = 0; g < 4; g++) {
        uint32_t kb[4];
        uint32_t koff = (uint32_t)((g * 16 + lrow) * APB + (ks * 16 + lc8) * 2);
        LDSM_X4(kb[0], kb[1], kb[2], kb[3], sK + koff);
        MMA16816(sacc[g * 2 + 0], aq[ks][0], aq[ks][1], aq[ks][2], aq[ks][3],
                 kb[0], kb[2]);
        MMA16816(sacc[g * 2 + 1], aq[ks][0], aq[ks][1], aq[ks][2], aq[ks][3],
                 kb[1], kb[3]);
      }
    }

    // ---- register softmax (rows erow, erow+8; log2 domain) ----
    float mx0 = -INFINITY, mx1 = -INFINITY;
#pragma unroll
    for (int j = 0; j < 8; j++) {
      mx0 = fmaxf(mx0, fmaxf(sacc[j][0], sacc[j][1]));
      mx1 = fmaxf(mx1, fmaxf(sacc[j][2], sacc[j][3]));
    }
    mx0 = fmaxf(mx0, __shfl_xor_sync(0xffffffff, mx0, 1));
    mx0 = fmaxf(mx0, __shfl_xor_sync(0xffffffff, mx0, 2));
    mx1 = fmaxf(mx1, __shfl_xor_sync(0xffffffff, mx1, 1));
    mx1 = fmaxf(mx1, __shfl_xor_sync(0xffffffff, mx1, 2));
    float nm0 = fmaxf(m_lo, mx0), nm1 = fmaxf(m_hi, mx1);
    float cf0 = exp2f(m_lo - nm0), cf1 = exp2f(m_hi - nm1);
    m_lo = nm0; m_hi = nm1;

    uint32_t pa[4][4];
    float s0 = 0.f, s1 = 0.f;
#pragma unroll
    for (int g = 0; g < 4; g++) {
#pragma unroll
      for (int hb = 0; hb < 2; hb++) {
        int j = g * 2 + hb;
        float p00 = exp2f(sacc[j][0] - nm0);
        float p01 = exp2f(sacc[j][1] - nm0);
        float p10 = exp2f(sacc[j][2] - nm1);
        float p11 = exp2f(sacc[j][3] - nm1);
        s0 += p00 + p01;
        s1 += p10 + p11;
        __half2 plo = __floats2half2_rn(p00, p01);
        __half2 phi = __floats2half2_rn(p10, p11);
        pa[g][hb * 2 + 0] = *(uint32_t*)&plo;
        pa[g][hb * 2 + 1] = *(uint32_t*)&phi;
      }
    }
    s0 += __shfl_xor_sync(0xffffffff, s0, 1);
    s0 += __shfl_xor_sync(0xffffffff, s0, 2);
    s1 += __shfl_xor_sync(0xffffffff, s1, 1);
    s1 += __shfl_xor_sync(0xffffffff, s1, 2);
    l_lo = l_lo * cf0 + s0;
    l_hi = l_hi * cf1 + s1;

    // ---- O = O*c + P V ----
#pragma unroll
    for (int j = 0; j < 8; j++) {
      oacc[j][0] *= cf0; oacc[j][1] *= cf0;
      oacc[j][2] *= cf1; oacc[j][3] *= cf1;
    }
#pragma unroll
    for (int g = 0; g < 4; g++) {
#pragma unroll
      for (int db = 0; db < 4; db++) {
        uint32_t vb[4];
        uint32_t voff = (uint32_t)((g * 16 + lrow) * APB + (db * 16 + lc8) * 2);
        LDSM_X4_T(vb[0], vb[1], vb[2], vb[3], sV + voff);
        MMA16816(oacc[db * 2 + 0], pa[g][0], pa[g][1], pa[g][2], pa[g][3],
                 vb[0], vb[1]);
        MMA16816(oacc[db * 2 + 1], pa[g][0], pa[g][1], pa[g][2], pa[g][3],
                 vb[2], vb[3]);
      }
    }
  }

  // ---- output: O / l -> fp16 at [B,N,C] ----
  int b = bh >> 4, h = bh & 15;
  float il0 = 1.f / l_lo, il1 = 1.f / l_hi;
  int qrow = qt * 128 + wid * 16 + erow;
  size_t rbase0 = ((size_t)(b * 2048 + qrow)) * 1024 + h * 64;
  size_t rbase1 = rbase0 + 8 * 1024;
#pragma unroll
  for (int db = 0; db < 4; db++) {
#pragma unroll
    for (int nb = 0; nb < 2; nb++) {
      int j = db * 2 + nb;
      int d = db * 16 + nb * 8 + ecol;
      *(__half2*)(og + rbase0 + d) = __floats2half2_rn(oacc[j][0] * il0,
                                                       oacc[j][1] * il0);
      *(__half2*)(og + rbase1 + d) = __floats2half2_rn(oacc[j][2] * il1,
                                                       oacc[j][3] * il1);
    }
  }
}

// ================= launch =================
extern "C" void kernel_launch(void* const* d_in, const int* in_sizes, int n_in,
                              void* d_out, int out_size) {
  const float* x = (const float*)d_in[0];
  const float* ln1_g = (const float*)d_in[1];
  const float* ln1_b = (const float*)d_in[2];
  const float* qkv_w = (const float*)d_in[3];
  const float* qkv_b = (const float*)d_in[4];
  const float* proj_w = (const float*)d_in[5];
  const float* proj_b = (const float*)d_in[6];
  const float* ln2_g = (const float*)d_in[7];
  const float* ln2_b = (const float*)d_in[8];
  const float* fc1_w = (const float*)d_in[9];
  const float* fc1_b = (const float*)d_in[10];
  const float* ffln_g = (const float*)d_in[11];
  const float* ffln_b = (const float*)d_in[12];
  const float* fc2_w = (const float*)d_in[13];
  const float* fc2_b = (const float*)d_in[14];
  float* out = (float*)d_out;

  __half *x1h, *h1h, *ah, *att, *q, *k, *v;
  __half *wq, *wp, *w1, *w2;
  cudaGetSymbolAddress((void**)&x1h, g_x1h);
  cudaGetSymbolAddress((void**)&h1h, g_h1h);
  cudaGetSymbolAddress((void**)&ah, g_ah);
  cudaGetSymbolAddress((void**)&att, g_att);
  cudaGetSymbolAddress((void**)&q, g_q2);
  cudaGetSymbolAddress((void**)&k, g_k2);
  cudaGetSymbolAddress((void**)&v, g_v2);
  cudaGetSymbolAddress((void**)&wq, g_wq);
  cudaGetSymbolAddress((void**)&wp, g_wp);
  cudaGetSymbolAddress((void**)&w1, g_w1);
  cudaGetSymbolAddress((void**)&w2, g_w2);

  cudaFuncSetAttribute(gemm_mma<0>, cudaFuncAttributeMaxDynamicSharedMemorySize, GEMM_SMEM);
  cudaFuncSetAttribute(gemm_mma<1>, cudaFuncAttributeMaxDynamicSharedMemorySize, GEMM_SMEM);
  cudaFuncSetAttribute(gemm_mma<3>, cudaFuncAttributeMaxDynamicSharedMemorySize, GEMM_SMEM);
  cudaFuncSetAttribute(gemm_mma<4>, cudaFuncAttributeMaxDynamicSharedMemorySize, GEMM_SMEM);
  cudaFuncSetAttribute(gemm_mma<5>, cudaFuncAttributeMaxDynamicSharedMemorySize, GEMM_SMEM);
  cudaFuncSetAttribute(attn_mma, cudaFuncAttributeMaxDynamicSharedMemorySize, ATTN_SMEM);

  wconv_kernel<<<dim3(3072 / 32, 1024 / 32), 256>>>(qkv_w, wq, 1024, 3072);
  wconv_kernel<<<dim3(1024 / 32, 1024 / 32), 256>>>(proj_w, wp, 1024, 1024);
  wconv_kernel<<<dim3(4096 / 32, 1024 / 32), 256>>>(fc1_w, w1, 1024, 4096);
  wconv_kernel<<<dim3(1024 / 32, 4096 / 32), 256>>>(fc2_w, w2, 4096, 1024);

  // 1) LN1 -> fp16
  ln_h_kernel<<<ROWS, 256>>>(x, ln1_g, ln1_b, ah);
  // 2) QKV GEMM + RoPE + scale + split write (EPI 3)
  gemm_mma<3><<<dim3(3072 / 128, ROWS / 128), 256, GEMM_SMEM>>>(
      ah, wq, qkv_b, nullptr, nullptr, nullptr, 1024, 3072, q, k, v);
  // 3) attention (FA2 register softmax, Q hoisted)
  attn_mma<<<dim3(NNq / 128, BB * HHn), 256, ATTN_SMEM>>>(q, k, v, att);
  // 4) proj + residual(x fp32) -> x1h (fp16, EPI 4)
  gemm_mma<4><<<dim3(1024 / 128, ROWS / 128), 256, GEMM_SMEM>>>(
      att, wp, proj_b, x, nullptr, nullptr, 1024, 1024, x1h, nullptr, nullptr);
  // 5) LN2 (fp16 in) -> fp16
  ln_h16_kernel<<<ROWS, 256>>>(x1h, ln2_g, ln2_b, ah);
  // 6) fc1 + GELU -> fp16 h1h (EPI 1)
  gemm_mma<1><<<dim3(4096 / 128, ROWS / 128), 256, GEMM_SMEM>>>(
      ah, w1, fc1_b, nullptr, nullptr, nullptr, 1024, 4096, h1h, nullptr, nullptr);
  // 7) ffn LN (fp16 in, 4096 wide) -> fp16
  ln_h_in_kernel<<<ROWS, 256>>>(h1h, ffln_g, ffln_b, ah);
  // 8) fc2 + residual(x1h fp16) -> out fp32 (EPI 5)
  gemm_mma<5><<<dim3(1024 / 128, ROWS / 128), 256, GEMM_SMEM>>>(
      ah, w2, fc2_b, nullptr, x1h, out, 4096, 1024, nullptr, nullptr, nullptr);
}

// round 12
// speedup vs baseline: 2.9562x; 1.0058x over previous
#include <cuda_runtime.h>
#include <cuda_fp16.h>
#include <math.h>
#include <stdint.h>

#define BB 2
#define NNq 2048
#define CCd 1024
#define HHn 16
#define HIDd 4096
#define ROWS (BB * NNq)   // 4096

// ================= scratch (device globals) =================
__device__ __half g_x1h[ROWS * CCd];           // x + proj(attn), fp16
__device__ __half g_h1h[ROWS * HIDd];          // fc1+gelu out (fp16)
__device__ __half g_ah[ROWS * HIDd];           // activations (fp16)
__device__ __half g_att[ROWS * CCd];           // attention out
__device__ __half g_q2[ROWS * CCd];            // q [B,H,N,D] (RoPE+scale)
__device__ __half g_k2[ROWS * CCd];            // k
__device__ __half g_v2[ROWS * CCd];            // v
__device__ __half g_wq[3072 * 1024];
__device__ __half g_wp[1024 * 1024];
__device__ __half g_w1[4096 * 1024];
__device__ __half g_w2[1024 * 4096];

// ================= helpers =================
__device__ __forceinline__ uint32_t smem_u32(const void* p) {
  uint32_t a;
  asm("{ .reg .u64 t; cvta.to.shared.u64 t, %1; cvt.u32.u64 %0, t; }"
      : "=r"(a) : "l"(p));
  return a;
}

#define CP_ASYNC16(sm, gp) \
  asm volatile("cp.async.cg.shared.global [%0], [%1], 16;" \
               :: "r"(sm), "l"(gp) : "memory")
#define CP_COMMIT() asm volatile("cp.async.commit_group;" ::: "memory")
#define CP_WAIT0() asm volatile("cp.async.wait_group 0;" ::: "memory")
#define CP_WAIT1() asm volatile("cp.async.wait_group 1;" ::: "memory")

#define LDSM_X4(r0, r1, r2, r3, a) \
  asm volatile("ldmatrix.sync.aligned.m8n8.x4.shared.b16 {%0,%1,%2,%3}, [%4];" \
               : "=r"(r0), "=r"(r1), "=r"(r2), "=r"(r3) : "r"(a))
#define LDSM_X4_T(r0, r1, r2, r3, a) \
  asm volatile("ldmatrix.sync.aligned.m8n8.x4.trans.shared.b16 {%0,%1,%2,%3}, [%4];" \
               : "=r"(r0), "=r"(r1), "=r"(r2), "=r"(r3) : "r"(a))

#define MMA16816(d, a0, a1, a2, a3, b0, b1) \
  asm volatile("mma.sync.aligned.m16n8k16.row.col.f32.f16.f16.f32 " \
               "{%0,%1,%2,%3}, {%4,%5,%6,%7}, {%8,%9}, {%0,%1,%2,%3};" \
               : "+f"((d)[0]), "+f"((d)[1]), "+f"((d)[2]), "+f"((d)[3]) \
               : "r"(a0), "r"(a1), "r"(a2), "r"(a3), "r"(b0), "r"(b1))

__device__ __forceinline__ float gelu_f(float v) {
  return 0.5f * v * (1.f + erff(v * 0.70710678118654752f));
}

// ================= weight convert + transpose (fp32 [K,N] -> fp16 [N,K]) ===
__global__ __launch_bounds__(256) void wconv_kernel(
    const float* __restrict__ W, __half* __restrict__ th, int K, int N) {
  __shared__ float t[32][33];
  int n0 = blockIdx.x * 32, k0 = blockIdx.y * 32;
  int tx = threadIdx.x & 31, ty = threadIdx.x >> 5;
#pragma unroll
  for (int i = 0; i < 4; i++)
    t[ty + i * 8][tx] = W[(size_t)(k0 + ty + i * 8) * N + n0 + tx];
  __syncthreads();
#pragma unroll
  for (int i = 0; i < 4; i++) {
    float v = t[tx][ty + i * 8];
    th[(size_t)(n0 + ty + i * 8) * K + k0 + tx] = __float2half_rn(v);
  }
}

// ================= LayerNorm (fp32 in, 1024) -> fp16 =================
__global__ __launch_bounds__(256) void ln_h_kernel(
    const float* __restrict__ in, const float* __restrict__ gw,
    const float* __restrict__ bw, __half* __restrict__ oh) {
  const int cols = 1024;
  int row = blockIdx.x;
  const float* rp = in + (size_t)row * cols;
  int c = threadIdx.x * 4;
  float4 v = *(const float4*)(rp + c);
  float s = v.x + v.y + v.z + v.w;
  float sq = v.x * v.x + v.y * v.y + v.z * v.z + v.w * v.w;
  __shared__ float red0[8], red1[8];
#pragma unroll
  for (int o = 16; o; o >>= 1) {
    s += __shfl_xor_sync(0xffffffff, s, o);
    sq += __shfl_xor_sync(0xffffffff, sq, o);
  }
  int warp = threadIdx.x >> 5, lane = threadIdx.x & 31;
  if (lane == 0) { red0[warp] = s; red1[warp] = sq; }
  __syncthreads();
  __shared__ float s_mu, s_ri;
  if (threadIdx.x == 0) {
    float ts = 0.f, tq = 0.f;
#pragma unroll
    for (int i = 0; i < 8; i++) { ts += red0[i]; tq += red1[i]; }
    float mu = ts / (float)cols;
    float var = tq / (float)cols - mu * mu;
    s_mu = mu;
    s_ri = rsqrtf(var + 1e-5f);
  }
  __syncthreads();
  float mu = s_mu, ri = s_ri;
  float4 g4 = *(const float4*)(gw + c);
  float4 b4 = *(const float4*)(bw + c);
  __half2 h01, h23;
  h01.x = __float2half_rn((v.x - mu) * ri * g4.x + b4.x);
  h01.y = __float2half_rn((v.y - mu) * ri * g4.y + b4.y);
  h23.x = __float2half_rn((v.z - mu) * ri * g4.z + b4.z);
  h23.y = __float2half_rn((v.w - mu) * ri * g4.w + b4.w);
  size_t o = (size_t)row * cols + c;
  *(__half2*)(oh + o) = h01;
  *(__half2*)(oh + o + 2) = h23;
}

// ================= LayerNorm (fp16 in, 1024) -> fp16 =================
__global__ __launch_bounds__(256) void ln_h16_kernel(
    const __half* __restrict__ in, const float* __restrict__ gw,
    const float* __restrict__ bw, __half* __restrict__ oh) {
  const int cols = 1024;
  int row = blockIdx.x;
  const __half* rp = in + (size_t)row * cols;
  int c = threadIdx.x * 4;
  __half2 raw0 = *(const __half2*)(rp + c);
  __half2 raw1 = *(const __half2*)(rp + c + 2);
  float2 f0 = __half22float2(raw0), f1 = __half22float2(raw1);
  float s = f0.x + f0.y + f1.x + f1.y;
  float sq = f0.x * f0.x + f0.y * f0.y + f1.x * f1.x + f1.y * f1.y;
  __shared__ float red0[8], red1[8];
#pragma unroll
  for (int o = 16; o; o >>= 1) {
    s += __shfl_xor_sync(0xffffffff, s, o);
    sq += __shfl_xor_sync(0xffffffff, sq, o);
  }
  int warp = threadIdx.x >> 5, lane = threadIdx.x & 31;
  if (lane == 0) { red0[warp] = s; red1[warp] = sq; }
  __syncthreads();
  __shared__ float s_mu, s_ri;
  if (threadIdx.x == 0) {
    float ts = 0.f, tq = 0.f;
#pragma unroll
    for (int i = 0; i < 8; i++) { ts += red0[i]; tq += red1[i]; }
    float mu = ts / (float)cols;
    float var = tq / (float)cols - mu * mu;
    s_mu = mu;
    s_ri = rsqrtf(var + 1e-5f);
  }
  __syncthreads();
  float mu = s_mu, ri = s_ri;
  float4 g4 = *(const float4*)(gw + c);
  float4 b4 = *(const float4*)(bw + c);
  __half2 h01, h23;
  h01 = __floats2half2_rn((f0.x - mu) * ri * g4.x + b4.x,
                          (f0.y - mu) * ri * g4.y + b4.y);
  h23 = __floats2half2_rn((f1.x - mu) * ri * g4.z + b4.z,
                          (f1.y - mu) * ri * g4.w + b4.w);
  size_t o = (size_t)row * cols + c;
  *(__half2*)(oh + o) = h01;
  *(__half2*)(oh + o + 2) = h23;
}

// ================= LayerNorm (fp16 in, 4096 wide) -> fp16 =================
__global__ __launch_bounds__(256) void ln_h_in_kernel(
    const __half* __restrict__ in, const float* __restrict__ gw,
    const float* __restrict__ bw, __half* __restrict__ oh) {
  const int cols = 4096;
  int row = blockIdx.x;
  const __half* rp = in + (size_t)row * cols;
  float vals[16];
  float s = 0.f, sq = 0.f;
#pragma unroll
  for (int it = 0; it < 2; it++) {
    int c = (it * 256 + threadIdx.x) * 8;
    uint4 raw = *(const uint4*)(rp + c);
    const __half2* h2 = (const __half2*)&raw;
#pragma unroll
    for (int j = 0; j < 4; j++) {
      float2 f = __half22float2(h2[j]);
      vals[it * 8 + j * 2] = f.x;
      vals[it * 8 + j * 2 + 1] = f.y;
      s += f.x + f.y;
      sq += f.x * f.x + f.y * f.y;
    }
  }
  __shared__ float red0[8], red1[8];
#pragma unroll
  for (int o = 16; o; o >>= 1) {
    s += __shfl_xor_sync(0xffffffff, s, o);
    sq += __shfl_xor_sync(0xffffffff, sq, o);
  }
  int warp = threadIdx.x >> 5, lane = threadIdx.x & 31;
  if (lane == 0) { red0[warp] = s; red1[warp] = sq; }
  __syncthreads();
  __shared__ float s_mu, s_ri;
  if (threadIdx.x == 0) {
    float ts = 0.f, tq = 0.f;
#pragma unroll
    for (int i = 0; i < 8; i++) { ts += red0[i]; tq += red1[i]; }
    float mu = ts / (float)cols;
    float var = tq / (float)cols - mu * mu;
    s_mu = mu;
    s_ri = rsqrtf(var + 1e-5f);
  }
  __syncthreads();
  float mu = s_mu, ri = s_ri;
#pragma unroll
  for (int it = 0; it < 2; it++) {
    int c = (it * 256 + threadIdx.x) * 8;
    uint4 outw;
    __half2* oh2 = (__half2*)&outw;
#pragma unroll
    for (int j = 0; j < 4; j++) {
      float2 g2 = *(const float2*)(gw + c + j * 2);
      float2 b2 = *(const float2*)(bw + c + j * 2);
      float o0 = (vals[it * 8 + j * 2] - mu) * ri * g2.x + b2.x;
      float o1 = (vals[it * 8 + j * 2 + 1] - mu) * ri * g2.y + b2.y;
      oh2[j] = __floats2half2_rn(o0, o1);
    }
    *(uint4*)(oh + (size_t)row * cols + c) = outw;
  }
}

// ================= mma.sync fp16 GEMM (BK=64, 3-stage, frag pipelined) ====
// C = A[M,K] @ B^T + bias, B stored [N,K]. Tile 128x128x64, 8 warps (2m x 4n),
// warp 64x32. A/B ldmatrix fragments double-buffered in registers so every
// LDSM is issued one iteration ahead of its consuming MMAs.
#define GPITCH 144                  // bytes per row (72 halves)
#define TILE_H (128 * GPITCH)       // 18432
#define STAGE_H (2 * TILE_H)        // 36864
#define GEMM_SMEM (3 * STAGE_H)     // 110592
#define QSCALE 0.1803368801111244f  // 0.125 * log2(e)

template <int EPI>
__global__ __launch_bounds__(256, 2) void gemm_mma(
    const __half* __restrict__ Ah, const __half* __restrict__ Bh,
    const float* __restrict__ bias, const float* __restrict__ res,
    const __half* __restrict__ resh,
    float* __restrict__ C, int K, int N,
    __half* hout, __half* k_, __half* v_) {
  extern __shared__ char smem[];
  uint32_t sb = smem_u32(smem);
  int tid = threadIdx.x, wid = tid >> 5, lane = tid & 31;
  int m0 = blockIdx.y * 128, n0 = blockIdx.x * 128;
  int wm = wid & 1, wn = wid >> 1;
  int lrow = lane & 15, lc8 = (lane >> 4) * 8;

  float acc[4][4][4];
#pragma unroll
  for (int i = 0; i < 4; i++)
#pragma unroll
    for (int j = 0; j < 4; j++)
#pragma unroll
      for (int t = 0; t < 4; t++) acc[i][j][t] = 0.f;

  int NCH = K >> 6;

  // 128 rows x 8 chunks(16B) per operand; 256 threads x 4 iters covers 1024.
#define GEMM_LOADS(stgbase, ktv)                                             \
  {                                                                          \
    uint32_t stg = (stgbase);                                                \
    int kt = (ktv);                                                          \
    _Pragma("unroll") for (int i = 0; i < 4; i++) {                          \
      int c = tid + i * 256;                                                 \
      int r = c >> 3, q = c & 7;                                             \
      uint32_t so = (uint32_t)(r * GPITCH + q * 16);                         \
      CP_ASYNC16(stg + so, Ah + (size_t)(m0 + r) * K + kt + q * 8);          \
      CP_ASYNC16(stg + TILE_H + so, Bh + (size_t)(n0 + r) * K + kt + q * 8); \
    }                                                                        \
    CP_COMMIT();                                                             \
  }

  GEMM_LOADS(sb, 0);
  GEMM_LOADS(sb + STAGE_H, 64);

  // per-warp base smem offsets (k offset added per step)
  uint32_t aRow = (uint32_t)((wm * 64 + lrow) * GPITCH + lc8 * 2);
  uint32_t bRow0 = (uint32_t)((wn * 32 + lrow) * GPITCH + lc8 * 2);
  uint32_t bRow1 = (uint32_t)((wn * 32 + 16 + lrow) * GPITCH + lc8 * 2);

#define LOADB(dst, stB_, ksv)                                                \
  {                                                                          \
    LDSM_X4((dst)[0], (dst)[1], (dst)[2], (dst)[3], (stB_) + bRow0 + (ksv) * 2); \
    LDSM_X4((dst)[4], (dst)[5], (dst)[6], (dst)[7], (stB_) + bRow1 + (ksv) * 2); \
  }
#define LOADA(dst, stA_, ksv, mbv)                                           \
  LDSM_X4((dst)[0], (dst)[1], (dst)[2], (dst)[3],                            \
          (stA_) + aRow + (uint32_t)((mbv) * 16 * GPITCH + (ksv) * 2))

  for (int kc = 0; kc < NCH; kc++) {
    if (kc + 1 < NCH) { CP_WAIT1(); } else { CP_WAIT0(); }
    __syncthreads();
    if (kc + 2 < NCH) GEMM_LOADS(sb + ((kc + 2) % 3) * STAGE_H, (kc + 2) * 64);

    uint32_t stA = sb + (kc % 3) * STAGE_H;
    uint32_t stB = stA + TILE_H;

    uint32_t bf2[2][8], af2[2][4];
    LOADB(bf2[0], stB, 0);
    LOADA(af2[0], stA, 0, 0);

#pragma unroll
    for (int ks4 = 0; ks4 < 4; ks4++) {
      int ks = ks4 * 16;
      if (ks4 < 3) LOADB(bf2[(ks4 + 1) & 1], stB, ks + 16);
#pragma unroll
      for (int mb = 0; mb < 4; mb++) {
        int cur = (ks4 * 4 + mb) & 1;
        if (mb < 3) {
          LOADA(af2[cur ^ 1], stA, ks, mb + 1);
        } else if (ks4 < 3) {
          LOADA(af2[cur ^ 1], stA, ks + 16, 0);
        }
        uint32_t* ah = af2[cur];
        uint32_t* bhf = bf2[ks4 & 1];
#pragma unroll
        for (int nb = 0; nb < 4; nb++) {
          int pi = (nb >> 1) * 4, od = nb & 1;
          MMA16816(acc[mb][nb], ah[0], ah[1], ah[2], ah[3],
                   bhf[pi + od], bhf[pi + 2 + od]);
        }
      }
    }
  }

  int erow = lane >> 2, ecol = (lane & 3) * 2;
#pragma unroll
  for (int mb = 0; mb < 4; mb++) {
#pragma unroll
    for (int nb = 0; nb < 4; nb++) {
      float* d = acc[mb][nb];
      int gr = m0 + wm * 64 + mb * 16 + erow;
      int gc = n0 + wn * 32 + nb * 8 + ecol;
      float2 b2 = *(const float2*)(bias + gc);
      float v0 = d[0] + b2.x, v1 = d[1] + b2.y;
      float v2 = d[2] + b2.x, v3 = d[3] + b2.y;
      if (EPI == 1) {
        v0 = gelu_f(v0); v1 = gelu_f(v1);
        v2 = gelu_f(v2); v3 = gelu_f(v3);
        *(__half2*)(hout + (size_t)gr * N + gc) = __floats2half2_rn(v0, v1);
        *(__half2*)(hout + (size_t)(gr + 8) * N + gc) = __floats2half2_rn(v2, v3);
      } else if (EPI == 3) {
        int region = gc >> 10;           // 0 q, 1 k, 2 v
        int hh = (gc & 1023) >> 6;
        int dd = gc & 63;
        int b = gr >> 11;
        int n = gr & 2047;
        if (region < 2) {
          float inv = 1.0f / powf(10000.0f, (float)(dd & ~1) / 64.0f);
          float c0, s0, c1, s1;
          sincosf((float)n * inv, &s0, &c0);
          sincosf((float)(n + 8) * inv, &s1, &c1);
          float r0 = v0 * c0 - v1 * s0, r1 = v1 * c0 + v0 * s0;
          float r2 = v2 * c1 - v3 * s1, r3 = v3 * c1 + v2 * s1;
          v0 = r0; v1 = r1; v2 = r2; v3 = r3;
          if (region == 0) { v0 *= QSCALE; v1 *= QSCALE; v2 *= QSCALE; v3 *= QSCALE; }
        }
        __half* dst = (region == 0) ? hout : (region == 1) ? k_ : v_;
        size_t o0 = ((size_t)((b * 16 + hh) * 2048 + n)) * 64 + dd;
        size_t o1 = o0 + 8 * 64;
        *(__half2*)(dst + o0) = __floats2half2_rn(v0, v1);
        *(__half2*)(dst + o1) = __floats2half2_rn(v2, v3);
      } else if (EPI == 4) {
        float2 r0 = *(const float2*)(res + (size_t)gr * N + gc);
        float2 r1 = *(const float2*)(res + (size_t)(gr + 8) * N + gc);
        v0 += r0.x; v1 += r0.y; v2 += r1.x; v3 += r1.y;
        *(__half2*)(hout + (size_t)gr * N + gc) = __floats2half2_rn(v0, v1);
        *(__half2*)(hout + (size_t)(gr + 8) * N + gc) = __floats2half2_rn(v2, v3);
      } else if (EPI == 5) {
        __half2 r0 = *(const __half2*)(resh + (size_t)gr * N + gc);
        __half2 r1 = *(const __half2*)(resh + (size_t)(gr + 8) * N + gc);
        float2 f0 = __half22float2(r0), f1 = __half22float2(r1);
        v0 += f0.x; v1 += f0.y; v2 += f1.x; v3 += f1.y;
        float2 o0 = {v0, v1}, o1 = {v2, v3};
        *(float2*)(C + (size_t)gr * N + gc) = o0;
        *(float2*)(C + (size_t)(gr + 8) * N + gc) = o1;
      } else {
        float2 o0 = {v0, v1}, o1 = {v2, v3};
        *(float2*)(C + (size_t)gr * N + gc) = o0;
        *(float2*)(C + (size_t)(gr + 8) * N + gc) = o1;
      }
    }
  }
}

// ================= FA2 flash attention (register softmax, Q hoisted) ======
#define APB 144   // bytes per smem row (72 fp16)
#define A_oQ 0                  // 128 * 144 = 18432
#define A_oKV 18432             // 3 stages x (K 9216 + V 9216)
#define ATTN_SMEM (18432 + 3 * 18432)   // 73728

__global__ __launch_bounds__(256, 2) void attn_mma(
    const __half* __restrict__ qg, const __half* __restrict__ kg_,
    const __half* __restrict__ vg, __half* __restrict__ og) {
  extern __shared__ char sm[];
  uint32_t sb = smem_u32(sm);

  int tid = threadIdx.x, wid = tid >> 5, lane = tid & 31;
  int lrow = lane & 15, lc8 = (lane >> 4) * 8;
  int erow = lane >> 2, ecol = (lane & 3) * 2;
  int bh = blockIdx.y, qt = blockIdx.x;
  size_t base = (size_t)bh * (2048 * 64);

  // Q tile (128 rows) — first commit group
  {
    const __half* gq = qg + base + (size_t)(qt * 128) * 64;
#pragma unroll
    for (int i = 0; i < 4; i++) {
      int f = tid + i * 256;
      int r = f >> 3, c8 = f & 7;
      CP_ASYNC16(sb + A_oQ + (uint32_t)(r * APB + c8 * 16), gq + r * 64 + c8 * 8);
    }
    CP_COMMIT();
  }

#define ATTN_KV_LOADS(stg, ktv)                                              \
  {                                                                          \
    int kt_ = (ktv);                                                         \
    uint32_t d0 = sb + A_oKV + (stg) * 18432;                                \
    _Pragma("unroll") for (int i = 0; i < 2; i++) {                          \
      int f = tid + i * 256;                                                 \
      int r = f >> 3, c8 = f & 7;                                            \
      uint32_t so = (uint32_t)(r * APB + c8 * 16);                           \
      size_t go = base + (size_t)(kt_ * 64 + r) * 64 + c8 * 8;               \
      CP_ASYNC16(d0 + so, kg_ + go);                                         \
      CP_ASYNC16(d0 + 9216 + so, vg + go);                                   \
    }                                                                        \
    CP_COMMIT();                                                             \
  }

  ATTN_KV_LOADS(0, 0);
  ATTN_KV_LOADS(1, 1);

  float oacc[8][4];
#pragma unroll
  for (int j = 0; j < 8; j++)
#pragma unroll
    for (int t = 0; t < 4; t++) oacc[j][t] = 0.f;
  float m_lo = -INFINITY, m_hi = -INFINITY, l_lo = 0.f, l_hi = 0.f;

  uint32_t qbase = sb + A_oQ + (uint32_t)((wid * 16 + lrow) * APB + lc8 * 2);
  uint32_t aq[4][4];   // Q fragments, hoisted (loop-invariant)

  for (int kt = 0; kt < 32; kt++) {
    if (kt + 1 < 32) { CP_WAIT1(); } else { CP_WAIT0(); }
    __syncthreads();
    if (kt + 2 < 32) ATTN_KV_LOADS((kt + 2) % 3, kt + 2);
    if (kt == 0) {
#pragma unroll
      for (int ks = 0; ks < 4; ks++)
        LDSM_X4(aq[ks][0], aq[ks][1], aq[ks][2], aq[ks][3], qbase + ks * 32);
    }

    uint32_t sK = sb + A_oKV + (kt % 3) * 18432;
    uint32_t sV = sK + 9216;

    // ---- S = Q' K^T (q pre-scaled) ----
    float sacc[8][4];
#pragma unroll
    for (int j = 0; j < 8; j++)
#pragma unroll
      for (int t = 0; t < 4; t++) sacc[j][t] = 0.f;
#pragma unroll
    for (int ks = 0; ks < 4; ks++) {
#pragma unroll
      for (int g = 0; g < 4; g++) {
        uint32_t kb[4];
        uint32_t koff = (uint32_t)((g * 16 + lrow) * APB + (ks * 16 + lc8) * 2);
        LDSM_X4(kb[0], kb[1], kb[2], kb[3], sK + koff);
        MMA16816(sacc[g * 2 + 0], aq[ks][0], aq[ks][1], aq[ks][2], aq[ks][3],
                 kb[0], kb[2]);
        MMA16816(sacc[g * 2 + 1], aq[ks][0], aq[ks][1], aq[ks][2], aq[ks][3],
                 kb[1], kb[3]);
      }
    }

    // ---- register softmax (rows erow, erow+8; log2 domain) ----
    float mx0 = -INFINITY, mx1 = -INFINITY;
#pragma unroll
    for (int j = 0; j < 8; j++) {
      mx0 = fmaxf(mx0, fmaxf(sacc[j][0], sacc[j][1]));
      mx1 = fmaxf(mx1, fmaxf(sacc[j][2], sacc[j][3]));
    }
    mx0 = fmaxf(mx0, __shfl_xor_sync(0xffffffff, mx0, 1));
    mx0 = fmaxf(mx0, __shfl_xor_sync(0xffffffff, mx0, 2));
    mx1 = fmaxf(mx1, __shfl_xor_sync(0xffffffff, mx1, 1));
    mx1 = fmaxf(mx1, __shfl_xor_sync(0xffffffff, mx1, 2));
    float nm0 = fmaxf(m_lo, mx0), nm1 = fmaxf(m_hi, mx1);
    float cf0 = exp2f(m_lo - nm0), cf1 = exp2f(m_hi - nm1);
    m_lo = nm0; m_hi = nm1;

    uint32_t pa[4][4];
    float s0 = 0.f, s1 = 0.f;
#pragma unroll
    for (int g = 0; g < 4; g++) {
#pragma unroll
      for (int hb = 0; hb < 2; hb++) {
        int j = g * 2 + hb;
        float p00 = exp2f(sacc[j][0] - nm0);
        float p01 = exp2f(sacc[j][1] - nm0);
        float p10 = exp2f(sacc[j][2] - nm1);
        float p11 = exp2f(sacc[j][3] - nm1);
        s0 += p00 + p01;
        s1 += p10 + p11;
        __half2 plo = __floats2half2_rn(p00, p01);
        __half2 phi = __floats2half2_rn(p10, p11);
        pa[g][hb * 2 + 0] = *(uint32_t*)&plo;
        pa[g][hb * 2 + 1] = *(uint32_t*)&phi;
      }
    }
    s0 += __shfl_xor_sync(0xffffffff, s0, 1);
    s0 += __shfl_xor_sync(0xffffffff, s0, 2);
    s1 += __shfl_xor_sync(0xffffffff, s1, 1);
    s1 += __shfl_xor_sync(0xffffffff, s1, 2);
    l_lo = l_lo * cf0 + s0;
    l_hi = l_hi * cf1 + s1;

    // ---- O = O*c + P V ----
#pragma unroll
    for (int j = 0; j < 8; j++) {
      oacc[j][0] *= cf0; oacc[j][1] *= cf0;
      oacc[j][2] *= cf1; oacc[j][3] *= cf1;
    }
#pragma unroll
    for (int g = 0; g < 4; g++) {
#pragma unroll
      for (int db = 0; db < 4; db++) {
        uint32_t vb[4];
        uint32_t voff = (uint32_t)((g * 16 + lrow) * APB + (db * 16 + lc8) * 2);
        LDSM_X4_T(vb[0], vb[1], vb[2], vb[3], sV + voff);
        MMA16816(oacc[db * 2 + 0], pa[g][0], pa[g][1], pa[g][2], pa[g][3],
                 vb[0], vb[1]);
        MMA16816(oacc[db * 2 + 1], pa[g][0], pa[g][1], pa[g][2], pa[g][3],
                 vb[2], vb[3]);
      }
    }
  }

  // ---- output: O / l -> fp16 at [B,N,C] ----
  int b = bh >> 4, h = bh & 15;
  float il0 = 1.f / l_lo, il1 = 1.f / l_hi;
  int qrow = qt * 128 + wid * 16 + erow;
  size_t rbase0 = ((size_t)(b * 2048 + qrow)) * 1024 + h * 64;
  size_t rbase1 = rbase0 + 8 * 1024;
#pragma unroll
  for (int db = 0; db < 4; db++) {
#pragma unroll
    for (int nb = 0; nb < 2; nb++) {
      int j = db * 2 + nb;
      int d = db * 16 + nb * 8 + ecol;
      *(__half2*)(og + rbase0 + d) = __floats2half2_rn(oacc[j][0] * il0,
                                                       oacc[j][1] * il0);
      *(__half2*)(og + rbase1 + d) = __floats2half2_rn(oacc[j][2] * il1,
                                                       oacc[j][3] * il1);
    }
  }
}

// ================= launch =================
extern "C" void kernel_launch(void* const* d_in, const int* in_sizes, int n_in,
                              void* d_out, int out_size) {
  const float* x = (const float*)d_in[0];
  const float* ln1_g = (const float*)d_in[1];
  const float* ln1_b = (const float*)d_in[2];
  const float* qkv_w = (const float*)d_in[3];
  const float* qkv_b = (const float*)d_in[4];
  const float* proj_w = (const float*)d_in[5];
  const float* proj_b = (const float*)d_in[6];
  const float* ln2_g = (const float*)d_in[7];
  const float* ln2_b = (const float*)d_in[8];
  const float* fc1_w = (const float*)d_in[9];
  const float* fc1_b = (const float*)d_in[10];
  const float* ffln_g = (const float*)d_in[11];
  const float* ffln_b = (const float*)d_in[12];
  const float* fc2_w = (const float*)d_in[13];
  const float* fc2_b = (const float*)d_in[14];
  float* out = (float*)d_out;

  __half *x1h, *h1h, *ah, *att, *q, *k, *v;
  __half *wq, *wp, *w1, *w2;
  cudaGetSymbolAddress((void**)&x1h, g_x1h);
  cudaGetSymbolAddress((void**)&h1h, g_h1h);
  cudaGetSymbolAddress((void**)&ah, g_ah);
  cudaGetSymbolAddress((void**)&att, g_att);
  cudaGetSymbolAddress((void**)&q, g_q2);
  cudaGetSymbolAddress((void**)&k, g_k2);
  cudaGetSymbolAddress((void**)&v, g_v2);
  cudaGetSymbolAddress((void**)&wq, g_wq);
  cudaGetSymbolAddress((void**)&wp, g_wp);
  cudaGetSymbolAddress((void**)&w1, g_w1);
  cudaGetSymbolAddress((void**)&w2, g_w2);

  cudaFuncSetAttribute(gemm_mma<0>, cudaFuncAttributeMaxDynamicSharedMemorySize, GEMM_SMEM);
  cudaFuncSetAttribute(gemm_mma<1>, cudaFuncAttributeMaxDynamicSharedMemorySize, GEMM_SMEM);
  cudaFuncSetAttribute(gemm_mma<3>, cudaFuncAttributeMaxDynamicSharedMemorySize, GEMM_SMEM);
  cudaFuncSetAttribute(gemm_mma<4>, cudaFuncAttributeMaxDynamicSharedMemorySize, GEMM_SMEM);
  cudaFuncSetAttribute(gemm_mma<5>, cudaFuncAttributeMaxDynamicSharedMemorySize, GEMM_SMEM);
  cudaFuncSetAttribute(attn_mma, cudaFuncAttributeMaxDynamicSharedMemorySize, ATTN_SMEM);

  wconv_kernel<<<dim3(3072 / 32, 1024 / 32), 256>>>(qkv_w, wq, 1024, 3072);
  wconv_kernel<<<dim3(1024 / 32, 1024 / 32), 256>>>(proj_w, wp, 1024, 1024);
  wconv_kernel<<<dim3(4096 / 32, 1024 / 32), 256>>>(fc1_w, w1, 1024, 4096);
  wconv_kernel<<<dim3(1024 / 32, 4096 / 32), 256>>>(fc2_w, w2, 4096, 1024);

  // 1) LN1 -> fp16
  ln_h_kernel<<<ROWS, 256>>>(x, ln1_g, ln1_b, ah);
  // 2) QKV GEMM + RoPE + scale + split write (EPI 3)
  gemm_mma<3><<<dim3(3072 / 128, ROWS / 128), 256, GEMM_SMEM>>>(
      ah, wq, qkv_b, nullptr, nullptr, nullptr, 1024, 3072, q, k, v);
  // 3) attention (FA2 register softmax, Q hoisted)
  attn_mma<<<dim3(NNq / 128, BB * HHn), 256, ATTN_SMEM>>>(q, k, v, att);
  // 4) proj + residual(x fp32) -> x1h (fp16, EPI 4)
  gemm_mma<4><<<dim3(1024 / 128, ROWS / 128), 256, GEMM_SMEM>>>(
      att, wp, proj_b, x, nullptr, nullptr, 1024, 1024, x1h, nullptr, nullptr);
  // 5) LN2 (fp16 in) -> fp16
  ln_h16_kernel<<<ROWS, 256>>>(x1h, ln2_g, ln2_b, ah);
  // 6) fc1 + GELU -> fp16 h1h (EPI 1)
  gemm_mma<1><<<dim3(4096 / 128, ROWS / 128), 256, GEMM_SMEM>>>(
      ah, w1, fc1_b, nullptr, nullptr, nullptr, 1024, 4096, h1h, nullptr, nullptr);
  // 7) ffn LN (fp16 in, 4096 wide) -> fp16
  ln_h_in_kernel<<<ROWS, 256>>>(h1h, ffln_g, ffln_b, ah);
  // 8) fc2 + residual(x1h fp16) -> out fp32 (EPI 5)
  gemm_mma<5><<<dim3(1024 / 128, ROWS / 128), 256, GEMM_SMEM>>>(
      ah, w2, fc2_b, nullptr, x1h, out, 4096, 1024, nullptr, nullptr, nullptr);
}

// round 13
// speedup vs baseline: 2.9873x; 1.0105x over previous
#include <cuda_runtime.h>
#include <cuda_fp16.h>
#include <math.h>
#include <stdint.h>

#define BB 2
#define NNq 2048
#define CCd 1024
#define HHn 16
#define HIDd 4096
#define ROWS (BB * NNq)   // 4096

// ================= scratch (device globals) =================
__device__ __half g_x1h[ROWS * CCd];
__device__ __half g_h1h[ROWS * HIDd];
__device__ __half g_ah[ROWS * HIDd];
__device__ __half g_att[ROWS * CCd];
__device__ __half g_q2[ROWS * CCd];
__device__ __half g_k2[ROWS * CCd];
__device__ __half g_v2[ROWS * CCd];
__device__ __half g_wq[3072 * 1024];
__device__ __half g_wp[1024 * 1024];
__device__ __half g_w1[4096 * 1024];
__device__ __half g_w2[1024 * 4096];

// ================= helpers =================
__device__ __forceinline__ uint32_t smem_u32(const void* p) {
  uint32_t a;
  asm("{ .reg .u64 t; cvta.to.shared.u64 t, %1; cvt.u32.u64 %0, t; }"
      : "=r"(a) : "l"(p));
  return a;
}

#define CP_ASYNC16(sm, gp) \
  asm volatile("cp.async.cg.shared.global [%0], [%1], 16;" \
               :: "r"(sm), "l"(gp) : "memory")
#define CP_COMMIT() asm volatile("cp.async.commit_group;" ::: "memory")
#define CP_WAIT0() asm volatile("cp.async.wait_group 0;" ::: "memory")
#define CP_WAIT1() asm volatile("cp.async.wait_group 1;" ::: "memory")

#define LDSM_X4(r0, r1, r2, r3, a) \
  asm volatile("ldmatrix.sync.aligned.m8n8.x4.shared.b16 {%0,%1,%2,%3}, [%4];" \
               : "=r"(r0), "=r"(r1), "=r"(r2), "=r"(r3) : "r"(a))
#define LDSM_X4_T(r0, r1, r2, r3, a) \
  asm volatile("ldmatrix.sync.aligned.m8n8.x4.trans.shared.b16 {%0,%1,%2,%3}, [%4];" \
               : "=r"(r0), "=r"(r1), "=r"(r2), "=r"(r3) : "r"(a))

#define MMA16816(d, a0, a1, a2, a3, b0, b1) \
  asm volatile("mma.sync.aligned.m16n8k16.row.col.f32.f16.f16.f32 " \
               "{%0,%1,%2,%3}, {%4,%5,%6,%7}, {%8,%9}, {%0,%1,%2,%3};" \
               : "+f"((d)[0]), "+f"((d)[1]), "+f"((d)[2]), "+f"((d)[3]) \
               : "r"(a0), "r"(a1), "r"(a2), "r"(a3), "r"(b0), "r"(b1))

__device__ __forceinline__ float gelu_f(float v) {
  return 0.5f * v * (1.f + erff(v * 0.70710678118654752f));
}

// ========== weight convert + transpose (fp32 [K,N] -> fp16 [N,K]) ==========
// 64(k) x 32(n) tiles; fp16 writes are 128B per warp (uint4 per thread).
__global__ __launch_bounds__(256) void wconv_kernel(
    const float* __restrict__ W, __half* __restrict__ th, int K, int N) {
  __shared__ float t[64][33];
  int n0 = blockIdx.x * 32, k0 = blockIdx.y * 64;
  int tn = threadIdx.x & 31, tk = threadIdx.x >> 5;  // tk 0..7
#pragma unroll
  for (int i = 0; i < 8; i++)
    t[tk + i * 8][tn] = W[(size_t)(k0 + tk + i * 8) * N + n0 + tn];
  __syncthreads();
  int wn = threadIdx.x >> 3, wk = (threadIdx.x & 7) * 8;
  __half tmp[8];
#pragma unroll
  for (int i = 0; i < 8; i++) tmp[i] = __float2half_rn(t[wk + i][wn]);
  *(uint4*)(th + (size_t)(n0 + wn) * K + k0 + wk) = *(uint4*)tmp;
}

// ================= LayerNorm (fp32 in, 1024) -> fp16 =================
__global__ __launch_bounds__(256) void ln_h_kernel(
    const float* __restrict__ in, const float* __restrict__ gw,
    const float* __restrict__ bw, __half* __restrict__ oh) {
  const int cols = 1024;
  int row = blockIdx.x;
  const float* rp = in + (size_t)row * cols;
  int c = threadIdx.x * 4;
  float4 v = *(const float4*)(rp + c);
  float s = v.x + v.y + v.z + v.w;
  float sq = v.x * v.x + v.y * v.y + v.z * v.z + v.w * v.w;
  __shared__ float red0[8], red1[8];
#pragma unroll
  for (int o = 16; o; o >>= 1) {
    s += __shfl_xor_sync(0xffffffff, s, o);
    sq += __shfl_xor_sync(0xffffffff, sq, o);
  }
  int warp = threadIdx.x >> 5, lane = threadIdx.x & 31;
  if (lane == 0) { red0[warp] = s; red1[warp] = sq; }
  __syncthreads();
  __shared__ float s_mu, s_ri;
  if (threadIdx.x == 0) {
    float ts = 0.f, tq = 0.f;
#pragma unroll
    for (int i = 0; i < 8; i++) { ts += red0[i]; tq += red1[i]; }
    float mu = ts / (float)cols;
    float var = tq / (float)cols - mu * mu;
    s_mu = mu;
    s_ri = rsqrtf(var + 1e-5f);
  }
  __syncthreads();
  float mu = s_mu, ri = s_ri;
  float4 g4 = *(const float4*)(gw + c);
  float4 b4 = *(const float4*)(bw + c);
  __half2 h01, h23;
  h01.x = __float2half_rn((v.x - mu) * ri * g4.x + b4.x);
  h01.y = __float2half_rn((v.y - mu) * ri * g4.y + b4.y);
  h23.x = __float2half_rn((v.z - mu) * ri * g4.z + b4.z);
  h23.y = __float2half_rn((v.w - mu) * ri * g4.w + b4.w);
  size_t o = (size_t)row * cols + c;
  *(__half2*)(oh + o) = h01;
  *(__half2*)(oh + o + 2) = h23;
}

// ================= LayerNorm (fp16 in, 1024) -> fp16 =================
__global__ __launch_bounds__(256) void ln_h16_kernel(
    const __half* __restrict__ in, const float* __restrict__ gw,
    const float* __restrict__ bw, __half* __restrict__ oh) {
  const int cols = 1024;
  int row = blockIdx.x;
  const __half* rp = in + (size_t)row * cols;
  int c = threadIdx.x * 4;
  __half2 raw0 = *(const __half2*)(rp + c);
  __half2 raw1 = *(const __half2*)(rp + c + 2);
  float2 f0 = __half22float2(raw0), f1 = __half22float2(raw1);
  float s = f0.x + f0.y + f1.x + f1.y;
  float sq = f0.x * f0.x + f0.y * f0.y + f1.x * f1.x + f1.y * f1.y;
  __shared__ float red0[8], red1[8];
#pragma unroll
  for (int o = 16; o; o >>= 1) {
    s += __shfl_xor_sync(0xffffffff, s, o);
    sq += __shfl_xor_sync(0xffffffff, sq, o);
  }
  int warp = threadIdx.x >> 5, lane = threadIdx.x & 31;
  if (lane == 0) { red0[warp] = s; red1[warp] = sq; }
  __syncthreads();
  __shared__ float s_mu, s_ri;
  if (threadIdx.x == 0) {
    float ts = 0.f, tq = 0.f;
#pragma unroll
    for (int i = 0; i < 8; i++) { ts += red0[i]; tq += red1[i]; }
    float mu = ts / (float)cols;
    float var = tq / (float)cols - mu * mu;
    s_mu = mu;
    s_ri = rsqrtf(var + 1e-5f);
  }
  __syncthreads();
  float mu = s_mu, ri = s_ri;
  float4 g4 = *(const float4*)(gw + c);
  float4 b4 = *(const float4*)(bw + c);
  __half2 h01, h23;
  h01 = __floats2half2_rn((f0.x - mu) * ri * g4.x + b4.x,
                          (f0.y - mu) * ri * g4.y + b4.y);
  h23 = __floats2half2_rn((f1.x - mu) * ri * g4.z + b4.z,
                          (f1.y - mu) * ri * g4.w + b4.w);
  size_t o = (size_t)row * cols + c;
  *(__half2*)(oh + o) = h01;
  *(__half2*)(oh + o + 2) = h23;
}

// ================= LayerNorm (fp16 in, 4096 wide) -> fp16 =================
__global__ __launch_bounds__(256) void ln_h_in_kernel(
    const __half* __restrict__ in, const float* __restrict__ gw,
    const float* __restrict__ bw, __half* __restrict__ oh) {
  const int cols = 4096;
  int row = blockIdx.x;
  const __half* rp = in + (size_t)row * cols;
  float vals[16];
  float s = 0.f, sq = 0.f;
#pragma unroll
  for (int it = 0; it < 2; it++) {
    int c = (it * 256 + threadIdx.x) * 8;
    uint4 raw = *(const uint4*)(rp + c);
    const __half2* h2 = (const __half2*)&raw;
#pragma unroll
    for (int j = 0; j < 4; j++) {
      float2 f = __half22float2(h2[j]);
      vals[it * 8 + j * 2] = f.x;
      vals[it * 8 + j * 2 + 1] = f.y;
      s += f.x + f.y;
      sq += f.x * f.x + f.y * f.y;
    }
  }
  __shared__ float red0[8], red1[8];
#pragma unroll
  for (int o = 16; o; o >>= 1) {
    s += __shfl_xor_sync(0xffffffff, s, o);
    sq += __shfl_xor_sync(0xffffffff, sq, o);
  }
  int warp = threadIdx.x >> 5, lane = threadIdx.x & 31;
  if (lane == 0) { red0[warp] = s; red1[warp] = sq; }
  __syncthreads();
  __shared__ float s_mu, s_ri;
  if (threadIdx.x == 0) {
    float ts = 0.f, tq = 0.f;
#pragma unroll
    for (int i = 0; i < 8; i++) { ts += red0[i]; tq += red1[i]; }
    float mu = ts / (float)cols;
    float var = tq / (float)cols - mu * mu;
    s_mu = mu;
    s_ri = rsqrtf(var + 1e-5f);
  }
  __syncthreads();
  float mu = s_mu, ri = s_ri;
#pragma unroll
  for (int it = 0; it < 2; it++) {
    int c = (it * 256 + threadIdx.x) * 8;
    uint4 outw;
    __half2* oh2 = (__half2*)&outw;
#pragma unroll
    for (int j = 0; j < 4; j++) {
      float2 g2 = *(const float2*)(gw + c + j * 2);
      float2 b2 = *(const float2*)(bw + c + j * 2);
      float o0 = (vals[it * 8 + j * 2] - mu) * ri * g2.x + b2.x;
      float o1 = (vals[it * 8 + j * 2 + 1] - mu) * ri * g2.y + b2.y;
      oh2[j] = __floats2half2_rn(o0, o1);
    }
    *(uint4*)(oh + (size_t)row * cols + c) = outw;
  }
}

// ================= mma.sync fp16 GEMM (BK=64, 3-stage) =================
#define GPITCH 144
#define TILE_H (128 * GPITCH)
#define STAGE_H (2 * TILE_H)
#define GEMM_SMEM (3 * STAGE_H)
#define QSCALE 0.1803368801111244f  // 0.125 * log2(e)

template <int EPI>
__global__ __launch_bounds__(256, 2) void gemm_mma(
    const __half* __restrict__ Ah, const __half* __restrict__ Bh,
    const float* __restrict__ bias, const float* __restrict__ res,
    const __half* __restrict__ resh,
    float* __restrict__ C, int K, int N,
    __half* hout, __half* k_, __half* v_) {
  extern __shared__ char smem[];
  uint32_t sb = smem_u32(smem);
  int tid = threadIdx.x, wid = tid >> 5, lane = tid & 31;
  int m0 = blockIdx.y * 128, n0 = blockIdx.x * 128;
  int wm = wid & 1, wn = wid >> 1;
  int lrow = lane & 15, lc8 = (lane >> 4) * 8;

  float acc[4][4][4];
#pragma unroll
  for (int i = 0; i < 4; i++)
#pragma unroll
    for (int j = 0; j < 4; j++)
#pragma unroll
      for (int t = 0; t < 4; t++) acc[i][j][t] = 0.f;

  int NCH = K >> 6;

#define GEMM_LOADS(stgbase, ktv)                                             \
  {                                                                          \
    uint32_t stg = (stgbase);                                                \
    int kt = (ktv);                                                          \
    _Pragma("unroll") for (int i = 0; i < 4; i++) {                          \
      int c = tid + i * 256;                                                 \
      int r = c >> 3, q = c & 7;                                             \
      uint32_t so = (uint32_t)(r * GPITCH + q * 16);                         \
      CP_ASYNC16(stg + so, Ah + (size_t)(m0 + r) * K + kt + q * 8);          \
      CP_ASYNC16(stg + TILE_H + so, Bh + (size_t)(n0 + r) * K + kt + q * 8); \
    }                                                                        \
    CP_COMMIT();                                                             \
  }

  GEMM_LOADS(sb, 0);
  GEMM_LOADS(sb + STAGE_H, 64);

  for (int kc = 0; kc < NCH; kc++) {
    if (kc + 1 < NCH) { CP_WAIT1(); } else { CP_WAIT0(); }
    __syncthreads();
    if (kc + 2 < NCH) GEMM_LOADS(sb + ((kc + 2) % 3) * STAGE_H, (kc + 2) * 64);

    uint32_t stA = sb + (kc % 3) * STAGE_H;
    uint32_t stB = stA + TILE_H;

#pragma unroll
    for (int ks = 0; ks < 64; ks += 16) {
      uint32_t bhf[8];
      uint32_t boff0 = (uint32_t)((wn * 32 + lrow) * GPITCH + (ks + lc8) * 2);
      uint32_t boff1 = (uint32_t)((wn * 32 + 16 + lrow) * GPITCH + (ks + lc8) * 2);
      LDSM_X4(bhf[0], bhf[1], bhf[2], bhf[3], stB + boff0);
      LDSM_X4(bhf[4], bhf[5], bhf[6], bhf[7], stB + boff1);
#pragma unroll
      for (int mb = 0; mb < 4; mb++) {
        uint32_t ah[4];
        uint32_t aoff = (uint32_t)((wm * 64 + mb * 16 + lrow) * GPITCH + (ks + lc8) * 2);
        LDSM_X4(ah[0], ah[1], ah[2], ah[3], stA + aoff);
#pragma unroll
        for (int nb = 0; nb < 4; nb++) {
          int pi = (nb >> 1) * 4, od = nb & 1;
          MMA16816(acc[mb][nb], ah[0], ah[1], ah[2], ah[3],
                   bhf[pi + od], bhf[pi + 2 + od]);
        }
      }
    }
  }

  int erow = lane >> 2, ecol = (lane & 3) * 2;
#pragma unroll
  for (int mb = 0; mb < 4; mb++) {
#pragma unroll
    for (int nb = 0; nb < 4; nb++) {
      float* d = acc[mb][nb];
      int gr = m0 + wm * 64 + mb * 16 + erow;
      int gc = n0 + wn * 32 + nb * 8 + ecol;
      float2 b2 = *(const float2*)(bias + gc);
      float v0 = d[0] + b2.x, v1 = d[1] + b2.y;
      float v2 = d[2] + b2.x, v3 = d[3] + b2.y;
      if (EPI == 1) {
        v0 = gelu_f(v0); v1 = gelu_f(v1);
        v2 = gelu_f(v2); v3 = gelu_f(v3);
        *(__half2*)(hout + (size_t)gr * N + gc) = __floats2half2_rn(v0, v1);
        *(__half2*)(hout + (size_t)(gr + 8) * N + gc) = __floats2half2_rn(v2, v3);
      } else if (EPI == 3) {
        int region = gc >> 10;
        int hh = (gc & 1023) >> 6;
        int dd = gc & 63;
        int b = gr >> 11;
        int n = gr & 2047;
        if (region < 2) {
          float inv = 1.0f / powf(10000.0f, (float)(dd & ~1) / 64.0f);
          float c0, s0, c1, s1;
          sincosf((float)n * inv, &s0, &c0);
          sincosf((float)(n + 8) * inv, &s1, &c1);
          float r0 = v0 * c0 - v1 * s0, r1 = v1 * c0 + v0 * s0;
          float r2 = v2 * c1 - v3 * s1, r3 = v3 * c1 + v2 * s1;
          v0 = r0; v1 = r1; v2 = r2; v3 = r3;
          if (region == 0) { v0 *= QSCALE; v1 *= QSCALE; v2 *= QSCALE; v3 *= QSCALE; }
        }
        __half* dst = (region == 0) ? hout : (region == 1) ? k_ : v_;
        size_t o0 = ((size_t)((b * 16 + hh) * 2048 + n)) * 64 + dd;
        size_t o1 = o0 + 8 * 64;
        *(__half2*)(dst + o0) = __floats2half2_rn(v0, v1);
        *(__half2*)(dst + o1) = __floats2half2_rn(v2, v3);
      } else if (EPI == 4) {
        float2 r0 = *(const float2*)(res + (size_t)gr * N + gc);
        float2 r1 = *(const float2*)(res + (size_t)(gr + 8) * N + gc);
        v0 += r0.x; v1 += r0.y; v2 += r1.x; v3 += r1.y;
        *(__half2*)(hout + (size_t)gr * N + gc) = __floats2half2_rn(v0, v1);
        *(__half2*)(hout + (size_t)(gr + 8) * N + gc) = __floats2half2_rn(v2, v3);
      } else if (EPI == 5) {
        __half2 r0 = *(const __half2*)(resh + (size_t)gr * N + gc);
        __half2 r1 = *(const __half2*)(resh + (size_t)(gr + 8) * N + gc);
        float2 f0 = __half22float2(r0), f1 = __half22float2(r1);
        v0 += f0.x; v1 += f0.y; v2 += f1.x; v3 += f1.y;
        float2 o0 = {v0, v1}, o1 = {v2, v3};
        *(float2*)(C + (size_t)gr * N + gc) = o0;
        *(float2*)(C + (size_t)(gr + 8) * N + gc) = o1;
      } else {
        float2 o0 = {v0, v1}, o1 = {v2, v3};
        *(float2*)(C + (size_t)gr * N + gc) = o0;
        *(float2*)(C + (size_t)(gr + 8) * N + gc) = o1;
      }
    }
  }
}

// ================= FA2 flash attention (register softmax, Q hoisted) ======
#define APB 144
#define A_oQ 0
#define A_oKV 18432
#define ATTN_SMEM (18432 + 3 * 18432)

__global__ __launch_bounds__(256, 2) void attn_mma(
    const __half* __restrict__ qg, const __half* __restrict__ kg_,
    const __half* __restrict__ vg, __half* __restrict__ og) {
  extern __shared__ char sm[];
  uint32_t sb = smem_u32(sm);

  int tid = threadIdx.x, wid = tid >> 5, lane = tid & 31;
  int lrow = lane & 15, lc8 = (lane >> 4) * 8;
  int erow = lane >> 2, ecol = (lane & 3) * 2;
  int bh = blockIdx.y, qt = blockIdx.x;
  size_t base = (size_t)bh * (2048 * 64);

  {
    const __half* gq = qg + base + (size_t)(qt * 128) * 64;
#pragma unroll
    for (int i = 0; i < 4; i++) {
      int f = tid + i * 256;
      int r = f >> 3, c8 = f & 7;
      CP_ASYNC16(sb + A_oQ + (uint32_t)(r * APB + c8 * 16), gq + r * 64 + c8 * 8);
    }
    CP_COMMIT();
  }

#define ATTN_KV_LOADS(stg, ktv)                                              \
  {                                                                          \
    int kt_ = (ktv);                                                         \
    uint32_t d0 = sb + A_oKV + (stg) * 18432;                                \
    _Pragma("unroll") for (int i = 0; i < 2; i++) {                          \
      int f = tid + i * 256;                                                 \
      int r = f >> 3, c8 = f & 7;                                            \
      uint32_t so = (uint32_t)(r * APB + c8 * 16);                           \
      size_t go = base + (size_t)(kt_ * 64 + r) * 64 + c8 * 8;               \
      CP_ASYNC16(d0 + so, kg_ + go);                                         \
      CP_ASYNC16(d0 + 9216 + so, vg + go);                                   \
    }                                                                        \
    CP_COMMIT();                                                             \
  }

  ATTN_KV_LOADS(0, 0);
  ATTN_KV_LOADS(1, 1);

  float oacc[8][4];
#pragma unroll
  for (int j = 0; j < 8; j++)
#pragma unroll
    for (int t = 0; t < 4; t++) oacc[j][t] = 0.f;
  float m_lo = -INFINITY, m_hi = -INFINITY, l_lo = 0.f, l_hi = 0.f;

  uint32_t qbase = sb + A_oQ + (uint32_t)((wid * 16 + lrow) * APB + lc8 * 2);
  uint32_t aq[4][4];

  for (int kt = 0; kt < 32; kt++) {
    if (kt + 1 < 32) { CP_WAIT1(); } else { CP_WAIT0(); }
    __syncthreads();
    if (kt + 2 < 32) ATTN_KV_LOADS((kt + 2) % 3, kt + 2);
    if (kt == 0) {
#pragma unroll
      for (int ks = 0; ks < 4; ks++)
        LDSM_X4(aq[ks][0], aq[ks][1], aq[ks][2], aq[ks][3], qbase + ks * 32);
    }

    uint32_t sK = sb + A_oKV + (kt % 3) * 18432;
    uint32_t sV = sK + 9216;

    float sacc[8][4];
#pragma unroll
    for (int j = 0; j < 8; j++)
#pragma unroll
      for (int t = 0; t < 4; t++) sacc[j][t] = 0.f;
#pragma unroll
    for (int ks = 0; ks < 4; ks++) {
#pragma unroll
      for (int g = 0; g < 4; g++) {
        uint32_t kb[4];
        uint32_t koff = (uint32_t)((g * 16 + lrow) * APB + (ks * 16 + lc8) * 2);
        LDSM_X4(kb[0], kb[1], kb[2], kb[3], sK + koff);
        MMA16816(sacc[g * 2 + 0], aq[ks][0], aq[ks][1], aq[ks][2], aq[ks][3],
                 kb[0], kb[2]);
        MMA16816(sacc[g * 2 + 1], aq[ks][0], aq[ks][1], aq[ks][2], aq[ks][3],
                 kb[1], kb[3]);
      }
    }

    float mx0 = -INFINITY, mx1 = -INFINITY;
#pragma unroll
    for (int j = 0; j < 8; j++) {
      mx0 = fmaxf(mx0, fmaxf(sacc[j][0], sacc[j][1]));
      mx1 = fmaxf(mx1, fmaxf(sacc[j][2], sacc[j][3]));
    }
    mx0 = fmaxf(mx0, __shfl_xor_sync(0xffffffff, mx0, 1));
    mx0 = fmaxf(mx0, __shfl_xor_sync(0xffffffff, mx0, 2));
    mx1 = fmaxf(mx1, __shfl_xor_sync(0xffffffff, mx1, 1));
    mx1 = fmaxf(mx1, __shfl_xor_sync(0xffffffff, mx1, 2));
    float nm0 = fmaxf(m_lo, mx0), nm1 = fmaxf(m_hi, mx1);
    float cf0 = exp2f(m_lo - nm0), cf1 = exp2f(m_hi - nm1);
    m_lo = nm0; m_hi = nm1;

    uint32_t pa[4][4];
    float s0 = 0.f, s1 = 0.f;
#pragma unroll
    for (int g = 0; g < 4; g++) {
#pragma unroll
      for (int hb = 0; hb < 2; hb++) {
        int j = g * 2 + hb;
        float p00 = exp2f(sacc[j][0] - nm0);
        float p01 = exp2f(sacc[j][1] - nm0);
        float p10 = exp2f(sacc[j][2] - nm1);
        float p11 = exp2f(sacc[j][3] - nm1);
        s0 += p00 + p01;
        s1 += p10 + p11;
        __half2 plo = __floats2half2_rn(p00, p01);
        __half2 phi = __floats2half2_rn(p10, p11);
        pa[g][hb * 2 + 0] = *(uint32_t*)&plo;
        pa[g][hb * 2 + 1] = *(uint32_t*)&phi;
      }
    }
    s0 += __shfl_xor_sync(0xffffffff, s0, 1);
    s0 += __shfl_xor_sync(0xffffffff, s0, 2);
    s1 += __shfl_xor_sync(0xffffffff, s1, 1);
    s1 += __shfl_xor_sync(0xffffffff, s1, 2);
    l_lo = l_lo * cf0 + s0;
    l_hi = l_hi * cf1 + s1;

#pragma unroll
    for (int j = 0; j < 8; j++) {
      oacc[j][0] *= cf0; oacc[j][1] *= cf0;
      oacc[j][2] *= cf1; oacc[j][3] *= cf1;
    }
#pragma unroll
    for (int g = 0; g < 4; g++) {
#pragma unroll
      for (int db = 0; db < 4; db++) {
        uint32_t vb[4];
        uint32_t voff = (uint32_t)((g * 16 + lrow) * APB + (db * 16 + lc8) * 2);
        LDSM_X4_T(vb[0], vb[1], vb[2], vb[3], sV + voff);
        MMA16816(oacc[db * 2 + 0], pa[g][0], pa[g][1], pa[g][2], pa[g][3],
                 vb[0], vb[1]);
        MMA16816(oacc[db * 2 + 1], pa[g][0], pa[g][1], pa[g][2], pa[g][3],
                 vb[2], vb[3]);
      }
    }
  }

  int b = bh >> 4, h = bh & 15;
  float il0 = 1.f / l_lo, il1 = 1.f / l_hi;
  int qrow = qt * 128 + wid * 16 + erow;
  size_t rbase0 = ((size_t)(b * 2048 + qrow)) * 1024 + h * 64;
  size_t rbase1 = rbase0 + 8 * 1024;
#pragma unroll
  for (int db = 0; db < 4; db++) {
#pragma unroll
    for (int nb = 0; nb < 2; nb++) {
      int j = db * 2 + nb;
      int d = db * 16 + nb * 8 + ecol;
      *(__half2*)(og + rbase0 + d) = __floats2half2_rn(oacc[j][0] * il0,
                                                       oacc[j][1] * il0);
      *(__half2*)(og + rbase1 + d) = __floats2half2_rn(oacc[j][2] * il1,
                                                       oacc[j][3] * il1);
    }
  }
}

// ================= launch =================
extern "C" void kernel_launch(void* const* d_in, const int* in_sizes, int n_in,
                              void* d_out, int out_size) {
  const float* x = (const float*)d_in[0];
  const float* ln1_g = (const float*)d_in[1];
  const float* ln1_b = (const float*)d_in[2];
  const float* qkv_w = (const float*)d_in[3];
  const float* qkv_b = (const float*)d_in[4];
  const float* proj_w = (const float*)d_in[5];
  const float* proj_b = (const float*)d_in[6];
  const float* ln2_g = (const float*)d_in[7];
  const float* ln2_b = (const float*)d_in[8];
  const float* fc1_w = (const float*)d_in[9];
  const float* fc1_b = (const float*)d_in[10];
  const float* ffln_g = (const float*)d_in[11];
  const float* ffln_b = (const float*)d_in[12];
  const float* fc2_w = (const float*)d_in[13];
  const float* fc2_b = (const float*)d_in[14];
  float* out = (float*)d_out;

  __half *x1h, *h1h, *ah, *att, *q, *k, *v;
  __half *wq, *wp, *w1, *w2;
  cudaGetSymbolAddress((void**)&x1h, g_x1h);
  cudaGetSymbolAddress((void**)&h1h, g_h1h);
  cudaGetSymbolAddress((void**)&ah, g_ah);
  cudaGetSymbolAddress((void**)&att, g_att);
  cudaGetSymbolAddress((void**)&q, g_q2);
  cudaGetSymbolAddress((void**)&k, g_k2);
  cudaGetSymbolAddress((void**)&v, g_v2);
  cudaGetSymbolAddress((void**)&wq, g_wq);
  cudaGetSymbolAddress((void**)&wp, g_wp);
  cudaGetSymbolAddress((void**)&w1, g_w1);
  cudaGetSymbolAddress((void**)&w2, g_w2);

  cudaFuncSetAttribute(gemm_mma<0>, cudaFuncAttributeMaxDynamicSharedMemorySize, GEMM_SMEM);
  cudaFuncSetAttribute(gemm_mma<1>, cudaFuncAttributeMaxDynamicSharedMemorySize, GEMM_SMEM);
  cudaFuncSetAttribute(gemm_mma<3>, cudaFuncAttributeMaxDynamicSharedMemorySize, GEMM_SMEM);
  cudaFuncSetAttribute(gemm_mma<4>, cudaFuncAttributeMaxDynamicSharedMemorySize, GEMM_SMEM);
  cudaFuncSetAttribute(gemm_mma<5>, cudaFuncAttributeMaxDynamicSharedMemorySize, GEMM_SMEM);
  cudaFuncSetAttribute(attn_mma, cudaFuncAttributeMaxDynamicSharedMemorySize, ATTN_SMEM);

  // --- side stream for weight conversion (parallel graph branch) ---
  cudaStream_t s1;
  cudaStreamCreateWithFlags(&s1, cudaStreamNonBlocking);
  cudaEvent_t evRoot, evQ, evRest;
  cudaEventCreateWithFlags(&evRoot, cudaEventDisableTiming);
  cudaEventCreateWithFlags(&evQ, cudaEventDisableTiming);
  cudaEventCreateWithFlags(&evRest, cudaEventDisableTiming);

  cudaEventRecord(evRoot, 0);
  cudaStreamWaitEvent(s1, evRoot, 0);

  // side branch: weight conversions (64x32 tiles)
  wconv_kernel<<<dim3(3072 / 32, 1024 / 64), 256, 0, s1>>>(qkv_w, wq, 1024, 3072);
  cudaEventRecord(evQ, s1);
  wconv_kernel<<<dim3(1024 / 32, 1024 / 64), 256, 0, s1>>>(proj_w, wp, 1024, 1024);
  wconv_kernel<<<dim3(4096 / 32, 1024 / 64), 256, 0, s1>>>(fc1_w, w1, 1024, 4096);
  wconv_kernel<<<dim3(1024 / 32, 4096 / 64), 256, 0, s1>>>(fc2_w, w2, 4096, 1024);
  cudaEventRecord(evRest, s1);

  // main branch
  // 1) LN1 -> fp16 (independent of wconv)
  ln_h_kernel<<<ROWS, 256>>>(x, ln1_g, ln1_b, ah);
  // 2) QKV GEMM (needs wq)
  cudaStreamWaitEvent(0, evQ, 0);
  gemm_mma<3><<<dim3(3072 / 128, ROWS / 128), 256, GEMM_SMEM>>>(
      ah, wq, qkv_b, nullptr, nullptr, nullptr, 1024, 3072, q, k, v);
  // 3) attention
  attn_mma<<<dim3(NNq / 128, BB * HHn), 256, ATTN_SMEM>>>(q, k, v, att);
  // 4) proj + residual (needs wp; all remaining wconvs done by here)
  cudaStreamWaitEvent(0, evRest, 0);
  gemm_mma<4><<<dim3(1024 / 128, ROWS / 128), 256, GEMM_SMEM>>>(
      att, wp, proj_b, x, nullptr, nullptr, 1024, 1024, x1h, nullptr, nullptr);
  // 5) LN2 (fp16 in)
  ln_h16_kernel<<<ROWS, 256>>>(x1h, ln2_g, ln2_b, ah);
  // 6) fc1 + GELU
  gemm_mma<1><<<dim3(4096 / 128, ROWS / 128), 256, GEMM_SMEM>>>(
      ah, w1, fc1_b, nullptr, nullptr, nullptr, 1024, 4096, h1h, nullptr, nullptr);
  // 7) ffn LN
  ln_h_in_kernel<<<ROWS, 256>>>(h1h, ffln_g, ffln_b, ah);
  // 8) fc2 + residual -> out
  gemm_mma<5><<<dim3(1024 / 128, ROWS / 128), 256, GEMM_SMEM>>>(
      ah, w2, fc2_b, nullptr, x1h, out, 4096, 1024, nullptr, nullptr, nullptr);
}